// round 8
// baseline (speedup 1.0000x reference)
#include <cuda_runtime.h>
#include <math.h>

#define TN 16000
#define NT 1024
#define NF 36
#define NB 64
#define NOUT 250
#define NTAPS 257
#define KPHI 569
#define NCH 37
#define TBL 102000

// ---------------- static device scratch ----------------
__device__ float2 d_X[NB * TN];        // scrambled forward FFT of x (8 MB, L2-resident)
__device__ int    d_idx[TBL];          // per-channel gather index into scrambled X
__device__ float  d_wt[TBL];           // per-channel psi_hat weight (incl 1/16000)
__device__ float  d_phiw[NTAPS];       // time-domain lowpass taps phi(d), d=-128..128
__device__ float2 d_rtA[128];          // W_16000^{-125 i}
__device__ float2 d_rtB[125];          // W_16000^{-i}
__device__ float  d_S1[NB * NCH * NOUT];

// ---------------- complex helpers ----------------
__device__ __forceinline__ float2 cmul(float2 a, float2 b) {
    return make_float2(a.x*b.x - a.y*b.y, a.x*b.y + a.y*b.x);
}
__device__ __forceinline__ float2 cadd(float2 a, float2 b){ return make_float2(a.x+b.x, a.y+b.y); }
__device__ __forceinline__ float2 csub(float2 a, float2 b){ return make_float2(a.x-b.x, a.y-b.y); }

// ---------------- one prep kernel: phi taps, twiddle roots, band gather tables ----------------
__global__ void prep_all(){
    int q = blockIdx.x * blockDim.x + threadIdx.x;
    int j = blockIdx.y;
    if (j == NF) {
        if (q < NTAPS) {
            int d = q - 128;
            const float sp = 0.35f / 64.0f;
            float acc = 0.f;
            for (int k = 1; k <= KPHI; ++k) {
                float f = (float)k / 16000.0f;
                float g = __expf(-f*f / (2.0f*sp*sp));
                acc += g * cospif(2.0f * (float)(k*d) / 16000.0f);
            }
            d_phiw[q] = (1.0f + 2.0f*acc) / 16000.0f;
        } else if (q >= 512 && q < 640) {
            int i = q - 512;
            float s, c; sincospif(-(float)i/64.0f, &s, &c);
            d_rtA[i] = make_float2(c, s);
        } else if (q >= 640 && q < 765) {
            int i = q - 640;
            float s, c; sincospif(-(float)i/8000.0f, &s, &c);
            d_rtB[i] = make_float2(c, s);
        }
        return;
    }
    int cls, NJ, off;
    if      (j <  6){ cls=1; NJ=8000; off = j*8000; }
    else if (j < 12){ cls=2; NJ=4000; off = 48000 + (j-6)*4000; }
    else if (j < 18){ cls=3; NJ=2000; off = 72000 + (j-12)*2000; }
    else            { cls=4; NJ=1000; off = 84000 + (j-18)*1000; }
    if (q >= NJ) return;
    // digit reversal for the class's DIT radix list -> natural frequency k
    int k;
    if      (cls == 1) { int a=q/4000, b=(q/1000)%4, c=(q/100)%10, d=(q/10)%10, e=q%10; k = a + 2*b + 8*c + 80*d + 800*e; }
    else if (cls == 2) { int b=q/1000, c=(q/100)%10, d=(q/10)%10, e=q%10; k = b + 4*c + 40*d + 400*e; }
    else if (cls == 3) { int a=q/1000, c=(q/100)%10, d=(q/10)%10, e=q%10; k = a + 2*c + 20*d + 200*e; }
    else               { int c=q/100, d=(q/10)%10, e=q%10; k = c + 10*d + 100*e; }
    // scrambled position of natural frequency k in the stored 16000 layout
    int e2 = k/1600, r = k - 1600*e2;
    int d2 = r/160;  r -= 160*d2;
    int c2 = r/16;   r -= 16*c2;
    int b2 = r/4,    a2 = r - 4*b2;
    int p = 4000*a2 + 1000*b2 + 100*c2 + 10*d2 + e2;
    // psi weight (float precision is ample: rel err ~5e-5 on a 1e-3 budget)
    float f = (k < 8000) ? (float)k/16000.0f : (float)(k - 16000)/16000.0f;
    float rr  = exp2f(1.0f/6.0f);
    float fac = (rr - 1.0f) / (rr + 1.0f);
    float xi = 0.35f * exp2f(-(float)j/6.0f);
    float sg = xi * fac;
    float u  = (f - xi) / sg;
    float v  = (u*u < 50.0f) ? __expf(-0.5f*u*u) : 0.0f;
    d_idx[off+q] = p;
    d_wt[off+q]  = v / 16000.0f;
}

// ---------------- small DFTs ----------------
template<int SIGN>
__device__ __forceinline__ void dft4(float2&z0,float2&z1,float2&z2,float2&z3){
    float2 t0=cadd(z0,z2), t1=csub(z0,z2), t2=cadd(z1,z3), t3=csub(z1,z3);
    const float s = (float)SIGN;
    z0 = cadd(t0,t2);
    z2 = csub(t0,t2);
    z1 = make_float2(t1.x - s*t3.y, t1.y + s*t3.x);
    z3 = make_float2(t1.x + s*t3.y, t1.y - s*t3.x);
}

template<int SIGN>
__device__ __forceinline__ void dft5(float2&z0,float2&z1,float2&z2,float2&z3,float2&z4){
    const float K1 =  0.309016994374947424f;
    const float K2 = -0.809016994374947424f;
    const float S1 =  0.951056516295153572f;
    const float S2 =  0.587785252292473129f;
    float2 t1=cadd(z1,z4), t2=cadd(z2,z3), t3=csub(z1,z4), t4=csub(z2,z3);
    float2 a = z0;
    float2 sum = cadd(a, cadd(t1,t2));
    float2 r1 = make_float2(a.x + K1*t1.x + K2*t2.x, a.y + K1*t1.y + K2*t2.y);
    float2 r2 = make_float2(a.x + K2*t1.x + K1*t2.x, a.y + K2*t1.y + K1*t2.y);
    float2 q1 = make_float2(S1*t3.x + S2*t4.x, S1*t3.y + S2*t4.y);
    float2 q2 = make_float2(S2*t3.x - S1*t4.x, S2*t3.y - S1*t4.y);
    const float s = (float)SIGN;
    z0 = sum;
    z1 = make_float2(r1.x - s*q1.y, r1.y + s*q1.x);
    z4 = make_float2(r1.x + s*q1.y, r1.y - s*q1.x);
    z2 = make_float2(r2.x - s*q2.y, r2.y + s*q2.x);
    z3 = make_float2(r2.x + s*q2.y, r2.y - s*q2.x);
}

__device__ __forceinline__ float2 twb(int x, const float2* rtA, const float2* rtB){
    int a = x / 125;
    return cmul(rtA[a], rtB[x - a*125]);
}

// ================= forward-only pieces (k_fwd, size 16000, NT threads) =================
__device__ void stage16_fwd(float2* buf, const float* xs, const float2* rtA, const float2* rtB){
    const float2 c16_1 = make_float2(0.92387953251128674f, -0.38268343236508977f);
    const float2 c16_2 = make_float2(0.70710678118654752f, -0.70710678118654752f);
    const float2 c16_3 = make_float2(0.38268343236508977f, -0.92387953251128674f);
    for (int p = threadIdx.x; p < 1000; p += NT) {
        float2 z[16];
        #pragma unroll
        for (int j=0;j<4;j++)
            #pragma unroll
            for (int i=0;i<4;i++)
                z[4*j+i] = make_float2(xs[p + 1000*j + 4000*i], 0.f);
        float2 a = twb(p, rtA, rtB);
        float2 b = twb(4*p, rtA, rtB);
        #pragma unroll
        for (int j=0;j<4;j++) dft4<-1>(z[4*j+0], z[4*j+1], z[4*j+2], z[4*j+3]);
        #pragma unroll
        for (int j=0;j<4;j++){
            float2 t = (j==0)? a : (j==1? cmul(a,c16_1) : (j==2? cmul(a,c16_2) : cmul(a,c16_3)));
            float2 t2 = cmul(t,t);
            z[4*j+1]=cmul(z[4*j+1],t); z[4*j+2]=cmul(z[4*j+2],t2); z[4*j+3]=cmul(z[4*j+3],cmul(t2,t));
        }
        #pragma unroll
        for (int s1=0;s1<4;s1++) dft4<-1>(z[s1], z[4+s1], z[8+s1], z[12+s1]);
        float2 b2 = cmul(b,b), b3 = cmul(b2,b);
        #pragma unroll
        for (int s1=0;s1<4;s1++){ z[4+s1]=cmul(z[4+s1],b); z[8+s1]=cmul(z[8+s1],b2); z[12+s1]=cmul(z[12+s1],b3); }
        #pragma unroll
        for (int s1=0;s1<4;s1++)
            #pragma unroll
            for (int s2=0;s2<4;s2++)
                buf[s1*4000 + s2*1000 + p] = z[4*s2+s1];
    }
    __syncthreads();
}

template<int M, int CC>
__device__ void stage10_fwd(float2* buf, const float2* rtA, const float2* rtB){
    const float c1x=0.809016994374947424f, c1y=0.587785252292473129f;
    const float c2x=0.309016994374947424f, c2y=0.951056516295153572f;
    const float2 w10_1 = make_float2( c1x, -c1y);
    const float2 w10_2 = make_float2( c2x, -c2y);
    const float2 w10_3 = make_float2(-c2x, -c2y);
    const float2 w10_4 = make_float2(-c1x, -c1y);
    for (int idx = threadIdx.x; idx < 1600; idx += NT) {
        int blk = idx / M;
        int p   = idx - blk*M;
        int o   = blk*(10*M) + p;
        float2 z[10];
        #pragma unroll
        for (int i=0;i<10;i++) z[i] = buf[o + M*i];
        float2 v = twb(CC*p, rtA, rtB);
        float2 b  = cmul(v,v);
        float2 b2 = cmul(b,b);
        float2 b3 = cmul(b2,b);
        float2 b4 = cmul(b2,b2);
        float2 m1 = cmul(w10_1, v);
        float2 m2 = cmul(w10_2, v);
        float2 m3 = cmul(w10_3, v);
        float2 m4 = cmul(w10_4, v);
        float2 e0=cadd(z[0],z[5]), e1=cadd(z[1],z[6]), e2=cadd(z[2],z[7]), e3=cadd(z[3],z[8]), e4=cadd(z[4],z[9]);
        float2 q0=cmul(csub(z[0],z[5]), v ), q1=cmul(csub(z[1],z[6]), m1),
               q2=cmul(csub(z[2],z[7]), m2), q3=cmul(csub(z[3],z[8]), m3),
               q4=cmul(csub(z[4],z[9]), m4);
        dft5<-1>(e0,e1,e2,e3,e4);
        dft5<-1>(q0,q1,q2,q3,q4);
        z[0]=e0;          z[1]=q0;
        z[2]=cmul(e1,b);  z[3]=cmul(q1,b);
        z[4]=cmul(e2,b2); z[5]=cmul(q2,b2);
        z[6]=cmul(e3,b3); z[7]=cmul(q3,b3);
        z[8]=cmul(e4,b4); z[9]=cmul(q4,b4);
        #pragma unroll
        for (int i=0;i<10;i++) buf[o + M*i] = z[i];
    }
    __syncthreads();
}

__device__ void stage10_fwd_store(const float2* buf, float2* __restrict__ Xo){
    const float c1x=0.809016994374947424f, c1y=0.587785252292473129f;
    const float c2x=0.309016994374947424f, c2y=0.951056516295153572f;
    const float2 w1 = make_float2( c1x, -c1y);
    const float2 w2 = make_float2( c2x, -c2y);
    const float2 w3 = make_float2(-c2x, -c2y);
    const float2 w4 = make_float2(-c1x, -c1y);
    for (int blk = threadIdx.x; blk < 1600; blk += NT) {
        int o = 10*blk;
        float2 z[10];
        #pragma unroll
        for (int i=0;i<10;i++) z[i] = buf[o+i];
        float2 e0=cadd(z[0],z[5]), e1=cadd(z[1],z[6]), e2=cadd(z[2],z[7]), e3=cadd(z[3],z[8]), e4=cadd(z[4],z[9]);
        float2 q0=csub(z[0],z[5]),           q1=cmul(csub(z[1],z[6]), w1),
               q2=cmul(csub(z[2],z[7]), w2), q3=cmul(csub(z[3],z[8]), w3),
               q4=cmul(csub(z[4],z[9]), w4);
        dft5<-1>(e0,e1,e2,e3,e4);
        dft5<-1>(q0,q1,q2,q3,q4);
        float4* X4 = (float4*)(Xo + o);
        X4[0] = make_float4(e0.x,e0.y,q0.x,q0.y);
        X4[1] = make_float4(e1.x,e1.y,q1.x,q1.y);
        X4[2] = make_float4(e2.x,e2.y,q2.x,q2.y);
        X4[3] = make_float4(e3.x,e3.y,q3.x,q3.y);
        X4[4] = make_float4(e4.x,e4.y,q4.x,q4.y);
    }
}

// ================= inverse pieces (generic over size / thread count) =================

// first DIT stage (radix-10, M=1, no twiddle): gather X via idx/wt tables
template<int THR>
__device__ void s10_load(float2* buf, const float2* __restrict__ Xb,
                         const int* __restrict__ idx, const float* __restrict__ wt, int cnt10){
    const float c1x=0.809016994374947424f, c1y=0.587785252292473129f;
    const float c2x=0.309016994374947424f, c2y=0.951056516295153572f;
    const float2 w1 = make_float2( c1x,  c1y);
    const float2 w2 = make_float2( c2x,  c2y);
    const float2 w3 = make_float2(-c2x,  c2y);
    const float2 w4 = make_float2(-c1x,  c1y);
    for (int blk = threadIdx.x; blk < cnt10; blk += THR) {
        int o = 10*blk;
        float2 z[10];
        #pragma unroll
        for (int i=0;i<10;i++){
            float2 v = Xb[idx[o+i]];
            float  w = wt[o+i];
            z[i] = make_float2(v.x*w, v.y*w);
        }
        float2 E0=z[0], E1=z[2], E2=z[4], E3=z[6], E4=z[8];
        float2 O0=z[1], O1=z[3], O2=z[5], O3=z[7], O4=z[9];
        dft5<1>(E0,E1,E2,E3,E4);
        dft5<1>(O0,O1,O2,O3,O4);
        O1=cmul(O1,w1); O2=cmul(O2,w2); O3=cmul(O3,w3); O4=cmul(O4,w4);
        buf[o  ]=cadd(E0,O0); buf[o+5]=csub(E0,O0);
        buf[o+1]=cadd(E1,O1); buf[o+6]=csub(E1,O1);
        buf[o+2]=cadd(E2,O2); buf[o+7]=csub(E2,O2);
        buf[o+3]=cadd(E3,O3); buf[o+8]=csub(E3,O3);
        buf[o+4]=cadd(E4,O4); buf[o+9]=csub(E4,O4);
    }
    __syncthreads();
}

// generic inverse radix-10 stage; if ABS, writes |z| to U instead of buf
template<int M, int CC, int THR, bool ABS>
__device__ void s10i(float2* buf, float* U, int cnt, const float2* rtA, const float2* rtB){
    const float c1x=0.809016994374947424f, c1y=0.587785252292473129f;
    const float c2x=0.309016994374947424f, c2y=0.951056516295153572f;
    const float2 w10_1 = make_float2( c1x,  c1y);
    const float2 w10_2 = make_float2( c2x,  c2y);
    const float2 w10_3 = make_float2(-c2x,  c2y);
    const float2 w10_4 = make_float2(-c1x,  c1y);
    for (int idx = threadIdx.x; idx < cnt; idx += THR) {
        int blk = idx / M;
        int p   = idx - blk*M;
        int o   = blk*(10*M) + p;
        float2 z[10];
        #pragma unroll
        for (int i=0;i<10;i++) z[i] = buf[o + M*i];
        float2 v = twb(CC*p, rtA, rtB);
        v.y = -v.y;
        float2 b  = cmul(v,v);
        float2 b2 = cmul(b,b);
        float2 b3 = cmul(b2,b);
        float2 b4 = cmul(b2,b2);
        float2 m1 = cmul(w10_1, v);
        float2 m2 = cmul(w10_2, v);
        float2 m3 = cmul(w10_3, v);
        float2 m4 = cmul(w10_4, v);
        float2 E0=z[0], E1=cmul(z[2],b), E2=cmul(z[4],b2), E3=cmul(z[6],b3), E4=cmul(z[8],b4);
        float2 O0=z[1], O1=cmul(z[3],b), O2=cmul(z[5],b2), O3=cmul(z[7],b3), O4=cmul(z[9],b4);
        dft5<1>(E0,E1,E2,E3,E4);
        dft5<1>(O0,O1,O2,O3,O4);
        O0=cmul(O0,v ); O1=cmul(O1,m1); O2=cmul(O2,m2); O3=cmul(O3,m3); O4=cmul(O4,m4);
        float2 y[10];
        y[0]=cadd(E0,O0); y[5]=csub(E0,O0);
        y[1]=cadd(E1,O1); y[6]=csub(E1,O1);
        y[2]=cadd(E2,O2); y[7]=csub(E2,O2);
        y[3]=cadd(E3,O3); y[8]=csub(E3,O3);
        y[4]=cadd(E4,O4); y[9]=csub(E4,O4);
        if (ABS) {
            #pragma unroll
            for (int i=0;i<10;i++) U[o + M*i] = sqrtf(y[i].x*y[i].x + y[i].y*y[i].y);
        } else {
            #pragma unroll
            for (int i=0;i<10;i++) buf[o + M*i] = y[i];
        }
    }
    __syncthreads();
}

// inverse radix-4 stage, M=1000, sub-length 4000 (twiddle = conj W_16000^{4p s})
template<int THR, bool ABS>
__device__ void s4i(float2* buf, float* U, int cnt, const float2* rtA, const float2* rtB){
    for (int idx = threadIdx.x; idx < cnt; idx += THR) {
        int blk = idx / 1000;
        int p   = idx - blk*1000;
        int o   = blk*4000 + p;
        float2 z0=buf[o], z1=buf[o+1000], z2=buf[o+2000], z3=buf[o+3000];
        float2 w1 = twb(4*p, rtA, rtB); w1.y = -w1.y;
        float2 w2 = cmul(w1,w1), w3 = cmul(w2,w1);
        z1=cmul(z1,w1); z2=cmul(z2,w2); z3=cmul(z3,w3);
        dft4<1>(z0,z1,z2,z3);
        if (ABS) {
            U[o]      = sqrtf(z0.x*z0.x + z0.y*z0.y);
            U[o+1000] = sqrtf(z1.x*z1.x + z1.y*z1.y);
            U[o+2000] = sqrtf(z2.x*z2.x + z2.y*z2.y);
            U[o+3000] = sqrtf(z3.x*z3.x + z3.y*z3.y);
        } else {
            buf[o]=z0; buf[o+1000]=z1; buf[o+2000]=z2; buf[o+3000]=z3;
        }
    }
    __syncthreads();
}

// inverse radix-2 stage, half-offset M2, twiddle conj W_16000^{DD p}
template<int THR, int M2, int DD>
__device__ void s2i_abs(float2* buf, float* U, const float2* rtA, const float2* rtB){
    for (int p = threadIdx.x; p < M2; p += THR) {
        float2 a = buf[p];
        float2 w = twb(DD*p, rtA, rtB); w.y = -w.y;
        float2 bb = cmul(buf[p+M2], w);
        float2 y0 = cadd(a,bb), y1 = csub(a,bb);
        U[p]    = sqrtf(y0.x*y0.x + y0.y*y0.y);
        U[p+M2] = sqrtf(y1.x*y1.x + y1.y*y1.y);
    }
    __syncthreads();
}

// ================= shared small helpers =================
template<int THR>
__device__ void init_tables(float2* rtA, float2* rtB, float* sphi){
    for (int i = threadIdx.x; i < 128; i += THR) rtA[i] = d_rtA[i];
    for (int i = threadIdx.x; i < 125; i += THR) rtB[i] = d_rtB[i];
    for (int i = threadIdx.x; i < NTAPS; i += THR) sphi[i] = d_phiw[i];
}

// decimated smoothing: S1[m] = DEC * sum_i phi(DEC*i) * U[(64m/DEC - i) mod NJ]
template<int NJ, int DEC, int THR>
__device__ void smooth_dec(const float* __restrict__ S, const float* __restrict__ sphi, float* dst){
    const int T = 128 / DEC;
    const int ITER = (2*T + 1 + 31) / 32;
    int w = threadIdx.x >> 5, l = threadIdx.x & 31;
    for (int m0 = w; m0 < NOUT; m0 += THR/32) {
        int tau = (64/DEC) * m0;
        float acc = 0.f;
        #pragma unroll
        for (int it = 0; it < ITER; ++it) {
            int tl = l + 32*it;
            if (tl <= 2*T) {
                int i = tl - T;
                int id = tau - i;
                if (id >= NJ) id -= NJ;
                if (id < 0)   id += NJ;
                acc += sphi[DEC*i + 128] * S[id];
            }
        }
        #pragma unroll
        for (int o = 16; o; o >>= 1) acc += __shfl_down_sync(0xffffffffu, acc, o);
        if (l == 0) dst[m0] = acc * (float)DEC;
    }
}

// ---------------- kernel 1: forward FFT of x (+ S0) ----------------
__global__ __launch_bounds__(NT, 1) void k_fwd(const float* __restrict__ x){
    extern __shared__ __align__(16) unsigned char sm[];
    float2* buf = (float2*)sm;
    float*  xs  = (float*)(sm + TN*sizeof(float2));
    __shared__ float2 rtA[128]; __shared__ float2 rtB[125]; __shared__ float sphi[NTAPS];
    int b = blockIdx.x;
    init_tables<NT>(rtA, rtB, sphi);
    const float4* xb4 = (const float4*)(x + b*TN);
    float4* xs4 = (float4*)xs;
    for (int n = threadIdx.x; n < TN/4; n += NT) xs4[n] = xb4[n];
    __syncthreads();
    smooth_dec<TN,1,NT>(xs, sphi, &d_S1[(b*NCH + 0)*NOUT]);
    stage16_fwd(buf, xs, rtA, rtB);
    stage10_fwd<100,16>(buf, rtA, rtB);
    stage10_fwd<10,160>(buf, rtA, rtB);
    stage10_fwd_store(buf, d_X + b*TN);
}

// ---------------- kernel 2: per-class band-pass ifft + |.| + smoothing ----------------
// CLS: 1=B(8000,D2) 2=C(4000,D4) 3=D(2000,D8) 4=E(1000,D16)
template<int NJ, int DEC, int THR, int CLS>
__global__ __launch_bounds__(THR, 1) void k_bandT(int j0, int off0){
    extern __shared__ __align__(16) unsigned char sm[];
    float2* buf = (float2*)sm;
    float*  U   = (float*)(sm + NJ*sizeof(float2));
    __shared__ float2 rtA[128]; __shared__ float2 rtB[125]; __shared__ float sphi[NTAPS];
    int jc = blockIdx.x, b = blockIdx.y;
    int j = j0 + jc;
    init_tables<THR>(rtA, rtB, sphi);
    __syncthreads();
    const float2* Xb = d_X + b*TN;
    const int*   idx = d_idx + off0 + jc*NJ;
    const float* wt  = d_wt  + off0 + jc*NJ;
    s10_load<THR>(buf, Xb, idx, wt, NJ/10);
    s10i<10,160,THR,false>(buf, U, NJ/10, rtA, rtB);
    if (CLS == 4) {
        s10i<100,16,THR,true>(buf, U, NJ/10, rtA, rtB);
    } else {
        s10i<100,16,THR,false>(buf, U, NJ/10, rtA, rtB);
        if (CLS == 1) { s4i<THR,false>(buf, U, 2000, rtA, rtB); s2i_abs<THR,4000,2>(buf, U, rtA, rtB); }
        if (CLS == 2) s4i<THR,true>(buf, U, 1000, rtA, rtB);
        if (CLS == 3) s2i_abs<THR,1000,8>(buf, U, rtA, rtB);
    }
    smooth_dec<NJ,DEC,THR>(U, sphi, &d_S1[(b*NCH + 1 + j)*NOUT]);
}

// ---------------- kernel 3: channel-group means ----------------
__global__ void k_reduce(float* __restrict__ out){
    int i = blockIdx.x * blockDim.x + threadIdx.x;
    if (i >= NB*3*NOUT) return;
    int m0 = i % NOUT;
    int g  = (i / NOUT) % 3;
    int b  = i / (3*NOUT);
    int c0 = (g==0) ? 0 : (g==1 ? 12 : 24);
    int nc = (g==2) ? 13 : 12;
    float acc = 0.f;
    for (int c = 0; c < nc; ++c) acc += d_S1[(b*NCH + c0 + c)*NOUT + m0];
    out[i] = acc / (float)nc;
}

// ---------------- launch ----------------
extern "C" void kernel_launch(void* const* d_in, const int* in_sizes, int n_in,
                              void* d_out, int out_size) {
    (void)in_sizes; (void)n_in; (void)out_size;
    const float* x = (const float*)d_in[0];
    float* out = (float*)d_out;
    const int smF = TN*8 + TN*4;            // 192000
    const int smB = 8000*8 + 8000*4;        // 96000
    const int smC = 4000*8 + 4000*4;        // 48000
    const int smD = 2000*8 + 2000*4;        // 24000
    const int smE = 1000*8 + 1000*4;        // 12000
    cudaFuncSetAttribute(k_fwd, cudaFuncAttributeMaxDynamicSharedMemorySize, smF);
    cudaFuncSetAttribute(k_bandT<8000,2,1024,1>, cudaFuncAttributeMaxDynamicSharedMemorySize, smB);
    cudaFuncSetAttribute(k_bandT<4000,4,512,2>,  cudaFuncAttributeMaxDynamicSharedMemorySize, smC);
    cudaFuncSetAttribute(k_bandT<2000,8,256,3>,  cudaFuncAttributeMaxDynamicSharedMemorySize, smD);
    cudaFuncSetAttribute(k_bandT<1000,16,128,4>, cudaFuncAttributeMaxDynamicSharedMemorySize, smE);
    prep_all<<<dim3(32, NF + 1), 256>>>();
    k_fwd<<<NB, NT, smF>>>(x);
    k_bandT<8000,2,1024,1> <<<dim3(6,  NB), 1024, smB>>>(0,  0);
    k_bandT<4000,4,512,2>  <<<dim3(6,  NB), 512,  smC>>>(6,  48000);
    k_bandT<2000,8,256,3>  <<<dim3(6,  NB), 256,  smD>>>(12, 72000);
    k_bandT<1000,16,128,4> <<<dim3(18, NB), 128,  smE>>>(18, 84000);
    k_reduce<<<(NB*3*NOUT + 255)/256, 256>>>(out);
}

// round 9
// speedup vs baseline: 1.9534x; 1.9534x over previous
#include <cuda_runtime.h>
#include <math.h>

#define TN 16000
#define NT 1024
#define NF 36
#define NB 64
#define NOUT 250
#define NTAPS 257
#define KPHI 569
#define NCH 37
#define TBL 102000

// ---------------- static device scratch ----------------
__device__ float2 d_X[NB * TN];        // scrambled forward FFT of x (8 MB, L2-resident)
__device__ int    d_idx[TBL];          // per-channel gather index into scrambled X
__device__ float  d_wt[TBL];           // per-channel psi_hat weight (incl 1/16000)
__device__ float  d_phiw[NTAPS];       // time-domain lowpass taps phi(d), d=-128..128
__device__ float2 d_rtA[128];          // W_16000^{-125 i}
__device__ float2 d_rtB[125];          // W_16000^{-i}
__device__ float  d_S1[NB * NCH * NOUT];

// ---------------- complex helpers ----------------
__device__ __forceinline__ float2 cmul(float2 a, float2 b) {
    return make_float2(a.x*b.x - a.y*b.y, a.x*b.y + a.y*b.x);
}
__device__ __forceinline__ float2 cadd(float2 a, float2 b){ return make_float2(a.x+b.x, a.y+b.y); }
__device__ __forceinline__ float2 csub(float2 a, float2 b){ return make_float2(a.x-b.x, a.y-b.y); }

// ---------------- prep kernels (R7-style: warp-parallel phi) ----------------
__global__ void prep_phi() {
    int tap  = blockIdx.x;
    int lane = threadIdx.x;
    int d = tap - 128;
    const double sp = 0.35 / 64.0;
    const double PI2 = 6.283185307179586476925286766559;
    double acc = 0.0;
    for (int k = 1 + lane; k <= KPHI; k += 32) {
        double f = (double)k / (double)TN;
        double g = exp(-f*f / (2.0*sp*sp));
        acc += g * cos(PI2 * (double)k * (double)d / (double)TN);
    }
    for (int o = 16; o; o >>= 1) acc += __shfl_down_sync(0xffffffffu, acc, o);
    if (lane == 0) d_phiw[tap] = (float)((1.0 + 2.0*acc) / (double)TN);
}

__global__ void prep_tw() {
    int i = threadIdx.x;
    if (i < 128) { double s, c; sincospi(-(double)i/64.0,   &s, &c); d_rtA[i] = make_float2((float)c, (float)s); }
    if (i < 125) { double s, c; sincospi(-(double)i/8000.0, &s, &c); d_rtB[i] = make_float2((float)c, (float)s); }
}

// per-channel decimated gather tables (float math; validated rel_err 4.8e-5)
__global__ void prep_band() {
    int q = blockIdx.x * blockDim.x + threadIdx.x;
    int j = blockIdx.y;
    int cls, NJ, off;
    if      (j <  6){ cls=1; NJ=8000; off = j*8000; }
    else if (j < 12){ cls=2; NJ=4000; off = 48000 + (j-6)*4000; }
    else if (j < 18){ cls=3; NJ=2000; off = 72000 + (j-12)*2000; }
    else            { cls=4; NJ=1000; off = 84000 + (j-18)*1000; }
    if (q >= NJ) return;
    // digit reversal for the class's DIT radix list -> natural frequency k
    int k;
    if      (cls == 1) { int a=q/4000, b=(q/1000)%4, c=(q/100)%10, d=(q/10)%10, e=q%10; k = a + 2*b + 8*c + 80*d + 800*e; }
    else if (cls == 2) { int b=q/1000, c=(q/100)%10, d=(q/10)%10, e=q%10; k = b + 4*c + 40*d + 400*e; }
    else if (cls == 3) { int a=q/1000, c=(q/100)%10, d=(q/10)%10, e=q%10; k = a + 2*c + 20*d + 200*e; }
    else               { int c=q/100, d=(q/10)%10, e=q%10; k = c + 10*d + 100*e; }
    // scrambled position of natural frequency k in the stored 16000 layout
    int e2 = k/1600, r = k - 1600*e2;
    int d2 = r/160;  r -= 160*d2;
    int c2 = r/16;   r -= 16*c2;
    int b2 = r/4,    a2 = r - 4*b2;
    int p = 4000*a2 + 1000*b2 + 100*c2 + 10*d2 + e2;
    float f = (k < 8000) ? (float)k/16000.0f : (float)(k - 16000)/16000.0f;
    float rr  = exp2f(1.0f/6.0f);
    float fac = (rr - 1.0f) / (rr + 1.0f);
    float xi = 0.35f * exp2f(-(float)j/6.0f);
    float sg = xi * fac;
    float u  = (f - xi) / sg;
    float v  = (u*u < 50.0f) ? __expf(-0.5f*u*u) : 0.0f;
    d_idx[off+q] = p;
    d_wt[off+q]  = v / 16000.0f;
}

// ---------------- small DFTs ----------------
template<int SIGN>
__device__ __forceinline__ void dft4(float2&z0,float2&z1,float2&z2,float2&z3){
    float2 t0=cadd(z0,z2), t1=csub(z0,z2), t2=cadd(z1,z3), t3=csub(z1,z3);
    const float s = (float)SIGN;
    z0 = cadd(t0,t2);
    z2 = csub(t0,t2);
    z1 = make_float2(t1.x - s*t3.y, t1.y + s*t3.x);
    z3 = make_float2(t1.x + s*t3.y, t1.y - s*t3.x);
}

template<int SIGN>
__device__ __forceinline__ void dft5(float2&z0,float2&z1,float2&z2,float2&z3,float2&z4){
    const float K1 =  0.309016994374947424f;
    const float K2 = -0.809016994374947424f;
    const float S1 =  0.951056516295153572f;
    const float S2 =  0.587785252292473129f;
    float2 t1=cadd(z1,z4), t2=cadd(z2,z3), t3=csub(z1,z4), t4=csub(z2,z3);
    float2 a = z0;
    float2 sum = cadd(a, cadd(t1,t2));
    float2 r1 = make_float2(a.x + K1*t1.x + K2*t2.x, a.y + K1*t1.y + K2*t2.y);
    float2 r2 = make_float2(a.x + K2*t1.x + K1*t2.x, a.y + K2*t1.y + K1*t2.y);
    float2 q1 = make_float2(S1*t3.x + S2*t4.x, S1*t3.y + S2*t4.y);
    float2 q2 = make_float2(S2*t3.x - S1*t4.x, S2*t3.y - S1*t4.y);
    const float s = (float)SIGN;
    z0 = sum;
    z1 = make_float2(r1.x - s*q1.y, r1.y + s*q1.x);
    z4 = make_float2(r1.x + s*q1.y, r1.y - s*q1.x);
    z2 = make_float2(r2.x - s*q2.y, r2.y + s*q2.x);
    z3 = make_float2(r2.x + s*q2.y, r2.y - s*q2.x);
}

__device__ __forceinline__ float2 twb(int x, const float2* rtA, const float2* rtB){
    int a = x / 125;
    return cmul(rtA[a], rtB[x - a*125]);
}

// ================= forward-only pieces (k_fwd, size 16000, NT threads) =================
__device__ void stage16_fwd(float2* buf, const float* xs, const float2* rtA, const float2* rtB){
    const float2 c16_1 = make_float2(0.92387953251128674f, -0.38268343236508977f);
    const float2 c16_2 = make_float2(0.70710678118654752f, -0.70710678118654752f);
    const float2 c16_3 = make_float2(0.38268343236508977f, -0.92387953251128674f);
    for (int p = threadIdx.x; p < 1000; p += NT) {
        float2 z[16];
        #pragma unroll
        for (int j=0;j<4;j++)
            #pragma unroll
            for (int i=0;i<4;i++)
                z[4*j+i] = make_float2(xs[p + 1000*j + 4000*i], 0.f);
        float2 a = twb(p, rtA, rtB);
        float2 b = twb(4*p, rtA, rtB);
        #pragma unroll
        for (int j=0;j<4;j++) dft4<-1>(z[4*j+0], z[4*j+1], z[4*j+2], z[4*j+3]);
        #pragma unroll
        for (int j=0;j<4;j++){
            float2 t = (j==0)? a : (j==1? cmul(a,c16_1) : (j==2? cmul(a,c16_2) : cmul(a,c16_3)));
            float2 t2 = cmul(t,t);
            z[4*j+1]=cmul(z[4*j+1],t); z[4*j+2]=cmul(z[4*j+2],t2); z[4*j+3]=cmul(z[4*j+3],cmul(t2,t));
        }
        #pragma unroll
        for (int s1=0;s1<4;s1++) dft4<-1>(z[s1], z[4+s1], z[8+s1], z[12+s1]);
        float2 b2 = cmul(b,b), b3 = cmul(b2,b);
        #pragma unroll
        for (int s1=0;s1<4;s1++){ z[4+s1]=cmul(z[4+s1],b); z[8+s1]=cmul(z[8+s1],b2); z[12+s1]=cmul(z[12+s1],b3); }
        #pragma unroll
        for (int s1=0;s1<4;s1++)
            #pragma unroll
            for (int s2=0;s2<4;s2++)
                buf[s1*4000 + s2*1000 + p] = z[4*s2+s1];
    }
    __syncthreads();
}

template<int M, int CC>
__device__ void stage10_fwd(float2* buf, const float2* rtA, const float2* rtB){
    const float c1x=0.809016994374947424f, c1y=0.587785252292473129f;
    const float c2x=0.309016994374947424f, c2y=0.951056516295153572f;
    const float2 w10_1 = make_float2( c1x, -c1y);
    const float2 w10_2 = make_float2( c2x, -c2y);
    const float2 w10_3 = make_float2(-c2x, -c2y);
    const float2 w10_4 = make_float2(-c1x, -c1y);
    for (int idx = threadIdx.x; idx < 1600; idx += NT) {
        int blk = idx / M;
        int p   = idx - blk*M;
        int o   = blk*(10*M) + p;
        float2 z[10];
        #pragma unroll
        for (int i=0;i<10;i++) z[i] = buf[o + M*i];
        float2 v = twb(CC*p, rtA, rtB);
        float2 b  = cmul(v,v);
        float2 b2 = cmul(b,b);
        float2 b3 = cmul(b2,b);
        float2 b4 = cmul(b2,b2);
        float2 m1 = cmul(w10_1, v);
        float2 m2 = cmul(w10_2, v);
        float2 m3 = cmul(w10_3, v);
        float2 m4 = cmul(w10_4, v);
        float2 e0=cadd(z[0],z[5]), e1=cadd(z[1],z[6]), e2=cadd(z[2],z[7]), e3=cadd(z[3],z[8]), e4=cadd(z[4],z[9]);
        float2 q0=cmul(csub(z[0],z[5]), v ), q1=cmul(csub(z[1],z[6]), m1),
               q2=cmul(csub(z[2],z[7]), m2), q3=cmul(csub(z[3],z[8]), m3),
               q4=cmul(csub(z[4],z[9]), m4);
        dft5<-1>(e0,e1,e2,e3,e4);
        dft5<-1>(q0,q1,q2,q3,q4);
        z[0]=e0;          z[1]=q0;
        z[2]=cmul(e1,b);  z[3]=cmul(q1,b);
        z[4]=cmul(e2,b2); z[5]=cmul(q2,b2);
        z[6]=cmul(e3,b3); z[7]=cmul(q3,b3);
        z[8]=cmul(e4,b4); z[9]=cmul(q4,b4);
        #pragma unroll
        for (int i=0;i<10;i++) buf[o + M*i] = z[i];
    }
    __syncthreads();
}

__device__ void stage10_fwd_store(const float2* buf, float2* __restrict__ Xo){
    const float c1x=0.809016994374947424f, c1y=0.587785252292473129f;
    const float c2x=0.309016994374947424f, c2y=0.951056516295153572f;
    const float2 w1 = make_float2( c1x, -c1y);
    const float2 w2 = make_float2( c2x, -c2y);
    const float2 w3 = make_float2(-c2x, -c2y);
    const float2 w4 = make_float2(-c1x, -c1y);
    for (int blk = threadIdx.x; blk < 1600; blk += NT) {
        int o = 10*blk;
        float2 z[10];
        #pragma unroll
        for (int i=0;i<10;i++) z[i] = buf[o+i];
        float2 e0=cadd(z[0],z[5]), e1=cadd(z[1],z[6]), e2=cadd(z[2],z[7]), e3=cadd(z[3],z[8]), e4=cadd(z[4],z[9]);
        float2 q0=csub(z[0],z[5]),           q1=cmul(csub(z[1],z[6]), w1),
               q2=cmul(csub(z[2],z[7]), w2), q3=cmul(csub(z[3],z[8]), w3),
               q4=cmul(csub(z[4],z[9]), w4);
        dft5<-1>(e0,e1,e2,e3,e4);
        dft5<-1>(q0,q1,q2,q3,q4);
        float4* X4 = (float4*)(Xo + o);
        X4[0] = make_float4(e0.x,e0.y,q0.x,q0.y);
        X4[1] = make_float4(e1.x,e1.y,q1.x,q1.y);
        X4[2] = make_float4(e2.x,e2.y,q2.x,q2.y);
        X4[3] = make_float4(e3.x,e3.y,q3.x,q3.y);
        X4[4] = make_float4(e4.x,e4.y,q4.x,q4.y);
    }
}

// ================= inverse pieces (generic over size / thread count) =================

// first DIT stage (radix-10, M=1, no twiddle): gather X via idx/wt tables
template<int THR>
__device__ void s10_load(float2* buf, const float2* __restrict__ Xb,
                         const int* __restrict__ idx, const float* __restrict__ wt, int cnt10){
    const float c1x=0.809016994374947424f, c1y=0.587785252292473129f;
    const float c2x=0.309016994374947424f, c2y=0.951056516295153572f;
    const float2 w1 = make_float2( c1x,  c1y);
    const float2 w2 = make_float2( c2x,  c2y);
    const float2 w3 = make_float2(-c2x,  c2y);
    const float2 w4 = make_float2(-c1x,  c1y);
    for (int blk = threadIdx.x; blk < cnt10; blk += THR) {
        int o = 10*blk;
        float2 z[10];
        #pragma unroll
        for (int i=0;i<10;i++){
            float2 v = Xb[idx[o+i]];
            float  w = wt[o+i];
            z[i] = make_float2(v.x*w, v.y*w);
        }
        float2 E0=z[0], E1=z[2], E2=z[4], E3=z[6], E4=z[8];
        float2 O0=z[1], O1=z[3], O2=z[5], O3=z[7], O4=z[9];
        dft5<1>(E0,E1,E2,E3,E4);
        dft5<1>(O0,O1,O2,O3,O4);
        O1=cmul(O1,w1); O2=cmul(O2,w2); O3=cmul(O3,w3); O4=cmul(O4,w4);
        buf[o  ]=cadd(E0,O0); buf[o+5]=csub(E0,O0);
        buf[o+1]=cadd(E1,O1); buf[o+6]=csub(E1,O1);
        buf[o+2]=cadd(E2,O2); buf[o+7]=csub(E2,O2);
        buf[o+3]=cadd(E3,O3); buf[o+8]=csub(E3,O3);
        buf[o+4]=cadd(E4,O4); buf[o+9]=csub(E4,O4);
    }
    __syncthreads();
}

// generic inverse radix-10 stage; if ABS, writes |z| to U instead of buf
template<int M, int CC, int THR, bool ABS>
__device__ void s10i(float2* buf, float* U, int cnt, const float2* rtA, const float2* rtB){
    const float c1x=0.809016994374947424f, c1y=0.587785252292473129f;
    const float c2x=0.309016994374947424f, c2y=0.951056516295153572f;
    const float2 w10_1 = make_float2( c1x,  c1y);
    const float2 w10_2 = make_float2( c2x,  c2y);
    const float2 w10_3 = make_float2(-c2x,  c2y);
    const float2 w10_4 = make_float2(-c1x,  c1y);
    for (int idx = threadIdx.x; idx < cnt; idx += THR) {
        int blk = idx / M;
        int p   = idx - blk*M;
        int o   = blk*(10*M) + p;
        float2 z[10];
        #pragma unroll
        for (int i=0;i<10;i++) z[i] = buf[o + M*i];
        float2 v = twb(CC*p, rtA, rtB);
        v.y = -v.y;
        float2 b  = cmul(v,v);
        float2 b2 = cmul(b,b);
        float2 b3 = cmul(b2,b);
        float2 b4 = cmul(b2,b2);
        float2 m1 = cmul(w10_1, v);
        float2 m2 = cmul(w10_2, v);
        float2 m3 = cmul(w10_3, v);
        float2 m4 = cmul(w10_4, v);
        float2 E0=z[0], E1=cmul(z[2],b), E2=cmul(z[4],b2), E3=cmul(z[6],b3), E4=cmul(z[8],b4);
        float2 O0=z[1], O1=cmul(z[3],b), O2=cmul(z[5],b2), O3=cmul(z[7],b3), O4=cmul(z[9],b4);
        dft5<1>(E0,E1,E2,E3,E4);
        dft5<1>(O0,O1,O2,O3,O4);
        O0=cmul(O0,v ); O1=cmul(O1,m1); O2=cmul(O2,m2); O3=cmul(O3,m3); O4=cmul(O4,m4);
        float2 y[10];
        y[0]=cadd(E0,O0); y[5]=csub(E0,O0);
        y[1]=cadd(E1,O1); y[6]=csub(E1,O1);
        y[2]=cadd(E2,O2); y[7]=csub(E2,O2);
        y[3]=cadd(E3,O3); y[8]=csub(E3,O3);
        y[4]=cadd(E4,O4); y[9]=csub(E4,O4);
        if (ABS) {
            #pragma unroll
            for (int i=0;i<10;i++) U[o + M*i] = sqrtf(y[i].x*y[i].x + y[i].y*y[i].y);
        } else {
            #pragma unroll
            for (int i=0;i<10;i++) buf[o + M*i] = y[i];
        }
    }
    __syncthreads();
}

// inverse radix-4 stage, M=1000, sub-length 4000 (twiddle = conj W_16000^{4p s})
template<int THR, bool ABS>
__device__ void s4i(float2* buf, float* U, int cnt, const float2* rtA, const float2* rtB){
    for (int idx = threadIdx.x; idx < cnt; idx += THR) {
        int blk = idx / 1000;
        int p   = idx - blk*1000;
        int o   = blk*4000 + p;
        float2 z0=buf[o], z1=buf[o+1000], z2=buf[o+2000], z3=buf[o+3000];
        float2 w1 = twb(4*p, rtA, rtB); w1.y = -w1.y;
        float2 w2 = cmul(w1,w1), w3 = cmul(w2,w1);
        z1=cmul(z1,w1); z2=cmul(z2,w2); z3=cmul(z3,w3);
        dft4<1>(z0,z1,z2,z3);
        if (ABS) {
            U[o]      = sqrtf(z0.x*z0.x + z0.y*z0.y);
            U[o+1000] = sqrtf(z1.x*z1.x + z1.y*z1.y);
            U[o+2000] = sqrtf(z2.x*z2.x + z2.y*z2.y);
            U[o+3000] = sqrtf(z3.x*z3.x + z3.y*z3.y);
        } else {
            buf[o]=z0; buf[o+1000]=z1; buf[o+2000]=z2; buf[o+3000]=z3;
        }
    }
    __syncthreads();
}

// inverse radix-2 stage, half-offset M2, twiddle conj W_16000^{DD p}
template<int THR, int M2, int DD>
__device__ void s2i_abs(float2* buf, float* U, const float2* rtA, const float2* rtB){
    for (int p = threadIdx.x; p < M2; p += THR) {
        float2 a = buf[p];
        float2 w = twb(DD*p, rtA, rtB); w.y = -w.y;
        float2 bb = cmul(buf[p+M2], w);
        float2 y0 = cadd(a,bb), y1 = csub(a,bb);
        U[p]    = sqrtf(y0.x*y0.x + y0.y*y0.y);
        U[p+M2] = sqrtf(y1.x*y1.x + y1.y*y1.y);
    }
    __syncthreads();
}

// ================= shared small helpers =================
template<int THR>
__device__ void init_tables(float2* rtA, float2* rtB, float* sphi){
    for (int i = threadIdx.x; i < 128; i += THR) rtA[i] = d_rtA[i];
    for (int i = threadIdx.x; i < 125; i += THR) rtB[i] = d_rtB[i];
    for (int i = threadIdx.x; i < NTAPS; i += THR) sphi[i] = d_phiw[i];
}

// decimated smoothing: S1[m] = DEC * sum_i phi(DEC*i) * U[(64m/DEC - i) mod NJ]
template<int NJ, int DEC, int THR>
__device__ void smooth_dec(const float* __restrict__ S, const float* __restrict__ sphi, float* dst){
    const int T = 128 / DEC;
    const int ITER = (2*T + 1 + 31) / 32;
    int w = threadIdx.x >> 5, l = threadIdx.x & 31;
    for (int m0 = w; m0 < NOUT; m0 += THR/32) {
        int tau = (64/DEC) * m0;
        float acc = 0.f;
        #pragma unroll
        for (int it = 0; it < ITER; ++it) {
            int tl = l + 32*it;
            if (tl <= 2*T) {
                int i = tl - T;
                int id = tau - i;
                if (id >= NJ) id -= NJ;
                if (id < 0)   id += NJ;
                acc += sphi[DEC*i + 128] * S[id];
            }
        }
        #pragma unroll
        for (int o = 16; o; o >>= 1) acc += __shfl_down_sync(0xffffffffu, acc, o);
        if (l == 0) dst[m0] = acc * (float)DEC;
    }
}

// ---------------- kernel 1: forward FFT of x (+ S0) ----------------
__global__ __launch_bounds__(NT, 1) void k_fwd(const float* __restrict__ x){
    extern __shared__ __align__(16) unsigned char sm[];
    float2* buf = (float2*)sm;
    float*  xs  = (float*)(sm + TN*sizeof(float2));
    __shared__ float2 rtA[128]; __shared__ float2 rtB[125]; __shared__ float sphi[NTAPS];
    int b = blockIdx.x;
    init_tables<NT>(rtA, rtB, sphi);
    const float4* xb4 = (const float4*)(x + b*TN);
    float4* xs4 = (float4*)xs;
    for (int n = threadIdx.x; n < TN/4; n += NT) xs4[n] = xb4[n];
    __syncthreads();
    smooth_dec<TN,1,NT>(xs, sphi, &d_S1[(b*NCH + 0)*NOUT]);
    stage16_fwd(buf, xs, rtA, rtB);
    stage10_fwd<100,16>(buf, rtA, rtB);
    stage10_fwd<10,160>(buf, rtA, rtB);
    stage10_fwd_store(buf, d_X + b*TN);
}

// ---------------- kernel 2: per-class band-pass ifft + |.| + smoothing ----------------
// CLS: 1=B(8000,D2) 2=C(4000,D4) 3=D(2000,D8) 4=E(1000,D16)
template<int NJ, int DEC, int THR, int CLS>
__global__ __launch_bounds__(THR, 1) void k_bandT(int j0, int off0){
    extern __shared__ __align__(16) unsigned char sm[];
    float2* buf = (float2*)sm;
    float*  U   = (float*)(sm + NJ*sizeof(float2));
    __shared__ float2 rtA[128]; __shared__ float2 rtB[125]; __shared__ float sphi[NTAPS];
    int jc = blockIdx.x, b = blockIdx.y;
    int j = j0 + jc;
    init_tables<THR>(rtA, rtB, sphi);
    __syncthreads();
    const float2* Xb = d_X + b*TN;
    const int*   idx = d_idx + off0 + jc*NJ;
    const float* wt  = d_wt  + off0 + jc*NJ;
    s10_load<THR>(buf, Xb, idx, wt, NJ/10);
    s10i<10,160,THR,false>(buf, U, NJ/10, rtA, rtB);
    if (CLS == 4) {
        s10i<100,16,THR,true>(buf, U, NJ/10, rtA, rtB);
    } else {
        s10i<100,16,THR,false>(buf, U, NJ/10, rtA, rtB);
        if (CLS == 1) { s4i<THR,false>(buf, U, 2000, rtA, rtB); s2i_abs<THR,4000,2>(buf, U, rtA, rtB); }
        if (CLS == 2) s4i<THR,true>(buf, U, 1000, rtA, rtB);
        if (CLS == 3) s2i_abs<THR,1000,8>(buf, U, rtA, rtB);
    }
    smooth_dec<NJ,DEC,THR>(U, sphi, &d_S1[(b*NCH + 1 + j)*NOUT]);
}

// ---------------- kernel 3: channel-group means ----------------
__global__ void k_reduce(float* __restrict__ out){
    int i = blockIdx.x * blockDim.x + threadIdx.x;
    if (i >= NB*3*NOUT) return;
    int m0 = i % NOUT;
    int g  = (i / NOUT) % 3;
    int b  = i / (3*NOUT);
    int c0 = (g==0) ? 0 : (g==1 ? 12 : 24);
    int nc = (g==2) ? 13 : 12;
    float acc = 0.f;
    for (int c = 0; c < nc; ++c) acc += d_S1[(b*NCH + c0 + c)*NOUT + m0];
    out[i] = acc / (float)nc;
}

// ---------------- launch ----------------
extern "C" void kernel_launch(void* const* d_in, const int* in_sizes, int n_in,
                              void* d_out, int out_size) {
    (void)in_sizes; (void)n_in; (void)out_size;
    const float* x = (const float*)d_in[0];
    float* out = (float*)d_out;
    const int smF = TN*8 + TN*4;            // 192000
    const int smB = 8000*8 + 8000*4;        // 96000
    const int smC = 4000*8 + 4000*4;        // 48000
    const int smD = 2000*8 + 2000*4;        // 24000
    const int smE = 1000*8 + 1000*4;        // 12000
    cudaFuncSetAttribute(k_fwd, cudaFuncAttributeMaxDynamicSharedMemorySize, smF);
    cudaFuncSetAttribute(k_bandT<8000,2,512,1>,  cudaFuncAttributeMaxDynamicSharedMemorySize, smB);
    cudaFuncSetAttribute(k_bandT<4000,4,512,2>,  cudaFuncAttributeMaxDynamicSharedMemorySize, smC);
    cudaFuncSetAttribute(k_bandT<2000,8,256,3>,  cudaFuncAttributeMaxDynamicSharedMemorySize, smD);
    cudaFuncSetAttribute(k_bandT<1000,16,128,4>, cudaFuncAttributeMaxDynamicSharedMemorySize, smE);
    prep_phi<<<NTAPS, 32>>>();
    prep_tw<<<1, 128>>>();
    prep_band<<<dim3(32, NF), 256>>>();
    k_fwd<<<NB, NT, smF>>>(x);
    k_bandT<8000,2,512,1>  <<<dim3(6,  NB), 512,  smB>>>(0,  0);
    k_bandT<4000,4,512,2>  <<<dim3(6,  NB), 512,  smC>>>(6,  48000);
    k_bandT<2000,8,256,3>  <<<dim3(6,  NB), 256,  smD>>>(12, 72000);
    k_bandT<1000,16,128,4> <<<dim3(18, NB), 128,  smE>>>(18, 84000);
    k_reduce<<<(NB*3*NOUT + 255)/256, 256>>>(out);
}

// round 10
// speedup vs baseline: 1.9830x; 1.0151x over previous
#include <cuda_runtime.h>
#include <math.h>

#define TN 16000
#define NT 1024
#define NF 36
#define NB 64
#define NOUT 250
#define NTAPS 257
#define KPHI 569
#define NCH 37
#define TBL 89000

// ---------------- static device scratch ----------------
__device__ float2 d_X[NB * TN];        // scrambled forward FFT of x (8 MB, L2-resident)
__device__ int    d_idx[TBL];          // per-channel gather index into scrambled X
__device__ float  d_wt[TBL];           // per-channel psi_hat weight (incl 1/16000)
__device__ float  d_phiw[NTAPS];       // time-domain lowpass taps phi(d), d=-128..128
__device__ float2 d_rtA[128];          // W_16000^{-125 i}
__device__ float2 d_rtB[125];          // W_16000^{-i}
__device__ float  d_S1[NB * NCH * NOUT];

// ---------------- complex helpers ----------------
__device__ __forceinline__ float2 cmul(float2 a, float2 b) {
    return make_float2(a.x*b.x - a.y*b.y, a.x*b.y + a.y*b.x);
}
__device__ __forceinline__ float2 cadd(float2 a, float2 b){ return make_float2(a.x+b.x, a.y+b.y); }
__device__ __forceinline__ float2 csub(float2 a, float2 b){ return make_float2(a.x-b.x, a.y-b.y); }

// ---------------- prep kernels (phi taps warp-parallel; twiddle roots folded in) ----------------
__global__ void prep_phi() {
    int blk  = blockIdx.x;
    int lane = threadIdx.x;
    if (blk >= NTAPS) {
        int i = (blk - NTAPS)*32 + lane;
        if (i < 128) { double s, c; sincospi(-(double)i/64.0,   &s, &c); d_rtA[i] = make_float2((float)c, (float)s); }
        else if (i < 253) { int t = i - 128; double s, c; sincospi(-(double)t/8000.0, &s, &c); d_rtB[t] = make_float2((float)c, (float)s); }
        return;
    }
    int d = blk - 128;
    const double sp = 0.35 / 64.0;
    const double PI2 = 6.283185307179586476925286766559;
    double acc = 0.0;
    for (int k = 1 + lane; k <= KPHI; k += 32) {
        double f = (double)k / (double)TN;
        double g = exp(-f*f / (2.0*sp*sp));
        acc += g * cos(PI2 * (double)k * (double)d / (double)TN);
    }
    for (int o = 16; o; o >>= 1) acc += __shfl_down_sync(0xffffffffu, acc, o);
    if (lane == 0) d_phiw[blk] = (float)((1.0 + 2.0*acc) / (double)TN);
}

// per-channel windowed (zoom) gather tables: position q holds natural bin k_lo + rev(q)
__global__ void prep_band() {
    int q = blockIdx.x * blockDim.x + threadIdx.x;
    int j = blockIdx.y;
    int cls, NJ, off;
    if      (j <  3){ cls=1; NJ=8000; off = j*8000; }
    else if (j < 10){ cls=2; NJ=4000; off = 24000 + (j-3)*4000; }
    else if (j < 21){ cls=3; NJ=2000; off = 52000 + (j-10)*2000; }
    else            { cls=4; NJ=1000; off = 74000 + (j-21)*1000; }
    if (q >= NJ) return;
    // digit reversal for the class's DIT radix list -> natural LOCAL frequency kq
    int kq;
    if      (cls == 1) { int a=q/4000, b=(q/1000)%4, c=(q/100)%10, d=(q/10)%10, e=q%10; kq = a + 2*b + 8*c + 80*d + 800*e; }
    else if (cls == 2) { int b=q/1000, c=(q/100)%10, d=(q/10)%10, e=q%10; kq = b + 4*c + 40*d + 400*e; }
    else if (cls == 3) { int a=q/1000, c=(q/100)%10, d=(q/10)%10, e=q%10; kq = a + 2*c + 20*d + 200*e; }
    else               { int c=q/100, d=(q/10)%10, e=q%10; kq = c + 10*d + 100*e; }
    // spectral window start: center the band (|.| kills the demodulation carrier)
    float xi = 0.35f * exp2f(-(float)j/6.0f);
    int k_lo = (int)(xi * 16000.0f) - NJ/2;
    if (k_lo < 0) k_lo = 0;
    int k = k_lo + kq;   // natural global bin, < 16000 for all classes
    // scrambled position of natural frequency k in the stored 16000 layout
    int e2 = k/1600, r = k - 1600*e2;
    int d2 = r/160;  r -= 160*d2;
    int c2 = r/16;   r -= 16*c2;
    int b2 = r/4,    a2 = r - 4*b2;
    int p = 4000*a2 + 1000*b2 + 100*c2 + 10*d2 + e2;
    float f = (k < 8000) ? (float)k/16000.0f : (float)(k - 16000)/16000.0f;
    float rr  = exp2f(1.0f/6.0f);
    float fac = (rr - 1.0f) / (rr + 1.0f);
    float sg = xi * fac;
    float u  = (f - xi) / sg;
    float v  = (u*u < 50.0f) ? __expf(-0.5f*u*u) : 0.0f;
    d_idx[off+q] = p;
    d_wt[off+q]  = v / 16000.0f;
}

// ---------------- small DFTs ----------------
template<int SIGN>
__device__ __forceinline__ void dft4(float2&z0,float2&z1,float2&z2,float2&z3){
    float2 t0=cadd(z0,z2), t1=csub(z0,z2), t2=cadd(z1,z3), t3=csub(z1,z3);
    const float s = (float)SIGN;
    z0 = cadd(t0,t2);
    z2 = csub(t0,t2);
    z1 = make_float2(t1.x - s*t3.y, t1.y + s*t3.x);
    z3 = make_float2(t1.x + s*t3.y, t1.y - s*t3.x);
}

template<int SIGN>
__device__ __forceinline__ void dft5(float2&z0,float2&z1,float2&z2,float2&z3,float2&z4){
    const float K1 =  0.309016994374947424f;
    const float K2 = -0.809016994374947424f;
    const float S1 =  0.951056516295153572f;
    const float S2 =  0.587785252292473129f;
    float2 t1=cadd(z1,z4), t2=cadd(z2,z3), t3=csub(z1,z4), t4=csub(z2,z3);
    float2 a = z0;
    float2 sum = cadd(a, cadd(t1,t2));
    float2 r1 = make_float2(a.x + K1*t1.x + K2*t2.x, a.y + K1*t1.y + K2*t2.y);
    float2 r2 = make_float2(a.x + K2*t1.x + K1*t2.x, a.y + K2*t1.y + K1*t2.y);
    float2 q1 = make_float2(S1*t3.x + S2*t4.x, S1*t3.y + S2*t4.y);
    float2 q2 = make_float2(S2*t3.x - S1*t4.x, S2*t3.y - S1*t4.y);
    const float s = (float)SIGN;
    z0 = sum;
    z1 = make_float2(r1.x - s*q1.y, r1.y + s*q1.x);
    z4 = make_float2(r1.x + s*q1.y, r1.y - s*q1.x);
    z2 = make_float2(r2.x - s*q2.y, r2.y + s*q2.x);
    z3 = make_float2(r2.x + s*q2.y, r2.y - s*q2.x);
}

__device__ __forceinline__ float2 twb(int x, const float2* rtA, const float2* rtB){
    int a = x / 125;
    return cmul(rtA[a], rtB[x - a*125]);
}

// ================= forward-only pieces (k_fwd, size 16000, NT threads) =================
__device__ void stage16_fwd(float2* buf, const float* xs, const float2* rtA, const float2* rtB){
    const float2 c16_1 = make_float2(0.92387953251128674f, -0.38268343236508977f);
    const float2 c16_2 = make_float2(0.70710678118654752f, -0.70710678118654752f);
    const float2 c16_3 = make_float2(0.38268343236508977f, -0.92387953251128674f);
    for (int p = threadIdx.x; p < 1000; p += NT) {
        float2 z[16];
        #pragma unroll
        for (int j=0;j<4;j++)
            #pragma unroll
            for (int i=0;i<4;i++)
                z[4*j+i] = make_float2(xs[p + 1000*j + 4000*i], 0.f);
        float2 a = twb(p, rtA, rtB);
        float2 b = twb(4*p, rtA, rtB);
        #pragma unroll
        for (int j=0;j<4;j++) dft4<-1>(z[4*j+0], z[4*j+1], z[4*j+2], z[4*j+3]);
        #pragma unroll
        for (int j=0;j<4;j++){
            float2 t = (j==0)? a : (j==1? cmul(a,c16_1) : (j==2? cmul(a,c16_2) : cmul(a,c16_3)));
            float2 t2 = cmul(t,t);
            z[4*j+1]=cmul(z[4*j+1],t); z[4*j+2]=cmul(z[4*j+2],t2); z[4*j+3]=cmul(z[4*j+3],cmul(t2,t));
        }
        #pragma unroll
        for (int s1=0;s1<4;s1++) dft4<-1>(z[s1], z[4+s1], z[8+s1], z[12+s1]);
        float2 b2 = cmul(b,b), b3 = cmul(b2,b);
        #pragma unroll
        for (int s1=0;s1<4;s1++){ z[4+s1]=cmul(z[4+s1],b); z[8+s1]=cmul(z[8+s1],b2); z[12+s1]=cmul(z[12+s1],b3); }
        #pragma unroll
        for (int s1=0;s1<4;s1++)
            #pragma unroll
            for (int s2=0;s2<4;s2++)
                buf[s1*4000 + s2*1000 + p] = z[4*s2+s1];
    }
    __syncthreads();
}

template<int M, int CC>
__device__ void stage10_fwd(float2* buf, const float2* rtA, const float2* rtB){
    const float c1x=0.809016994374947424f, c1y=0.587785252292473129f;
    const float c2x=0.309016994374947424f, c2y=0.951056516295153572f;
    const float2 w10_1 = make_float2( c1x, -c1y);
    const float2 w10_2 = make_float2( c2x, -c2y);
    const float2 w10_3 = make_float2(-c2x, -c2y);
    const float2 w10_4 = make_float2(-c1x, -c1y);
    for (int idx = threadIdx.x; idx < 1600; idx += NT) {
        int blk = idx / M;
        int p   = idx - blk*M;
        int o   = blk*(10*M) + p;
        float2 z[10];
        #pragma unroll
        for (int i=0;i<10;i++) z[i] = buf[o + M*i];
        float2 v = twb(CC*p, rtA, rtB);
        float2 b  = cmul(v,v);
        float2 b2 = cmul(b,b);
        float2 b3 = cmul(b2,b);
        float2 b4 = cmul(b2,b2);
        float2 m1 = cmul(w10_1, v);
        float2 m2 = cmul(w10_2, v);
        float2 m3 = cmul(w10_3, v);
        float2 m4 = cmul(w10_4, v);
        float2 e0=cadd(z[0],z[5]), e1=cadd(z[1],z[6]), e2=cadd(z[2],z[7]), e3=cadd(z[3],z[8]), e4=cadd(z[4],z[9]);
        float2 q0=cmul(csub(z[0],z[5]), v ), q1=cmul(csub(z[1],z[6]), m1),
               q2=cmul(csub(z[2],z[7]), m2), q3=cmul(csub(z[3],z[8]), m3),
               q4=cmul(csub(z[4],z[9]), m4);
        dft5<-1>(e0,e1,e2,e3,e4);
        dft5<-1>(q0,q1,q2,q3,q4);
        z[0]=e0;          z[1]=q0;
        z[2]=cmul(e1,b);  z[3]=cmul(q1,b);
        z[4]=cmul(e2,b2); z[5]=cmul(q2,b2);
        z[6]=cmul(e3,b3); z[7]=cmul(q3,b3);
        z[8]=cmul(e4,b4); z[9]=cmul(q4,b4);
        #pragma unroll
        for (int i=0;i<10;i++) buf[o + M*i] = z[i];
    }
    __syncthreads();
}

__device__ void stage10_fwd_store(const float2* buf, float2* __restrict__ Xo){
    const float c1x=0.809016994374947424f, c1y=0.587785252292473129f;
    const float c2x=0.309016994374947424f, c2y=0.951056516295153572f;
    const float2 w1 = make_float2( c1x, -c1y);
    const float2 w2 = make_float2( c2x, -c2y);
    const float2 w3 = make_float2(-c2x, -c2y);
    const float2 w4 = make_float2(-c1x, -c1y);
    for (int blk = threadIdx.x; blk < 1600; blk += NT) {
        int o = 10*blk;
        float2 z[10];
        #pragma unroll
        for (int i=0;i<10;i++) z[i] = buf[o+i];
        float2 e0=cadd(z[0],z[5]), e1=cadd(z[1],z[6]), e2=cadd(z[2],z[7]), e3=cadd(z[3],z[8]), e4=cadd(z[4],z[9]);
        float2 q0=csub(z[0],z[5]),           q1=cmul(csub(z[1],z[6]), w1),
               q2=cmul(csub(z[2],z[7]), w2), q3=cmul(csub(z[3],z[8]), w3),
               q4=cmul(csub(z[4],z[9]), w4);
        dft5<-1>(e0,e1,e2,e3,e4);
        dft5<-1>(q0,q1,q2,q3,q4);
        float4* X4 = (float4*)(Xo + o);
        X4[0] = make_float4(e0.x,e0.y,q0.x,q0.y);
        X4[1] = make_float4(e1.x,e1.y,q1.x,q1.y);
        X4[2] = make_float4(e2.x,e2.y,q2.x,q2.y);
        X4[3] = make_float4(e3.x,e3.y,q3.x,q3.y);
        X4[4] = make_float4(e4.x,e4.y,q4.x,q4.y);
    }
}

// ================= inverse pieces (generic over size / thread count) =================

// first DIT stage (radix-10, M=1, no twiddle): gather X via idx/wt tables
template<int THR>
__device__ void s10_load(float2* buf, const float2* __restrict__ Xb,
                         const int* __restrict__ idx, const float* __restrict__ wt, int cnt10){
    const float c1x=0.809016994374947424f, c1y=0.587785252292473129f;
    const float c2x=0.309016994374947424f, c2y=0.951056516295153572f;
    const float2 w1 = make_float2( c1x,  c1y);
    const float2 w2 = make_float2( c2x,  c2y);
    const float2 w3 = make_float2(-c2x,  c2y);
    const float2 w4 = make_float2(-c1x,  c1y);
    for (int blk = threadIdx.x; blk < cnt10; blk += THR) {
        int o = 10*blk;
        float2 z[10];
        #pragma unroll
        for (int i=0;i<10;i++){
            float2 v = Xb[idx[o+i]];
            float  w = wt[o+i];
            z[i] = make_float2(v.x*w, v.y*w);
        }
        float2 E0=z[0], E1=z[2], E2=z[4], E3=z[6], E4=z[8];
        float2 O0=z[1], O1=z[3], O2=z[5], O3=z[7], O4=z[9];
        dft5<1>(E0,E1,E2,E3,E4);
        dft5<1>(O0,O1,O2,O3,O4);
        O1=cmul(O1,w1); O2=cmul(O2,w2); O3=cmul(O3,w3); O4=cmul(O4,w4);
        buf[o  ]=cadd(E0,O0); buf[o+5]=csub(E0,O0);
        buf[o+1]=cadd(E1,O1); buf[o+6]=csub(E1,O1);
        buf[o+2]=cadd(E2,O2); buf[o+7]=csub(E2,O2);
        buf[o+3]=cadd(E3,O3); buf[o+8]=csub(E3,O3);
        buf[o+4]=cadd(E4,O4); buf[o+9]=csub(E4,O4);
    }
    __syncthreads();
}

// generic inverse radix-10 stage; if ABS, writes |z| to U instead of buf
template<int M, int CC, int THR, bool ABS>
__device__ void s10i(float2* buf, float* U, int cnt, const float2* rtA, const float2* rtB){
    const float c1x=0.809016994374947424f, c1y=0.587785252292473129f;
    const float c2x=0.309016994374947424f, c2y=0.951056516295153572f;
    const float2 w10_1 = make_float2( c1x,  c1y);
    const float2 w10_2 = make_float2( c2x,  c2y);
    const float2 w10_3 = make_float2(-c2x,  c2y);
    const float2 w10_4 = make_float2(-c1x,  c1y);
    for (int idx = threadIdx.x; idx < cnt; idx += THR) {
        int blk = idx / M;
        int p   = idx - blk*M;
        int o   = blk*(10*M) + p;
        float2 z[10];
        #pragma unroll
        for (int i=0;i<10;i++) z[i] = buf[o + M*i];
        float2 v = twb(CC*p, rtA, rtB);
        v.y = -v.y;
        float2 b  = cmul(v,v);
        float2 b2 = cmul(b,b);
        float2 b3 = cmul(b2,b);
        float2 b4 = cmul(b2,b2);
        float2 m1 = cmul(w10_1, v);
        float2 m2 = cmul(w10_2, v);
        float2 m3 = cmul(w10_3, v);
        float2 m4 = cmul(w10_4, v);
        float2 E0=z[0], E1=cmul(z[2],b), E2=cmul(z[4],b2), E3=cmul(z[6],b3), E4=cmul(z[8],b4);
        float2 O0=z[1], O1=cmul(z[3],b), O2=cmul(z[5],b2), O3=cmul(z[7],b3), O4=cmul(z[9],b4);
        dft5<1>(E0,E1,E2,E3,E4);
        dft5<1>(O0,O1,O2,O3,O4);
        O0=cmul(O0,v ); O1=cmul(O1,m1); O2=cmul(O2,m2); O3=cmul(O3,m3); O4=cmul(O4,m4);
        float2 y[10];
        y[0]=cadd(E0,O0); y[5]=csub(E0,O0);
        y[1]=cadd(E1,O1); y[6]=csub(E1,O1);
        y[2]=cadd(E2,O2); y[7]=csub(E2,O2);
        y[3]=cadd(E3,O3); y[8]=csub(E3,O3);
        y[4]=cadd(E4,O4); y[9]=csub(E4,O4);
        if (ABS) {
            #pragma unroll
            for (int i=0;i<10;i++) U[o + M*i] = sqrtf(y[i].x*y[i].x + y[i].y*y[i].y);
        } else {
            #pragma unroll
            for (int i=0;i<10;i++) buf[o + M*i] = y[i];
        }
    }
    __syncthreads();
}

// inverse radix-4 stage, M=1000, sub-length 4000 (twiddle = conj W_16000^{4p s})
template<int THR, bool ABS>
__device__ void s4i(float2* buf, float* U, int cnt, const float2* rtA, const float2* rtB){
    for (int idx = threadIdx.x; idx < cnt; idx += THR) {
        int blk = idx / 1000;
        int p   = idx - blk*1000;
        int o   = blk*4000 + p;
        float2 z0=buf[o], z1=buf[o+1000], z2=buf[o+2000], z3=buf[o+3000];
        float2 w1 = twb(4*p, rtA, rtB); w1.y = -w1.y;
        float2 w2 = cmul(w1,w1), w3 = cmul(w2,w1);
        z1=cmul(z1,w1); z2=cmul(z2,w2); z3=cmul(z3,w3);
        dft4<1>(z0,z1,z2,z3);
        if (ABS) {
            U[o]      = sqrtf(z0.x*z0.x + z0.y*z0.y);
            U[o+1000] = sqrtf(z1.x*z1.x + z1.y*z1.y);
            U[o+2000] = sqrtf(z2.x*z2.x + z2.y*z2.y);
            U[o+3000] = sqrtf(z3.x*z3.x + z3.y*z3.y);
        } else {
            buf[o]=z0; buf[o+1000]=z1; buf[o+2000]=z2; buf[o+3000]=z3;
        }
    }
    __syncthreads();
}

// inverse radix-2 stage, half-offset M2, twiddle conj W_16000^{DD p}
template<int THR, int M2, int DD>
__device__ void s2i_abs(float2* buf, float* U, const float2* rtA, const float2* rtB){
    for (int p = threadIdx.x; p < M2; p += THR) {
        float2 a = buf[p];
        float2 w = twb(DD*p, rtA, rtB); w.y = -w.y;
        float2 bb = cmul(buf[p+M2], w);
        float2 y0 = cadd(a,bb), y1 = csub(a,bb);
        U[p]    = sqrtf(y0.x*y0.x + y0.y*y0.y);
        U[p+M2] = sqrtf(y1.x*y1.x + y1.y*y1.y);
    }
    __syncthreads();
}

// ================= shared small helpers =================
template<int THR>
__device__ void init_tables(float2* rtA, float2* rtB, float* sphi){
    for (int i = threadIdx.x; i < 128; i += THR) rtA[i] = d_rtA[i];
    for (int i = threadIdx.x; i < 125; i += THR) rtB[i] = d_rtB[i];
    for (int i = threadIdx.x; i < NTAPS; i += THR) sphi[i] = d_phiw[i];
}

// decimated smoothing: S1[m] = DEC * sum_i phi(DEC*i) * U[(64m/DEC - i) mod NJ]
template<int NJ, int DEC, int THR>
__device__ void smooth_dec(const float* __restrict__ S, const float* __restrict__ sphi, float* dst){
    const int T = 128 / DEC;
    const int ITER = (2*T + 1 + 31) / 32;
    int w = threadIdx.x >> 5, l = threadIdx.x & 31;
    for (int m0 = w; m0 < NOUT; m0 += THR/32) {
        int tau = (64/DEC) * m0;
        float acc = 0.f;
        #pragma unroll
        for (int it = 0; it < ITER; ++it) {
            int tl = l + 32*it;
            if (tl <= 2*T) {
                int i = tl - T;
                int id = tau - i;
                if (id >= NJ) id -= NJ;
                if (id < 0)   id += NJ;
                acc += sphi[DEC*i + 128] * S[id];
            }
        }
        #pragma unroll
        for (int o = 16; o; o >>= 1) acc += __shfl_down_sync(0xffffffffu, acc, o);
        if (l == 0) dst[m0] = acc * (float)DEC;
    }
}

// ---------------- kernel 1: forward FFT of x (+ S0) ----------------
__global__ __launch_bounds__(NT, 1) void k_fwd(const float* __restrict__ x){
    extern __shared__ __align__(16) unsigned char sm[];
    float2* buf = (float2*)sm;
    float*  xs  = (float*)(sm + TN*sizeof(float2));
    __shared__ float2 rtA[128]; __shared__ float2 rtB[125]; __shared__ float sphi[NTAPS];
    int b = blockIdx.x;
    init_tables<NT>(rtA, rtB, sphi);
    const float4* xb4 = (const float4*)(x + b*TN);
    float4* xs4 = (float4*)xs;
    for (int n = threadIdx.x; n < TN/4; n += NT) xs4[n] = xb4[n];
    __syncthreads();
    smooth_dec<TN,1,NT>(xs, sphi, &d_S1[(b*NCH + 0)*NOUT]);
    stage16_fwd(buf, xs, rtA, rtB);
    stage10_fwd<100,16>(buf, rtA, rtB);
    stage10_fwd<10,160>(buf, rtA, rtB);
    stage10_fwd_store(buf, d_X + b*TN);
}

// ---------------- kernel 2: per-class band-pass ifft + |.| + smoothing ----------------
// CLS: 1=B(8000,D2) 2=C(4000,D4) 3=D(2000,D8) 4=E(1000,D16)
template<int NJ, int DEC, int THR, int CLS>
__global__ __launch_bounds__(THR, 1) void k_bandT(int j0, int off0){
    extern __shared__ __align__(16) unsigned char sm[];
    float2* buf = (float2*)sm;
    float*  U   = (float*)(sm + NJ*sizeof(float2));
    __shared__ float2 rtA[128]; __shared__ float2 rtB[125]; __shared__ float sphi[NTAPS];
    int jc = blockIdx.x, b = blockIdx.y;
    int j = j0 + jc;
    init_tables<THR>(rtA, rtB, sphi);
    __syncthreads();
    const float2* Xb = d_X + b*TN;
    const int*   idx = d_idx + off0 + jc*NJ;
    const float* wt  = d_wt  + off0 + jc*NJ;
    s10_load<THR>(buf, Xb, idx, wt, NJ/10);
    s10i<10,160,THR,false>(buf, U, NJ/10, rtA, rtB);
    if (CLS == 4) {
        s10i<100,16,THR,true>(buf, U, NJ/10, rtA, rtB);
    } else {
        s10i<100,16,THR,false>(buf, U, NJ/10, rtA, rtB);
        if (CLS == 1) { s4i<THR,false>(buf, U, 2000, rtA, rtB); s2i_abs<THR,4000,2>(buf, U, rtA, rtB); }
        if (CLS == 2) s4i<THR,true>(buf, U, 1000, rtA, rtB);
        if (CLS == 3) s2i_abs<THR,1000,8>(buf, U, rtA, rtB);
    }
    smooth_dec<NJ,DEC,THR>(U, sphi, &d_S1[(b*NCH + 1 + j)*NOUT]);
}

// ---------------- kernel 3: channel-group means ----------------
__global__ void k_reduce(float* __restrict__ out){
    int i = blockIdx.x * blockDim.x + threadIdx.x;
    if (i >= NB*3*NOUT) return;
    int m0 = i % NOUT;
    int g  = (i / NOUT) % 3;
    int b  = i / (3*NOUT);
    int c0 = (g==0) ? 0 : (g==1 ? 12 : 24);
    int nc = (g==2) ? 13 : 12;
    float acc = 0.f;
    for (int c = 0; c < nc; ++c) acc += d_S1[(b*NCH + c0 + c)*NOUT + m0];
    out[i] = acc / (float)nc;
}

// ---------------- launch ----------------
extern "C" void kernel_launch(void* const* d_in, const int* in_sizes, int n_in,
                              void* d_out, int out_size) {
    (void)in_sizes; (void)n_in; (void)out_size;
    const float* x = (const float*)d_in[0];
    float* out = (float*)d_out;
    const int smF = TN*8 + TN*4;            // 192000
    const int smB = 8000*8 + 8000*4;        // 96000
    const int smC = 4000*8 + 4000*4;        // 48000
    const int smD = 2000*8 + 2000*4;        // 24000
    const int smE = 1000*8 + 1000*4;        // 12000
    cudaFuncSetAttribute(k_fwd, cudaFuncAttributeMaxDynamicSharedMemorySize, smF);
    cudaFuncSetAttribute(k_bandT<8000,2,512,1>,  cudaFuncAttributeMaxDynamicSharedMemorySize, smB);
    cudaFuncSetAttribute(k_bandT<4000,4,512,2>,  cudaFuncAttributeMaxDynamicSharedMemorySize, smC);
    cudaFuncSetAttribute(k_bandT<2000,8,256,3>,  cudaFuncAttributeMaxDynamicSharedMemorySize, smD);
    cudaFuncSetAttribute(k_bandT<1000,16,128,4>, cudaFuncAttributeMaxDynamicSharedMemorySize, smE);
    prep_phi<<<NTAPS + 8, 32>>>();
    prep_band<<<dim3(32, NF), 256>>>();
    k_fwd<<<NB, NT, smF>>>(x);
    k_bandT<8000,2,512,1>  <<<dim3(3,  NB), 512,  smB>>>(0,  0);
    k_bandT<4000,4,512,2>  <<<dim3(7,  NB), 512,  smC>>>(3,  24000);
    k_bandT<2000,8,256,3>  <<<dim3(11, NB), 256,  smD>>>(10, 52000);
    k_bandT<1000,16,128,4> <<<dim3(15, NB), 128,  smE>>>(21, 74000);
    k_reduce<<<(NB*3*NOUT + 255)/256, 256>>>(out);
}

// round 11
// speedup vs baseline: 1.9848x; 1.0009x over previous
#include <cuda_runtime.h>
#include <math.h>

#define TN 16000
#define NT 1024
#define NF 36
#define NB 64
#define NOUT 250
#define NTAPS 257
#define KPHI 569
#define NCH 37
#define TBL 65000

// ---------------- static device scratch ----------------
__device__ float2 d_X[NB * TN];        // scrambled forward FFT of x (8 MB, L2-resident)
__device__ int    d_idx[TBL];          // per-channel gather index (classes C/D/E)
__device__ float  d_wt[TBL];           // per-channel psi weight (incl 1/16000)
__device__ int2   d_sidx[6*4000];      // split units (j=0..2 x parity): two gather indices
__device__ float4 d_swt[6*4000];       // split units: two complex weights
__device__ float  d_phiw[NTAPS];       // time-domain lowpass taps phi(d), d=-128..128
__device__ float2 d_rtA[128];          // W_16000^{-125 i}
__device__ float2 d_rtB[125];          // W_16000^{-i}
__device__ float  d_S1[NB * NCH * NOUT];
__device__ float  d_S1p[NB * 3 * NOUT];  // parity-1 partial sums for j=0..2

// ---------------- complex helpers ----------------
__device__ __forceinline__ float2 cmul(float2 a, float2 b) {
    return make_float2(a.x*b.x - a.y*b.y, a.x*b.y + a.y*b.x);
}
__device__ __forceinline__ float2 cadd(float2 a, float2 b){ return make_float2(a.x+b.x, a.y+b.y); }
__device__ __forceinline__ float2 csub(float2 a, float2 b){ return make_float2(a.x-b.x, a.y-b.y); }

// global digit reversal helpers (host-side layout of d_X, radices [4,4,10,10,10] DIF)
__device__ __forceinline__ int scrampos(int k){
    int e2 = k/1600, r = k - 1600*e2;
    int d2 = r/160;  r -= 160*d2;
    int c2 = r/16;   r -= 16*c2;
    int b2 = r/4,    a2 = r - 4*b2;
    return 4000*a2 + 1000*b2 + 100*c2 + 10*d2 + e2;
}
__device__ __forceinline__ float psiwt(int k, float xi, float sg){
    float f = (k < 8000) ? (float)k/16000.0f : (float)(k - 16000)/16000.0f;
    float u = (f - xi) / sg;
    return (u*u < 50.0f) ? __expf(-0.5f*u*u)/16000.0f : 0.0f;
}

// ---------------- ONE prep kernel ----------------
// rows 0..35: normal channel tables (j<3 skipped); rows 36..41: split units; row 42: phi; row 43: twiddle roots
__global__ void prep_all2() {
    int row = blockIdx.y;
    int q = blockIdx.x * blockDim.x + threadIdx.x;
    const float rr  = exp2f(1.0f/6.0f);
    const float fac = (rr - 1.0f) / (rr + 1.0f);
    if (row < NF) {
        int j = row;
        if (j < 3) return;
        int cls, NJ, off;
        if      (j < 10){ cls=2; NJ=4000; off = (j-3)*4000; }
        else if (j < 21){ cls=3; NJ=2000; off = 28000 + (j-10)*2000; }
        else            { cls=4; NJ=1000; off = 50000 + (j-21)*1000; }
        if (q >= NJ) return;
        int kq;
        if      (cls == 2) { int b=q/1000, c=(q/100)%10, d=(q/10)%10, e=q%10; kq = b + 4*c + 40*d + 400*e; }
        else if (cls == 3) { int a=q/1000, c=(q/100)%10, d=(q/10)%10, e=q%10; kq = a + 2*c + 20*d + 200*e; }
        else               { int c=q/100, d=(q/10)%10, e=q%10; kq = c + 10*d + 100*e; }
        float xi = 0.35f * exp2f(-(float)j/6.0f);
        int k_lo = (int)(xi * 16000.0f) - NJ/2;
        if (k_lo < 0) k_lo = 0;
        int k = k_lo + kq;
        d_idx[off+q] = scrampos(k);
        d_wt[off+q]  = psiwt(k, xi, xi*fac);
    } else if (row < NF + 6) {
        int u = row - NF;            // split unit: j = u>>1, parity = u&1
        int j = u >> 1, pi = u & 1;
        if (q >= 4000) return;
        int b=q/1000, c=(q/100)%10, d=(q/10)%10, e=q%10;
        int kq = b + 4*c + 40*d + 400*e;          // local bin in [0,4000)
        float xi = 0.35f * exp2f(-(float)j/6.0f);
        int k_lo = (int)(xi * 16000.0f) - 4000;   // 8000-window start
        if (k_lo < 0) k_lo = 0;
        int k1 = k_lo + kq, k2 = k_lo + kq + 4000;
        float sg = xi*fac;
        float p1 = psiwt(k1, xi, sg);
        float p2 = psiwt(k2, xi, sg);
        float2 ph = make_float2(1.f, 0.f);
        if (pi) { float s, cx; sincospif((float)kq/4000.0f, &s, &cx); ph = make_float2(cx, s); }
        float sgn = pi ? -1.f : 1.f;
        d_sidx[u*4000+q] = make_int2(scrampos(k1), scrampos(k2));
        d_swt[u*4000+q]  = make_float4(p1*ph.x, p1*ph.y, sgn*p2*ph.x, sgn*p2*ph.y);
    } else if (row == NF + 6) {
        // phi taps: one warp per tap, float math, warp-parallel over k
        int tap  = blockIdx.x*8 + (threadIdx.x >> 5);
        int lane = threadIdx.x & 31;
        if (tap >= NTAPS) return;
        int d = tap - 128;
        const float sp = 0.35f / 64.0f;
        float acc = 0.f;
        for (int k = 1 + lane; k <= KPHI; k += 32) {
            float f = (float)k / 16000.0f;
            float g = __expf(-f*f / (2.0f*sp*sp));
            acc += g * cospif(2.0f * (float)(k*d) / 16000.0f);
        }
        for (int o = 16; o; o >>= 1) acc += __shfl_down_sync(0xffffffffu, acc, o);
        if (lane == 0) d_phiw[tap] = (1.0f + 2.0f*acc) / 16000.0f;
    } else {
        if (q < 128) { float s, c; sincospif(-(float)q/64.0f, &s, &c); d_rtA[q] = make_float2(c, s); }
        else if (q < 253) { int t = q-128; float s, c; sincospif(-(float)t/8000.0f, &s, &c); d_rtB[t] = make_float2(c, s); }
    }
}

// ---------------- small DFTs ----------------
template<int SIGN>
__device__ __forceinline__ void dft4(float2&z0,float2&z1,float2&z2,float2&z3){
    float2 t0=cadd(z0,z2), t1=csub(z0,z2), t2=cadd(z1,z3), t3=csub(z1,z3);
    const float s = (float)SIGN;
    z0 = cadd(t0,t2);
    z2 = csub(t0,t2);
    z1 = make_float2(t1.x - s*t3.y, t1.y + s*t3.x);
    z3 = make_float2(t1.x + s*t3.y, t1.y - s*t3.x);
}

template<int SIGN>
__device__ __forceinline__ void dft5(float2&z0,float2&z1,float2&z2,float2&z3,float2&z4){
    const float K1 =  0.309016994374947424f;
    const float K2 = -0.809016994374947424f;
    const float S1 =  0.951056516295153572f;
    const float S2 =  0.587785252292473129f;
    float2 t1=cadd(z1,z4), t2=cadd(z2,z3), t3=csub(z1,z4), t4=csub(z2,z3);
    float2 a = z0;
    float2 sum = cadd(a, cadd(t1,t2));
    float2 r1 = make_float2(a.x + K1*t1.x + K2*t2.x, a.y + K1*t1.y + K2*t2.y);
    float2 r2 = make_float2(a.x + K2*t1.x + K1*t2.x, a.y + K2*t1.y + K1*t2.y);
    float2 q1 = make_float2(S1*t3.x + S2*t4.x, S1*t3.y + S2*t4.y);
    float2 q2 = make_float2(S2*t3.x - S1*t4.x, S2*t3.y - S1*t4.y);
    const float s = (float)SIGN;
    z0 = sum;
    z1 = make_float2(r1.x - s*q1.y, r1.y + s*q1.x);
    z4 = make_float2(r1.x + s*q1.y, r1.y - s*q1.x);
    z2 = make_float2(r2.x - s*q2.y, r2.y + s*q2.x);
    z3 = make_float2(r2.x + s*q2.y, r2.y - s*q2.x);
}

__device__ __forceinline__ float2 twb(int x, const float2* rtA, const float2* rtB){
    int a = x / 125;
    return cmul(rtA[a], rtB[x - a*125]);
}

// ================= forward-only pieces (k_fwd, size 16000, NT threads) =================
__device__ void stage16_fwd(float2* buf, const float* xs, const float2* rtA, const float2* rtB){
    const float2 c16_1 = make_float2(0.92387953251128674f, -0.38268343236508977f);
    const float2 c16_2 = make_float2(0.70710678118654752f, -0.70710678118654752f);
    const float2 c16_3 = make_float2(0.38268343236508977f, -0.92387953251128674f);
    for (int p = threadIdx.x; p < 1000; p += NT) {
        float2 z[16];
        #pragma unroll
        for (int j=0;j<4;j++)
            #pragma unroll
            for (int i=0;i<4;i++)
                z[4*j+i] = make_float2(xs[p + 1000*j + 4000*i], 0.f);
        float2 a = twb(p, rtA, rtB);
        float2 b = twb(4*p, rtA, rtB);
        #pragma unroll
        for (int j=0;j<4;j++) dft4<-1>(z[4*j+0], z[4*j+1], z[4*j+2], z[4*j+3]);
        #pragma unroll
        for (int j=0;j<4;j++){
            float2 t = (j==0)? a : (j==1? cmul(a,c16_1) : (j==2? cmul(a,c16_2) : cmul(a,c16_3)));
            float2 t2 = cmul(t,t);
            z[4*j+1]=cmul(z[4*j+1],t); z[4*j+2]=cmul(z[4*j+2],t2); z[4*j+3]=cmul(z[4*j+3],cmul(t2,t));
        }
        #pragma unroll
        for (int s1=0;s1<4;s1++) dft4<-1>(z[s1], z[4+s1], z[8+s1], z[12+s1]);
        float2 b2 = cmul(b,b), b3 = cmul(b2,b);
        #pragma unroll
        for (int s1=0;s1<4;s1++){ z[4+s1]=cmul(z[4+s1],b); z[8+s1]=cmul(z[8+s1],b2); z[12+s1]=cmul(z[12+s1],b3); }
        #pragma unroll
        for (int s1=0;s1<4;s1++)
            #pragma unroll
            for (int s2=0;s2<4;s2++)
                buf[s1*4000 + s2*1000 + p] = z[4*s2+s1];
    }
    __syncthreads();
}

template<int M, int CC>
__device__ void stage10_fwd(float2* buf, const float2* rtA, const float2* rtB){
    const float c1x=0.809016994374947424f, c1y=0.587785252292473129f;
    const float c2x=0.309016994374947424f, c2y=0.951056516295153572f;
    const float2 w10_1 = make_float2( c1x, -c1y);
    const float2 w10_2 = make_float2( c2x, -c2y);
    const float2 w10_3 = make_float2(-c2x, -c2y);
    const float2 w10_4 = make_float2(-c1x, -c1y);
    for (int idx = threadIdx.x; idx < 1600; idx += NT) {
        int blk = idx / M;
        int p   = idx - blk*M;
        int o   = blk*(10*M) + p;
        float2 z[10];
        #pragma unroll
        for (int i=0;i<10;i++) z[i] = buf[o + M*i];
        float2 v = twb(CC*p, rtA, rtB);
        float2 b  = cmul(v,v);
        float2 b2 = cmul(b,b);
        float2 b3 = cmul(b2,b);
        float2 b4 = cmul(b2,b2);
        float2 m1 = cmul(w10_1, v);
        float2 m2 = cmul(w10_2, v);
        float2 m3 = cmul(w10_3, v);
        float2 m4 = cmul(w10_4, v);
        float2 e0=cadd(z[0],z[5]), e1=cadd(z[1],z[6]), e2=cadd(z[2],z[7]), e3=cadd(z[3],z[8]), e4=cadd(z[4],z[9]);
        float2 q0=cmul(csub(z[0],z[5]), v ), q1=cmul(csub(z[1],z[6]), m1),
               q2=cmul(csub(z[2],z[7]), m2), q3=cmul(csub(z[3],z[8]), m3),
               q4=cmul(csub(z[4],z[9]), m4);
        dft5<-1>(e0,e1,e2,e3,e4);
        dft5<-1>(q0,q1,q2,q3,q4);
        z[0]=e0;          z[1]=q0;
        z[2]=cmul(e1,b);  z[3]=cmul(q1,b);
        z[4]=cmul(e2,b2); z[5]=cmul(q2,b2);
        z[6]=cmul(e3,b3); z[7]=cmul(q3,b3);
        z[8]=cmul(e4,b4); z[9]=cmul(q4,b4);
        #pragma unroll
        for (int i=0;i<10;i++) buf[o + M*i] = z[i];
    }
    __syncthreads();
}

__device__ void stage10_fwd_store(const float2* buf, float2* __restrict__ Xo){
    const float c1x=0.809016994374947424f, c1y=0.587785252292473129f;
    const float c2x=0.309016994374947424f, c2y=0.951056516295153572f;
    const float2 w1 = make_float2( c1x, -c1y);
    const float2 w2 = make_float2( c2x, -c2y);
    const float2 w3 = make_float2(-c2x, -c2y);
    const float2 w4 = make_float2(-c1x, -c1y);
    for (int blk = threadIdx.x; blk < 1600; blk += NT) {
        int o = 10*blk;
        float2 z[10];
        #pragma unroll
        for (int i=0;i<10;i++) z[i] = buf[o+i];
        float2 e0=cadd(z[0],z[5]), e1=cadd(z[1],z[6]), e2=cadd(z[2],z[7]), e3=cadd(z[3],z[8]), e4=cadd(z[4],z[9]);
        float2 q0=csub(z[0],z[5]),           q1=cmul(csub(z[1],z[6]), w1),
               q2=cmul(csub(z[2],z[7]), w2), q3=cmul(csub(z[3],z[8]), w3),
               q4=cmul(csub(z[4],z[9]), w4);
        dft5<-1>(e0,e1,e2,e3,e4);
        dft5<-1>(q0,q1,q2,q3,q4);
        float4* X4 = (float4*)(Xo + o);
        X4[0] = make_float4(e0.x,e0.y,q0.x,q0.y);
        X4[1] = make_float4(e1.x,e1.y,q1.x,q1.y);
        X4[2] = make_float4(e2.x,e2.y,q2.x,q2.y);
        X4[3] = make_float4(e3.x,e3.y,q3.x,q3.y);
        X4[4] = make_float4(e4.x,e4.y,q4.x,q4.y);
    }
}

// ================= inverse pieces =================

// first DIT stage (radix-10, M=1): single gather
template<int THR>
__device__ void s10_load(float2* buf, const float2* __restrict__ Xb,
                         const int* __restrict__ idx, const float* __restrict__ wt, int cnt10){
    const float c1x=0.809016994374947424f, c1y=0.587785252292473129f;
    const float c2x=0.309016994374947424f, c2y=0.951056516295153572f;
    const float2 w1 = make_float2( c1x,  c1y);
    const float2 w2 = make_float2( c2x,  c2y);
    const float2 w3 = make_float2(-c2x,  c2y);
    const float2 w4 = make_float2(-c1x,  c1y);
    for (int blk = threadIdx.x; blk < cnt10; blk += THR) {
        int o = 10*blk;
        float2 z[10];
        #pragma unroll
        for (int i=0;i<10;i++){
            float2 v = Xb[idx[o+i]];
            float  w = wt[o+i];
            z[i] = make_float2(v.x*w, v.y*w);
        }
        float2 E0=z[0], E1=z[2], E2=z[4], E3=z[6], E4=z[8];
        float2 O0=z[1], O1=z[3], O2=z[5], O3=z[7], O4=z[9];
        dft5<1>(E0,E1,E2,E3,E4);
        dft5<1>(O0,O1,O2,O3,O4);
        O1=cmul(O1,w1); O2=cmul(O2,w2); O3=cmul(O3,w3); O4=cmul(O4,w4);
        buf[o  ]=cadd(E0,O0); buf[o+5]=csub(E0,O0);
        buf[o+1]=cadd(E1,O1); buf[o+6]=csub(E1,O1);
        buf[o+2]=cadd(E2,O2); buf[o+7]=csub(E2,O2);
        buf[o+3]=cadd(E3,O3); buf[o+8]=csub(E3,O3);
        buf[o+4]=cadd(E4,O4); buf[o+9]=csub(E4,O4);
    }
    __syncthreads();
}

// first DIT stage with DUAL complex-weighted gather (polyphase split units)
template<int THR>
__device__ void s10_load_dual(float2* buf, const float2* __restrict__ Xb,
                              const int2* __restrict__ sidx, const float4* __restrict__ swt, int cnt10){
    const float c1x=0.809016994374947424f, c1y=0.587785252292473129f;
    const float c2x=0.309016994374947424f, c2y=0.951056516295153572f;
    const float2 w1 = make_float2( c1x,  c1y);
    const float2 w2 = make_float2( c2x,  c2y);
    const float2 w3 = make_float2(-c2x,  c2y);
    const float2 w4 = make_float2(-c1x,  c1y);
    for (int blk = threadIdx.x; blk < cnt10; blk += THR) {
        int o = 10*blk;
        float2 z[10];
        #pragma unroll
        for (int i=0;i<10;i++){
            int2   ii = sidx[o+i];
            float4 ww = swt[o+i];
            float2 v1 = Xb[ii.x];
            float2 v2 = Xb[ii.y];
            z[i] = cadd(cmul(v1, make_float2(ww.x, ww.y)), cmul(v2, make_float2(ww.z, ww.w)));
        }
        float2 E0=z[0], E1=z[2], E2=z[4], E3=z[6], E4=z[8];
        float2 O0=z[1], O1=z[3], O2=z[5], O3=z[7], O4=z[9];
        dft5<1>(E0,E1,E2,E3,E4);
        dft5<1>(O0,O1,O2,O3,O4);
        O1=cmul(O1,w1); O2=cmul(O2,w2); O3=cmul(O3,w3); O4=cmul(O4,w4);
        buf[o  ]=cadd(E0,O0); buf[o+5]=csub(E0,O0);
        buf[o+1]=cadd(E1,O1); buf[o+6]=csub(E1,O1);
        buf[o+2]=cadd(E2,O2); buf[o+7]=csub(E2,O2);
        buf[o+3]=cadd(E3,O3); buf[o+8]=csub(E3,O3);
        buf[o+4]=cadd(E4,O4); buf[o+9]=csub(E4,O4);
    }
    __syncthreads();
}

// generic inverse radix-10 stage; if ABS, writes |z| to U instead of buf
template<int M, int CC, int THR, bool ABS>
__device__ void s10i(float2* buf, float* U, int cnt, const float2* rtA, const float2* rtB){
    const float c1x=0.809016994374947424f, c1y=0.587785252292473129f;
    const float c2x=0.309016994374947424f, c2y=0.951056516295153572f;
    const float2 w10_1 = make_float2( c1x,  c1y);
    const float2 w10_2 = make_float2( c2x,  c2y);
    const float2 w10_3 = make_float2(-c2x,  c2y);
    const float2 w10_4 = make_float2(-c1x,  c1y);
    for (int idx = threadIdx.x; idx < cnt; idx += THR) {
        int blk = idx / M;
        int p   = idx - blk*M;
        int o   = blk*(10*M) + p;
        float2 z[10];
        #pragma unroll
        for (int i=0;i<10;i++) z[i] = buf[o + M*i];
        float2 v = twb(CC*p, rtA, rtB);
        v.y = -v.y;
        float2 b  = cmul(v,v);
        float2 b2 = cmul(b,b);
        float2 b3 = cmul(b2,b);
        float2 b4 = cmul(b2,b2);
        float2 m1 = cmul(w10_1, v);
        float2 m2 = cmul(w10_2, v);
        float2 m3 = cmul(w10_3, v);
        float2 m4 = cmul(w10_4, v);
        float2 E0=z[0], E1=cmul(z[2],b), E2=cmul(z[4],b2), E3=cmul(z[6],b3), E4=cmul(z[8],b4);
        float2 O0=z[1], O1=cmul(z[3],b), O2=cmul(z[5],b2), O3=cmul(z[7],b3), O4=cmul(z[9],b4);
        dft5<1>(E0,E1,E2,E3,E4);
        dft5<1>(O0,O1,O2,O3,O4);
        O0=cmul(O0,v ); O1=cmul(O1,m1); O2=cmul(O2,m2); O3=cmul(O3,m3); O4=cmul(O4,m4);
        float2 y[10];
        y[0]=cadd(E0,O0); y[5]=csub(E0,O0);
        y[1]=cadd(E1,O1); y[6]=csub(E1,O1);
        y[2]=cadd(E2,O2); y[7]=csub(E2,O2);
        y[3]=cadd(E3,O3); y[8]=csub(E3,O3);
        y[4]=cadd(E4,O4); y[9]=csub(E4,O4);
        if (ABS) {
            #pragma unroll
            for (int i=0;i<10;i++) U[o + M*i] = sqrtf(y[i].x*y[i].x + y[i].y*y[i].y);
        } else {
            #pragma unroll
            for (int i=0;i<10;i++) buf[o + M*i] = y[i];
        }
    }
    __syncthreads();
}

// inverse radix-4 stage, M=1000, sub-length 4000
template<int THR, bool ABS>
__device__ void s4i(float2* buf, float* U, int cnt, const float2* rtA, const float2* rtB){
    for (int idx = threadIdx.x; idx < cnt; idx += THR) {
        int blk = idx / 1000;
        int p   = idx - blk*1000;
        int o   = blk*4000 + p;
        float2 z0=buf[o], z1=buf[o+1000], z2=buf[o+2000], z3=buf[o+3000];
        float2 w1 = twb(4*p, rtA, rtB); w1.y = -w1.y;
        float2 w2 = cmul(w1,w1), w3 = cmul(w2,w1);
        z1=cmul(z1,w1); z2=cmul(z2,w2); z3=cmul(z3,w3);
        dft4<1>(z0,z1,z2,z3);
        if (ABS) {
            U[o]      = sqrtf(z0.x*z0.x + z0.y*z0.y);
            U[o+1000] = sqrtf(z1.x*z1.x + z1.y*z1.y);
            U[o+2000] = sqrtf(z2.x*z2.x + z2.y*z2.y);
            U[o+3000] = sqrtf(z3.x*z3.x + z3.y*z3.y);
        } else {
            buf[o]=z0; buf[o+1000]=z1; buf[o+2000]=z2; buf[o+3000]=z3;
        }
    }
    __syncthreads();
}

// inverse radix-2 stage, half-offset M2, twiddle conj W_16000^{DD p}
template<int THR, int M2, int DD>
__device__ void s2i_abs(float2* buf, float* U, const float2* rtA, const float2* rtB){
    for (int p = threadIdx.x; p < M2; p += THR) {
        float2 a = buf[p];
        float2 w = twb(DD*p, rtA, rtB); w.y = -w.y;
        float2 bb = cmul(buf[p+M2], w);
        float2 y0 = cadd(a,bb), y1 = csub(a,bb);
        U[p]    = sqrtf(y0.x*y0.x + y0.y*y0.y);
        U[p+M2] = sqrtf(y1.x*y1.x + y1.y*y1.y);
    }
    __syncthreads();
}

// ================= shared small helpers =================
template<int THR>
__device__ void init_tables(float2* rtA, float2* rtB, float* sphi){
    for (int i = threadIdx.x; i < 128; i += THR) rtA[i] = d_rtA[i];
    for (int i = threadIdx.x; i < 125; i += THR) rtB[i] = d_rtB[i];
    for (int i = threadIdx.x; i < NTAPS; i += THR) sphi[i] = d_phiw[i];
}

// decimated smoothing: S1[m] = DEC * sum_i phi(DEC*i) * U[(64m/DEC - i) mod NJ]
template<int NJ, int DEC, int THR>
__device__ void smooth_dec(const float* __restrict__ S, const float* __restrict__ sphi, float* dst){
    const int T = 128 / DEC;
    const int ITER = (2*T + 1 + 31) / 32;
    int w = threadIdx.x >> 5, l = threadIdx.x & 31;
    for (int m0 = w; m0 < NOUT; m0 += THR/32) {
        int tau = (64/DEC) * m0;
        float acc = 0.f;
        #pragma unroll
        for (int it = 0; it < ITER; ++it) {
            int tl = l + 32*it;
            if (tl <= 2*T) {
                int i = tl - T;
                int id = tau - i;
                if (id >= NJ) id -= NJ;
                if (id < 0)   id += NJ;
                acc += sphi[DEC*i + 128] * S[id];
            }
        }
        #pragma unroll
        for (int o = 16; o; o >>= 1) acc += __shfl_down_sync(0xffffffffu, acc, o);
        if (l == 0) dst[m0] = acc * (float)DEC;
    }
}

// parity-split smoothing (class-B polyphase): partial sum for parity PI over U_pi (len 4000)
// S1_pi[m] = 2 * sum_{i=-32}^{32-PI} phi(4i + 2*PI) * U_pi[(16m - i - PI) mod 4000]
template<int THR, int PI>
__device__ void smooth_split(const float* __restrict__ S, const float* __restrict__ sphi, float* dst){
    int w = threadIdx.x >> 5, l = threadIdx.x & 31;
    for (int m0 = w; m0 < NOUT; m0 += THR/32) {
        int tau = 16*m0 - PI;
        float acc = 0.f;
        #pragma unroll
        for (int it = 0; it < 3; ++it) {
            int t = l + 32*it;
            if (t <= 64 - PI) {
                int i = t - 32;
                int id = tau - i;
                if (id >= 4000) id -= 4000;
                if (id < 0)     id += 4000;
                acc += sphi[4*i + 2*PI + 128] * S[id];
            }
        }
        #pragma unroll
        for (int o = 16; o; o >>= 1) acc += __shfl_down_sync(0xffffffffu, acc, o);
        if (l == 0) dst[m0] = 2.0f * acc;
    }
}

// ---------------- kernel 1: forward FFT of x (+ S0) ----------------
__global__ __launch_bounds__(NT, 1) void k_fwd(const float* __restrict__ x){
    extern __shared__ __align__(16) unsigned char sm[];
    float2* buf = (float2*)sm;
    float*  xs  = (float*)(sm + TN*sizeof(float2));
    __shared__ float2 rtA[128]; __shared__ float2 rtB[125]; __shared__ float sphi[NTAPS];
    int b = blockIdx.x;
    init_tables<NT>(rtA, rtB, sphi);
    const float4* xb4 = (const float4*)(x + b*TN);
    float4* xs4 = (float4*)xs;
    for (int n = threadIdx.x; n < TN/4; n += NT) xs4[n] = xb4[n];
    __syncthreads();
    smooth_dec<TN,1,NT>(xs, sphi, &d_S1[(b*NCH + 0)*NOUT]);
    stage16_fwd(buf, xs, rtA, rtB);
    stage10_fwd<100,16>(buf, rtA, rtB);
    stage10_fwd<10,160>(buf, rtA, rtB);
    stage10_fwd_store(buf, d_X + b*TN);
}

// ---------------- kernel 2a: split units (j=0..2 x parity), 4000-pt pipeline ----------------
__global__ __launch_bounds__(512, 3) void k_bandS(){
    extern __shared__ __align__(16) unsigned char sm[];
    float2* buf = (float2*)sm;
    float*  U   = (float*)(sm + 4000*sizeof(float2));
    __shared__ float2 rtA[128]; __shared__ float2 rtB[125]; __shared__ float sphi[NTAPS];
    int u = blockIdx.x, b = blockIdx.y;
    int j = u >> 1, pi = u & 1;
    init_tables<512>(rtA, rtB, sphi);
    __syncthreads();
    s10_load_dual<512>(buf, d_X + b*TN, d_sidx + u*4000, d_swt + u*4000, 400);
    s10i<10,160,512,false>(buf, U, 400, rtA, rtB);
    s10i<100,16,512,false>(buf, U, 400, rtA, rtB);
    s4i<512,true>(buf, U, 1000, rtA, rtB);
    if (pi == 0) smooth_split<512,0>(U, sphi, &d_S1[(b*NCH + 1 + j)*NOUT]);
    else         smooth_split<512,1>(U, sphi, &d_S1p[(b*3 + j)*NOUT]);
}

// ---------------- kernel 2b: per-class band-pass ifft + |.| + smoothing ----------------
// CLS: 2=C(4000,D4) 3=D(2000,D8) 4=E(1000,D16)
template<int NJ, int DEC, int THR, int CLS, int MINB>
__global__ __launch_bounds__(THR, MINB) void k_bandT(int j0, int off0){
    extern __shared__ __align__(16) unsigned char sm[];
    float2* buf = (float2*)sm;
    float*  U   = (float*)(sm + NJ*sizeof(float2));
    __shared__ float2 rtA[128]; __shared__ float2 rtB[125]; __shared__ float sphi[NTAPS];
    int jc = blockIdx.x, b = blockIdx.y;
    int j = j0 + jc;
    init_tables<THR>(rtA, rtB, sphi);
    __syncthreads();
    const float2* Xb = d_X + b*TN;
    const int*   idx = d_idx + off0 + jc*NJ;
    const float* wt  = d_wt  + off0 + jc*NJ;
    s10_load<THR>(buf, Xb, idx, wt, NJ/10);
    s10i<10,160,THR,false>(buf, U, NJ/10, rtA, rtB);
    if (CLS == 4) {
        s10i<100,16,THR,true>(buf, U, NJ/10, rtA, rtB);
    } else {
        s10i<100,16,THR,false>(buf, U, NJ/10, rtA, rtB);
        if (CLS == 2) s4i<THR,true>(buf, U, 1000, rtA, rtB);
        if (CLS == 3) s2i_abs<THR,1000,8>(buf, U, rtA, rtB);
    }
    smooth_dec<NJ,DEC,THR>(U, sphi, &d_S1[(b*NCH + 1 + j)*NOUT]);
}

// ---------------- kernel 3: channel-group means (adds parity-1 partials for j=0..2) ----------------
__global__ void k_reduce(float* __restrict__ out){
    int i = blockIdx.x * blockDim.x + threadIdx.x;
    if (i >= NB*3*NOUT) return;
    int m0 = i % NOUT;
    int g  = (i / NOUT) % 3;
    int b  = i / (3*NOUT);
    int c0 = (g==0) ? 0 : (g==1 ? 12 : 24);
    int nc = (g==2) ? 13 : 12;
    float acc = 0.f;
    for (int c = 0; c < nc; ++c) acc += d_S1[(b*NCH + c0 + c)*NOUT + m0];
    if (g == 0) {
        for (int j = 0; j < 3; ++j) acc += d_S1p[(b*3 + j)*NOUT + m0];
    }
    out[i] = acc / (float)nc;
}

// ---------------- launch ----------------
extern "C" void kernel_launch(void* const* d_in, const int* in_sizes, int n_in,
                              void* d_out, int out_size) {
    (void)in_sizes; (void)n_in; (void)out_size;
    const float* x = (const float*)d_in[0];
    float* out = (float*)d_out;
    const int smF = TN*8 + TN*4;            // 192000
    const int smC = 4000*8 + 4000*4;        // 48000
    const int smD = 2000*8 + 2000*4;        // 24000
    const int smE = 1000*8 + 1000*4;        // 12000
    cudaFuncSetAttribute(k_fwd,   cudaFuncAttributeMaxDynamicSharedMemorySize, smF);
    cudaFuncSetAttribute(k_bandS, cudaFuncAttributeMaxDynamicSharedMemorySize, smC);
    cudaFuncSetAttribute(k_bandT<4000,4,512,2,3>,  cudaFuncAttributeMaxDynamicSharedMemorySize, smC);
    cudaFuncSetAttribute(k_bandT<2000,8,256,3,1>,  cudaFuncAttributeMaxDynamicSharedMemorySize, smD);
    cudaFuncSetAttribute(k_bandT<1000,16,128,4,1>, cudaFuncAttributeMaxDynamicSharedMemorySize, smE);
    prep_all2<<<dim3(33, NF + 8), 256>>>();
    k_fwd<<<NB, NT, smF>>>(x);
    k_bandS<<<dim3(6, NB), 512, smC>>>();
    k_bandT<4000,4,512,2,3>  <<<dim3(7,  NB), 512, smC>>>(3,  0);
    k_bandT<2000,8,256,3,1>  <<<dim3(11, NB), 256, smD>>>(10, 28000);
    k_bandT<1000,16,128,4,1> <<<dim3(15, NB), 128, smE>>>(21, 50000);
    k_reduce<<<(NB*3*NOUT + 255)/256, 256>>>(out);
}

// round 12
// speedup vs baseline: 2.0948x; 1.0554x over previous
#include <cuda_runtime.h>
#include <math.h>

#define TN 16000
#define NF 36
#define NB 64
#define NOUT 250
#define NTAPS 257
#define KPHI 569
#define NCH 37
#define TBL 65000

// ---------------- static device scratch ----------------
__device__ float2 d_X[NB * TN];        // scrambled forward FFT of x
__device__ float2 d_Xm[NB * TN];       // intermediate after radix-16 stage
__device__ int    d_idx[TBL];          // per-channel gather index (classes C/D/E)
__device__ float  d_wt[TBL];           // per-channel psi weight (incl 1/16000)
__device__ int2   d_sidx[6*4000];      // split units (j=0..2 x parity): two gather indices
__device__ float4 d_swt[6*4000];       // split units: two complex weights
__device__ float  d_phiw[NTAPS];       // time-domain lowpass taps phi(d), d=-128..128
__device__ float2 d_rtA[128];          // W_16000^{-125 i}
__device__ float2 d_rtB[125];          // W_16000^{-i}
__device__ float  d_S1[NB * NCH * NOUT];
__device__ float  d_S1p[NB * 3 * NOUT];  // parity-1 partial sums for j=0..2

// ---------------- complex helpers ----------------
__device__ __forceinline__ float2 cmul(float2 a, float2 b) {
    return make_float2(a.x*b.x - a.y*b.y, a.x*b.y + a.y*b.x);
}
__device__ __forceinline__ float2 cadd(float2 a, float2 b){ return make_float2(a.x+b.x, a.y+b.y); }
__device__ __forceinline__ float2 csub(float2 a, float2 b){ return make_float2(a.x-b.x, a.y-b.y); }

__device__ __forceinline__ int scrampos(int k){
    int e2 = k/1600, r = k - 1600*e2;
    int d2 = r/160;  r -= 160*d2;
    int c2 = r/16;   r -= 16*c2;
    int b2 = r/4,    a2 = r - 4*b2;
    return 4000*a2 + 1000*b2 + 100*c2 + 10*d2 + e2;
}
__device__ __forceinline__ float psiwt(int k, float xi, float sg){
    float f = (k < 8000) ? (float)k/16000.0f : (float)(k - 16000)/16000.0f;
    float u = (f - xi) / sg;
    return (u*u < 50.0f) ? __expf(-0.5f*u*u)/16000.0f : 0.0f;
}

// ---------------- ONE prep kernel ----------------
__global__ void prep_all2() {
    int row = blockIdx.y;
    int q = blockIdx.x * blockDim.x + threadIdx.x;
    const float rr  = exp2f(1.0f/6.0f);
    const float fac = (rr - 1.0f) / (rr + 1.0f);
    if (row < NF) {
        int j = row;
        if (j < 3) return;
        int cls, NJ, off;
        if      (j < 10){ cls=2; NJ=4000; off = (j-3)*4000; }
        else if (j < 21){ cls=3; NJ=2000; off = 28000 + (j-10)*2000; }
        else            { cls=4; NJ=1000; off = 50000 + (j-21)*1000; }
        if (q >= NJ) return;
        int kq;
        if      (cls == 2) { int b=q/1000, c=(q/100)%10, d=(q/10)%10, e=q%10; kq = b + 4*c + 40*d + 400*e; }
        else if (cls == 3) { int a=q/1000, c=(q/100)%10, d=(q/10)%10, e=q%10; kq = a + 2*c + 20*d + 200*e; }
        else               { int c=q/100, d=(q/10)%10, e=q%10; kq = c + 10*d + 100*e; }
        float xi = 0.35f * exp2f(-(float)j/6.0f);
        int k_lo = (int)(xi * 16000.0f) - NJ/2;
        if (k_lo < 0) k_lo = 0;
        int k = k_lo + kq;
        d_idx[off+q] = scrampos(k);
        d_wt[off+q]  = psiwt(k, xi, xi*fac);
    } else if (row < NF + 6) {
        int u = row - NF;
        int j = u >> 1, pi = u & 1;
        if (q >= 4000) return;
        int b=q/1000, c=(q/100)%10, d=(q/10)%10, e=q%10;
        int kq = b + 4*c + 40*d + 400*e;
        float xi = 0.35f * exp2f(-(float)j/6.0f);
        int k_lo = (int)(xi * 16000.0f) - 4000;
        if (k_lo < 0) k_lo = 0;
        int k1 = k_lo + kq, k2 = k_lo + kq + 4000;
        float sg = xi*fac;
        float p1 = psiwt(k1, xi, sg);
        float p2 = psiwt(k2, xi, sg);
        float2 ph = make_float2(1.f, 0.f);
        if (pi) { float s, cx; sincospif((float)kq/4000.0f, &s, &cx); ph = make_float2(cx, s); }
        float sgn = pi ? -1.f : 1.f;
        d_sidx[u*4000+q] = make_int2(scrampos(k1), scrampos(k2));
        d_swt[u*4000+q]  = make_float4(p1*ph.x, p1*ph.y, sgn*p2*ph.x, sgn*p2*ph.y);
    } else if (row == NF + 6) {
        int tap  = blockIdx.x*8 + (threadIdx.x >> 5);
        int lane = threadIdx.x & 31;
        if (tap >= NTAPS) return;
        int d = tap - 128;
        const float sp = 0.35f / 64.0f;
        float acc = 0.f;
        for (int k = 1 + lane; k <= KPHI; k += 32) {
            float f = (float)k / 16000.0f;
            float g = __expf(-f*f / (2.0f*sp*sp));
            acc += g * cospif(2.0f * (float)(k*d) / 16000.0f);
        }
        for (int o = 16; o; o >>= 1) acc += __shfl_down_sync(0xffffffffu, acc, o);
        if (lane == 0) d_phiw[tap] = (1.0f + 2.0f*acc) / 16000.0f;
    } else {
        if (q < 128) { float s, c; sincospif(-(float)q/64.0f, &s, &c); d_rtA[q] = make_float2(c, s); }
        else if (q < 253) { int t = q-128; float s, c; sincospif(-(float)t/8000.0f, &s, &c); d_rtB[t] = make_float2(c, s); }
    }
}

// ---------------- small DFTs ----------------
template<int SIGN>
__device__ __forceinline__ void dft4(float2&z0,float2&z1,float2&z2,float2&z3){
    float2 t0=cadd(z0,z2), t1=csub(z0,z2), t2=cadd(z1,z3), t3=csub(z1,z3);
    const float s = (float)SIGN;
    z0 = cadd(t0,t2);
    z2 = csub(t0,t2);
    z1 = make_float2(t1.x - s*t3.y, t1.y + s*t3.x);
    z3 = make_float2(t1.x + s*t3.y, t1.y - s*t3.x);
}

template<int SIGN>
__device__ __forceinline__ void dft5(float2&z0,float2&z1,float2&z2,float2&z3,float2&z4){
    const float K1 =  0.309016994374947424f;
    const float K2 = -0.809016994374947424f;
    const float S1 =  0.951056516295153572f;
    const float S2 =  0.587785252292473129f;
    float2 t1=cadd(z1,z4), t2=cadd(z2,z3), t3=csub(z1,z4), t4=csub(z2,z3);
    float2 a = z0;
    float2 sum = cadd(a, cadd(t1,t2));
    float2 r1 = make_float2(a.x + K1*t1.x + K2*t2.x, a.y + K1*t1.y + K2*t2.y);
    float2 r2 = make_float2(a.x + K2*t1.x + K1*t2.x, a.y + K2*t1.y + K1*t2.y);
    float2 q1 = make_float2(S1*t3.x + S2*t4.x, S1*t3.y + S2*t4.y);
    float2 q2 = make_float2(S2*t3.x - S1*t4.x, S2*t3.y - S1*t4.y);
    const float s = (float)SIGN;
    z0 = sum;
    z1 = make_float2(r1.x - s*q1.y, r1.y + s*q1.x);
    z4 = make_float2(r1.x + s*q1.y, r1.y - s*q1.x);
    z2 = make_float2(r2.x - s*q2.y, r2.y + s*q2.x);
    z3 = make_float2(r2.x + s*q2.y, r2.y - s*q2.x);
}

__device__ __forceinline__ float2 twb(int x, const float2* rtA, const float2* rtB){
    int a = x / 125;
    return cmul(rtA[a], rtB[x - a*125]);
}
__device__ __forceinline__ float2 twg(int x){
    int a = x / 125;
    return cmul(d_rtA[a], d_rtB[x - a*125]);
}

// ================= forward phase A: pure-register radix-16, global->global =================
__global__ void k_fwdA(const float* __restrict__ x){
    const float2 c16_1 = make_float2(0.92387953251128674f, -0.38268343236508977f);
    const float2 c16_2 = make_float2(0.70710678118654752f, -0.70710678118654752f);
    const float2 c16_3 = make_float2(0.38268343236508977f, -0.92387953251128674f);
    int b = blockIdx.y;
    int p = blockIdx.x*512 + threadIdx.x;
    if (p >= 1000) return;
    const float* xb = x + b*TN;
    float2 z[16];
    #pragma unroll
    for (int j=0;j<4;j++)
        #pragma unroll
        for (int i=0;i<4;i++)
            z[4*j+i] = make_float2(xb[p + 1000*j + 4000*i], 0.f);
    float2 a = twg(p);
    float2 bw = twg(4*p);
    #pragma unroll
    for (int j=0;j<4;j++) dft4<-1>(z[4*j+0], z[4*j+1], z[4*j+2], z[4*j+3]);
    #pragma unroll
    for (int j=0;j<4;j++){
        float2 t = (j==0)? a : (j==1? cmul(a,c16_1) : (j==2? cmul(a,c16_2) : cmul(a,c16_3)));
        float2 t2 = cmul(t,t);
        z[4*j+1]=cmul(z[4*j+1],t); z[4*j+2]=cmul(z[4*j+2],t2); z[4*j+3]=cmul(z[4*j+3],cmul(t2,t));
    }
    #pragma unroll
    for (int s1=0;s1<4;s1++) dft4<-1>(z[s1], z[4+s1], z[8+s1], z[12+s1]);
    float2 b2 = cmul(bw,bw), b3 = cmul(b2,bw);
    #pragma unroll
    for (int s1=0;s1<4;s1++){ z[4+s1]=cmul(z[4+s1],bw); z[8+s1]=cmul(z[8+s1],b2); z[12+s1]=cmul(z[12+s1],b3); }
    float2* Xo = d_Xm + b*TN;
    #pragma unroll
    for (int s1=0;s1<4;s1++)
        #pragma unroll
        for (int s2=0;s2<4;s2++)
            Xo[s1*4000 + s2*1000 + p] = z[4*s2+s1];
}

// forward radix-10 stage, generalized (cnt=400, 512 thr), block-local
template<int M, int CC>
__device__ void stage10fg(float2* buf, const float2* rtA, const float2* rtB){
    const float c1x=0.809016994374947424f, c1y=0.587785252292473129f;
    const float c2x=0.309016994374947424f, c2y=0.951056516295153572f;
    const float2 w10_1 = make_float2( c1x, -c1y);
    const float2 w10_2 = make_float2( c2x, -c2y);
    const float2 w10_3 = make_float2(-c2x, -c2y);
    const float2 w10_4 = make_float2(-c1x, -c1y);
    for (int idx = threadIdx.x; idx < 400; idx += 512) {
        int blk = idx / M;
        int p   = idx - blk*M;
        int o   = blk*(10*M) + p;
        float2 z[10];
        #pragma unroll
        for (int i=0;i<10;i++) z[i] = buf[o + M*i];
        float2 v = twb(CC*p, rtA, rtB);
        float2 b  = cmul(v,v);
        float2 b2 = cmul(b,b);
        float2 b3 = cmul(b2,b);
        float2 b4 = cmul(b2,b2);
        float2 m1 = cmul(w10_1, v);
        float2 m2 = cmul(w10_2, v);
        float2 m3 = cmul(w10_3, v);
        float2 m4 = cmul(w10_4, v);
        float2 e0=cadd(z[0],z[5]), e1=cadd(z[1],z[6]), e2=cadd(z[2],z[7]), e3=cadd(z[3],z[8]), e4=cadd(z[4],z[9]);
        float2 q0=cmul(csub(z[0],z[5]), v ), q1=cmul(csub(z[1],z[6]), m1),
               q2=cmul(csub(z[2],z[7]), m2), q3=cmul(csub(z[3],z[8]), m3),
               q4=cmul(csub(z[4],z[9]), m4);
        dft5<-1>(e0,e1,e2,e3,e4);
        dft5<-1>(q0,q1,q2,q3,q4);
        z[0]=e0;          z[1]=q0;
        z[2]=cmul(e1,b);  z[3]=cmul(q1,b);
        z[4]=cmul(e2,b2); z[5]=cmul(q2,b2);
        z[6]=cmul(e3,b3); z[7]=cmul(q3,b3);
        z[8]=cmul(e4,b4); z[9]=cmul(q4,b4);
        #pragma unroll
        for (int i=0;i<10;i++) buf[o + M*i] = z[i];
    }
    __syncthreads();
}

// ================= forward phase B: 4 independent 1000-pt blocks per CTA =================
__global__ __launch_bounds__(512) void k_fwdB(){
    extern __shared__ __align__(16) unsigned char sm[];
    float2* buf = (float2*)sm;                       // 4000 complex
    __shared__ float2 rtA[128]; __shared__ float2 rtB[125];
    for (int i = threadIdx.x; i < 128; i += 512) rtA[i] = d_rtA[i];
    for (int i = threadIdx.x; i < 125; i += 512) rtB[i] = d_rtB[i];
    int b = blockIdx.y;
    int base = blockIdx.x * 4000;
    const float4* src = (const float4*)(d_Xm + b*TN + base);
    float4* bd = (float4*)buf;
    for (int i = threadIdx.x; i < 2000; i += 512) bd[i] = src[i];
    __syncthreads();
    stage10fg<100,16>(buf, rtA, rtB);
    stage10fg<10,160>(buf, rtA, rtB);
    // last stage: radix-10 M=1, no twiddle, store natural
    const float c1x=0.809016994374947424f, c1y=0.587785252292473129f;
    const float c2x=0.309016994374947424f, c2y=0.951056516295153572f;
    const float2 w1 = make_float2( c1x, -c1y);
    const float2 w2 = make_float2( c2x, -c2y);
    const float2 w3 = make_float2(-c2x, -c2y);
    const float2 w4 = make_float2(-c1x, -c1y);
    float2* Xo = d_X + b*TN + base;
    for (int blk = threadIdx.x; blk < 400; blk += 512) {
        int o = 10*blk;
        float2 z[10];
        #pragma unroll
        for (int i=0;i<10;i++) z[i] = buf[o+i];
        float2 e0=cadd(z[0],z[5]), e1=cadd(z[1],z[6]), e2=cadd(z[2],z[7]), e3=cadd(z[3],z[8]), e4=cadd(z[4],z[9]);
        float2 q0=csub(z[0],z[5]),           q1=cmul(csub(z[1],z[6]), w1),
               q2=cmul(csub(z[2],z[7]), w2), q3=cmul(csub(z[3],z[8]), w3),
               q4=cmul(csub(z[4],z[9]), w4);
        dft5<-1>(e0,e1,e2,e3,e4);
        dft5<-1>(q0,q1,q2,q3,q4);
        float4* X4 = (float4*)(Xo + o);
        X4[0] = make_float4(e0.x,e0.y,q0.x,q0.y);
        X4[1] = make_float4(e1.x,e1.y,q1.x,q1.y);
        X4[2] = make_float4(e2.x,e2.y,q2.x,q2.y);
        X4[3] = make_float4(e3.x,e3.y,q3.x,q3.y);
        X4[4] = make_float4(e4.x,e4.y,q4.x,q4.y);
    }
}

// ================= S0: warp-per-output smoothing straight from global x =================
__global__ void k_s0(const float* __restrict__ x){
    int b = blockIdx.x;
    int w = threadIdx.x >> 5, l = threadIdx.x & 31;
    const float* xb = x + b*TN;
    for (int m0 = w; m0 < NOUT; m0 += 8) {
        int tau = 64*m0;
        float acc = 0.f;
        #pragma unroll
        for (int it = 0; it < 9; ++it) {
            int tl = l + 32*it;
            if (tl <= 256) {
                int i = tl - 128;
                int id = tau - i;
                if (id >= TN) id -= TN;
                if (id < 0)   id += TN;
                acc += d_phiw[tl] * xb[id];
            }
        }
        #pragma unroll
        for (int o = 16; o; o >>= 1) acc += __shfl_down_sync(0xffffffffu, acc, o);
        if (l == 0) d_S1[(b*NCH)*NOUT + m0] = acc;
    }
}

// ================= inverse pieces (generalized over sub-unit tid/THRL) =================

template<int THRL>
__device__ void s10_load_g(int t, float2* buf, const float2* __restrict__ Xb,
                           const int* __restrict__ idx, const float* __restrict__ wt, int cnt10){
    const float c1x=0.809016994374947424f, c1y=0.587785252292473129f;
    const float c2x=0.309016994374947424f, c2y=0.951056516295153572f;
    const float2 w1 = make_float2( c1x,  c1y);
    const float2 w2 = make_float2( c2x,  c2y);
    const float2 w3 = make_float2(-c2x,  c2y);
    const float2 w4 = make_float2(-c1x,  c1y);
    for (int blk = t; blk < cnt10; blk += THRL) {
        int o = 10*blk;
        float2 z[10];
        #pragma unroll
        for (int i=0;i<10;i++){
            float2 v = Xb[idx[o+i]];
            float  w = wt[o+i];
            z[i] = make_float2(v.x*w, v.y*w);
        }
        float2 E0=z[0], E1=z[2], E2=z[4], E3=z[6], E4=z[8];
        float2 O0=z[1], O1=z[3], O2=z[5], O3=z[7], O4=z[9];
        dft5<1>(E0,E1,E2,E3,E4);
        dft5<1>(O0,O1,O2,O3,O4);
        O1=cmul(O1,w1); O2=cmul(O2,w2); O3=cmul(O3,w3); O4=cmul(O4,w4);
        buf[o  ]=cadd(E0,O0); buf[o+5]=csub(E0,O0);
        buf[o+1]=cadd(E1,O1); buf[o+6]=csub(E1,O1);
        buf[o+2]=cadd(E2,O2); buf[o+7]=csub(E2,O2);
        buf[o+3]=cadd(E3,O3); buf[o+8]=csub(E3,O3);
        buf[o+4]=cadd(E4,O4); buf[o+9]=csub(E4,O4);
    }
    __syncthreads();
}

__device__ void s10_load_dual(float2* buf, const float2* __restrict__ Xb,
                              const int2* __restrict__ sidx, const float4* __restrict__ swt){
    const float c1x=0.809016994374947424f, c1y=0.587785252292473129f;
    const float c2x=0.309016994374947424f, c2y=0.951056516295153572f;
    const float2 w1 = make_float2( c1x,  c1y);
    const float2 w2 = make_float2( c2x,  c2y);
    const float2 w3 = make_float2(-c2x,  c2y);
    const float2 w4 = make_float2(-c1x,  c1y);
    for (int blk = threadIdx.x; blk < 400; blk += 512) {
        int o = 10*blk;
        float2 z[10];
        #pragma unroll
        for (int i=0;i<10;i++){
            int2   ii = sidx[o+i];
            float4 ww = swt[o+i];
            float2 v1 = Xb[ii.x];
            float2 v2 = Xb[ii.y];
            z[i] = cadd(cmul(v1, make_float2(ww.x, ww.y)), cmul(v2, make_float2(ww.z, ww.w)));
        }
        float2 E0=z[0], E1=z[2], E2=z[4], E3=z[6], E4=z[8];
        float2 O0=z[1], O1=z[3], O2=z[5], O3=z[7], O4=z[9];
        dft5<1>(E0,E1,E2,E3,E4);
        dft5<1>(O0,O1,O2,O3,O4);
        O1=cmul(O1,w1); O2=cmul(O2,w2); O3=cmul(O3,w3); O4=cmul(O4,w4);
        buf[o  ]=cadd(E0,O0); buf[o+5]=csub(E0,O0);
        buf[o+1]=cadd(E1,O1); buf[o+6]=csub(E1,O1);
        buf[o+2]=cadd(E2,O2); buf[o+7]=csub(E2,O2);
        buf[o+3]=cadd(E3,O3); buf[o+8]=csub(E3,O3);
        buf[o+4]=cadd(E4,O4); buf[o+9]=csub(E4,O4);
    }
    __syncthreads();
}

template<int M, int CC, int THRL, bool ABS>
__device__ void s10i_g(int t, float2* buf, float* U, int cnt, const float2* rtA, const float2* rtB){
    const float c1x=0.809016994374947424f, c1y=0.587785252292473129f;
    const float c2x=0.309016994374947424f, c2y=0.951056516295153572f;
    const float2 w10_1 = make_float2( c1x,  c1y);
    const float2 w10_2 = make_float2( c2x,  c2y);
    const float2 w10_3 = make_float2(-c2x,  c2y);
    const float2 w10_4 = make_float2(-c1x,  c1y);
    for (int idx = t; idx < cnt; idx += THRL) {
        int blk = idx / M;
        int p   = idx - blk*M;
        int o   = blk*(10*M) + p;
        float2 z[10];
        #pragma unroll
        for (int i=0;i<10;i++) z[i] = buf[o + M*i];
        float2 v = twb(CC*p, rtA, rtB);
        v.y = -v.y;
        float2 b  = cmul(v,v);
        float2 b2 = cmul(b,b);
        float2 b3 = cmul(b2,b);
        float2 b4 = cmul(b2,b2);
        float2 m1 = cmul(w10_1, v);
        float2 m2 = cmul(w10_2, v);
        float2 m3 = cmul(w10_3, v);
        float2 m4 = cmul(w10_4, v);
        float2 E0=z[0], E1=cmul(z[2],b), E2=cmul(z[4],b2), E3=cmul(z[6],b3), E4=cmul(z[8],b4);
        float2 O0=z[1], O1=cmul(z[3],b), O2=cmul(z[5],b2), O3=cmul(z[7],b3), O4=cmul(z[9],b4);
        dft5<1>(E0,E1,E2,E3,E4);
        dft5<1>(O0,O1,O2,O3,O4);
        O0=cmul(O0,v ); O1=cmul(O1,m1); O2=cmul(O2,m2); O3=cmul(O3,m3); O4=cmul(O4,m4);
        float2 y[10];
        y[0]=cadd(E0,O0); y[5]=csub(E0,O0);
        y[1]=cadd(E1,O1); y[6]=csub(E1,O1);
        y[2]=cadd(E2,O2); y[7]=csub(E2,O2);
        y[3]=cadd(E3,O3); y[8]=csub(E3,O3);
        y[4]=cadd(E4,O4); y[9]=csub(E4,O4);
        if (ABS) {
            #pragma unroll
            for (int i=0;i<10;i++) U[o + M*i] = sqrtf(y[i].x*y[i].x + y[i].y*y[i].y);
        } else {
            #pragma unroll
            for (int i=0;i<10;i++) buf[o + M*i] = y[i];
        }
    }
    __syncthreads();
}

template<int THRL, bool ABS>
__device__ void s4i_g(int t, float2* buf, float* U, int cnt, const float2* rtA, const float2* rtB){
    for (int idx = t; idx < cnt; idx += THRL) {
        int blk = idx / 1000;
        int p   = idx - blk*1000;
        int o   = blk*4000 + p;
        float2 z0=buf[o], z1=buf[o+1000], z2=buf[o+2000], z3=buf[o+3000];
        float2 w1 = twb(4*p, rtA, rtB); w1.y = -w1.y;
        float2 w2 = cmul(w1,w1), w3 = cmul(w2,w1);
        z1=cmul(z1,w1); z2=cmul(z2,w2); z3=cmul(z3,w3);
        dft4<1>(z0,z1,z2,z3);
        if (ABS) {
            U[o]      = sqrtf(z0.x*z0.x + z0.y*z0.y);
            U[o+1000] = sqrtf(z1.x*z1.x + z1.y*z1.y);
            U[o+2000] = sqrtf(z2.x*z2.x + z2.y*z2.y);
            U[o+3000] = sqrtf(z3.x*z3.x + z3.y*z3.y);
        } else {
            buf[o]=z0; buf[o+1000]=z1; buf[o+2000]=z2; buf[o+3000]=z3;
        }
    }
    __syncthreads();
}

template<int THRL, int M2, int DD>
__device__ void s2i_abs_g(int t, float2* buf, float* U, const float2* rtA, const float2* rtB){
    for (int p = t; p < M2; p += THRL) {
        float2 a = buf[p];
        float2 w = twb(DD*p, rtA, rtB); w.y = -w.y;
        float2 bb = cmul(buf[p+M2], w);
        float2 y0 = cadd(a,bb), y1 = csub(a,bb);
        U[p]    = sqrtf(y0.x*y0.x + y0.y*y0.y);
        U[p+M2] = sqrtf(y1.x*y1.x + y1.y*y1.y);
    }
    __syncthreads();
}

template<int THRL>
__device__ void init_tables(float2* rtA, float2* rtB, float* sphi){
    for (int i = threadIdx.x; i < 128; i += THRL) rtA[i] = d_rtA[i];
    for (int i = threadIdx.x; i < 125; i += THRL) rtB[i] = d_rtB[i];
    for (int i = threadIdx.x; i < NTAPS; i += THRL) sphi[i] = d_phiw[i];
}

template<int NJ, int DEC, int THRL>
__device__ void smooth_dec_g(int t, const float* __restrict__ S, const float* __restrict__ sphi, float* dst){
    const int T = 128 / DEC;
    const int ITER = (2*T + 1 + 31) / 32;
    int w = t >> 5, l = t & 31;
    for (int m0 = w; m0 < NOUT; m0 += THRL/32) {
        int tau = (64/DEC) * m0;
        float acc = 0.f;
        #pragma unroll
        for (int it = 0; it < ITER; ++it) {
            int tl = l + 32*it;
            if (tl <= 2*T) {
                int i = tl - T;
                int id = tau - i;
                if (id >= NJ) id -= NJ;
                if (id < 0)   id += NJ;
                acc += sphi[DEC*i + 128] * S[id];
            }
        }
        #pragma unroll
        for (int o = 16; o; o >>= 1) acc += __shfl_down_sync(0xffffffffu, acc, o);
        if (l == 0) dst[m0] = acc * (float)DEC;
    }
}

template<int PI>
__device__ void smooth_split(const float* __restrict__ S, const float* __restrict__ sphi, float* dst){
    int w = threadIdx.x >> 5, l = threadIdx.x & 31;
    for (int m0 = w; m0 < NOUT; m0 += 16) {
        int tau = 16*m0 - PI;
        float acc = 0.f;
        #pragma unroll
        for (int it = 0; it < 3; ++it) {
            int t = l + 32*it;
            if (t <= 64 - PI) {
                int i = t - 32;
                int id = tau - i;
                if (id >= 4000) id -= 4000;
                if (id < 0)     id += 4000;
                acc += sphi[4*i + 2*PI + 128] * S[id];
            }
        }
        #pragma unroll
        for (int o = 16; o; o >>= 1) acc += __shfl_down_sync(0xffffffffu, acc, o);
        if (l == 0) dst[m0] = 2.0f * acc;
    }
}

// ---------------- unified band kernel: 23 CTAs per batch ----------------
// u<6: split units (S); u<13: C (1/CTA); u<19: D (2/CTA); u<23: E (4/CTA)
__global__ __launch_bounds__(512, 3) void k_band_all(){
    extern __shared__ __align__(16) unsigned char sm[];
    __shared__ float2 rtA[128]; __shared__ float2 rtB[125]; __shared__ float sphi[NTAPS];
    int u = blockIdx.x, b = blockIdx.y;
    int tid = threadIdx.x;
    init_tables<512>(rtA, rtB, sphi);
    __syncthreads();
    const float2* Xb = d_X + b*TN;
    if (u < 6) {
        float2* buf = (float2*)sm;
        float*  U   = (float*)(sm + 4000*sizeof(float2));
        int j = u >> 1, pi = u & 1;
        s10_load_dual(buf, Xb, d_sidx + u*4000, d_swt + u*4000);
        s10i_g<10,160,512,false>(tid, buf, U, 400, rtA, rtB);
        s10i_g<100,16,512,false>(tid, buf, U, 400, rtA, rtB);
        s4i_g<512,true>(tid, buf, U, 1000, rtA, rtB);
        if (pi == 0) smooth_split<0>(U, sphi, &d_S1[(b*NCH + 1 + j)*NOUT]);
        else         smooth_split<1>(U, sphi, &d_S1p[(b*3 + j)*NOUT]);
    } else if (u < 13) {
        float2* buf = (float2*)sm;
        float*  U   = (float*)(sm + 4000*sizeof(float2));
        int jc = u - 6;
        s10_load_g<512>(tid, buf, Xb, d_idx + jc*4000, d_wt + jc*4000, 400);
        s10i_g<10,160,512,false>(tid, buf, U, 400, rtA, rtB);
        s10i_g<100,16,512,false>(tid, buf, U, 400, rtA, rtB);
        s4i_g<512,true>(tid, buf, U, 1000, rtA, rtB);
        smooth_dec_g<4000,4,512>(tid, U, sphi, &d_S1[(b*NCH + 1 + 3 + jc)*NOUT]);
    } else if (u < 19) {
        int sub = tid >> 8, t = tid & 255;
        int jc = (u - 13)*2 + sub; if (jc > 10) jc = 10;   // duplicate unit: identical writes
        float2* buf = (float2*)(sm + sub*24000);
        float*  U   = (float*)(sm + sub*24000 + 2000*sizeof(float2));
        s10_load_g<256>(t, buf, Xb, d_idx + 28000 + jc*2000, d_wt + 28000 + jc*2000, 200);
        s10i_g<10,160,256,false>(t, buf, U, 200, rtA, rtB);
        s10i_g<100,16,256,false>(t, buf, U, 200, rtA, rtB);
        s2i_abs_g<256,1000,8>(t, buf, U, rtA, rtB);
        smooth_dec_g<2000,8,256>(t, U, sphi, &d_S1[(b*NCH + 1 + 10 + jc)*NOUT]);
    } else {
        int sub = tid >> 7, t = tid & 127;
        int jc = (u - 19)*4 + sub; if (jc > 14) jc = 14;   // duplicate unit: identical writes
        float2* buf = (float2*)(sm + sub*12000);
        float*  U   = (float*)(sm + sub*12000 + 1000*sizeof(float2));
        s10_load_g<128>(t, buf, Xb, d_idx + 50000 + jc*1000, d_wt + 50000 + jc*1000, 100);
        s10i_g<10,160,128,false>(t, buf, U, 100, rtA, rtB);
        s10i_g<100,16,128,true>(t, buf, U, 100, rtA, rtB);
        smooth_dec_g<1000,16,128>(t, U, sphi, &d_S1[(b*NCH + 1 + 21 + jc)*NOUT]);
    }
}

// ---------------- kernel 3: channel-group means (+ parity-1 partials for j=0..2) ----------------
__global__ void k_reduce(float* __restrict__ out){
    int i = blockIdx.x * blockDim.x + threadIdx.x;
    if (i >= NB*3*NOUT) return;
    int m0 = i % NOUT;
    int g  = (i / NOUT) % 3;
    int b  = i / (3*NOUT);
    int c0 = (g==0) ? 0 : (g==1 ? 12 : 24);
    int nc = (g==2) ? 13 : 12;
    float acc = 0.f;
    for (int c = 0; c < nc; ++c) acc += d_S1[(b*NCH + c0 + c)*NOUT + m0];
    if (g == 0) {
        for (int j = 0; j < 3; ++j) acc += d_S1p[(b*3 + j)*NOUT + m0];
    }
    out[i] = acc / (float)nc;
}

// ---------------- launch ----------------
extern "C" void kernel_launch(void* const* d_in, const int* in_sizes, int n_in,
                              void* d_out, int out_size) {
    (void)in_sizes; (void)n_in; (void)out_size;
    const float* x = (const float*)d_in[0];
    float* out = (float*)d_out;
    const int smBand = 48000;
    const int smFB   = 32000;
    cudaFuncSetAttribute(k_band_all, cudaFuncAttributeMaxDynamicSharedMemorySize, smBand);
    cudaFuncSetAttribute(k_fwdB,     cudaFuncAttributeMaxDynamicSharedMemorySize, smFB);
    prep_all2<<<dim3(33, NF + 8), 256>>>();
    k_fwdA<<<dim3(2, NB), 512>>>(x);
    k_fwdB<<<dim3(4, NB), 512, smFB>>>();
    k_s0<<<NB, 256>>>(x);
    k_band_all<<<dim3(23, NB), 512, smBand>>>();
    k_reduce<<<(NB*3*NOUT + 255)/256, 256>>>(out);
}

// round 14
// speedup vs baseline: 2.1902x; 1.0455x over previous
#include <cuda_runtime.h>
#include <math.h>

#define TN 16000
#define NF 36
#define NB 64
#define NOUT 250
#define NTAPS 257
#define KPHI 569
#define NCH 37
#define TBL 65000

// ---------------- static device scratch ----------------
__device__ float2 d_X[NB * TN];        // scrambled forward FFT of x
__device__ float2 d_Xm[NB * TN];       // intermediate after radix-16 stage
__device__ int    d_idx[TBL];          // per-channel gather index (classes C/D/E)
__device__ float  d_wt[TBL];           // per-channel psi weight (incl 1/16000)
__device__ int2   d_sidx[6*4000];      // split units (j=0..2 x parity): two gather indices
__device__ float4 d_swt[6*4000];       // split units: two complex weights
__device__ float  d_phiw[NTAPS];       // time-domain lowpass taps phi(d), d=-128..128
__device__ float2 d_rtA[128];          // W_16000^{-125 i}
__device__ float2 d_rtB[125];          // W_16000^{-i}
__device__ float  d_S1[NB * NCH * NOUT];
__device__ float  d_S1p[NB * 3 * NOUT];  // parity-1 partial sums for j=0..2

// ---------------- complex helpers ----------------
__device__ __forceinline__ float2 cmul(float2 a, float2 b) {
    return make_float2(a.x*b.x - a.y*b.y, a.x*b.y + a.y*b.x);
}
__device__ __forceinline__ float2 cadd(float2 a, float2 b){ return make_float2(a.x+b.x, a.y+b.y); }
__device__ __forceinline__ float2 csub(float2 a, float2 b){ return make_float2(a.x-b.x, a.y-b.y); }

__device__ __forceinline__ int scrampos(int k){
    int e2 = k/1600, r = k - 1600*e2;
    int d2 = r/160;  r -= 160*d2;
    int c2 = r/16;   r -= 16*c2;
    int b2 = r/4,    a2 = r - 4*b2;
    return 4000*a2 + 1000*b2 + 100*c2 + 10*d2 + e2;
}
__device__ __forceinline__ float psiwt(int k, float xi, float sg){
    float f = (k < 8000) ? (float)k/16000.0f : (float)(k - 16000)/16000.0f;
    float u = (f - xi) / sg;
    return (u*u < 50.0f) ? __expf(-0.5f*u*u)/16000.0f : 0.0f;
}

// ---------------- ONE prep kernel ----------------
__global__ void prep_all2() {
    int row = blockIdx.y;
    int q = blockIdx.x * blockDim.x + threadIdx.x;
    const float rr  = exp2f(1.0f/6.0f);
    const float fac = (rr - 1.0f) / (rr + 1.0f);
    if (row < NF) {
        int j = row;
        if (j < 3) return;
        int cls, NJ, off;
        if      (j < 10){ cls=2; NJ=4000; off = (j-3)*4000; }
        else if (j < 21){ cls=3; NJ=2000; off = 28000 + (j-10)*2000; }
        else            { cls=4; NJ=1000; off = 50000 + (j-21)*1000; }
        if (q >= NJ) return;
        int kq;
        if      (cls == 2) { int b=q/1000, c=(q/100)%10, d=(q/10)%10, e=q%10; kq = b + 4*c + 40*d + 400*e; }
        else if (cls == 3) { int a=q/1000, c=(q/100)%10, d=(q/10)%10, e=q%10; kq = a + 2*c + 20*d + 200*e; }
        else               { int c=q/100, d=(q/10)%10, e=q%10; kq = c + 10*d + 100*e; }
        float xi = 0.35f * exp2f(-(float)j/6.0f);
        int k_lo = (int)(xi * 16000.0f) - NJ/2;
        if (k_lo < 0) k_lo = 0;
        int k = k_lo + kq;
        d_idx[off+q] = scrampos(k);
        d_wt[off+q]  = psiwt(k, xi, xi*fac);
    } else if (row < NF + 6) {
        int u = row - NF;
        int j = u >> 1, pi = u & 1;
        if (q >= 4000) return;
        int b=q/1000, c=(q/100)%10, d=(q/10)%10, e=q%10;
        int kq = b + 4*c + 40*d + 400*e;
        float xi = 0.35f * exp2f(-(float)j/6.0f);
        int k_lo = (int)(xi * 16000.0f) - 4000;
        if (k_lo < 0) k_lo = 0;
        int k1 = k_lo + kq, k2 = k_lo + kq + 4000;
        float sg = xi*fac;
        float p1 = psiwt(k1, xi, sg);
        float p2 = psiwt(k2, xi, sg);
        float2 ph = make_float2(1.f, 0.f);
        if (pi) { float s, cx; sincospif((float)kq/4000.0f, &s, &cx); ph = make_float2(cx, s); }
        float sgn = pi ? -1.f : 1.f;
        d_sidx[u*4000+q] = make_int2(scrampos(k1), scrampos(k2));
        d_swt[u*4000+q]  = make_float4(p1*ph.x, p1*ph.y, sgn*p2*ph.x, sgn*p2*ph.y);
    } else if (row == NF + 6) {
        int tap  = blockIdx.x*8 + (threadIdx.x >> 5);
        int lane = threadIdx.x & 31;
        if (tap >= NTAPS) return;
        int d = tap - 128;
        const float sp = 0.35f / 64.0f;
        float acc = 0.f;
        for (int k = 1 + lane; k <= KPHI; k += 32) {
            float f = (float)k / 16000.0f;
            float g = __expf(-f*f / (2.0f*sp*sp));
            acc += g * cospif(2.0f * (float)(k*d) / 16000.0f);
        }
        for (int o = 16; o; o >>= 1) acc += __shfl_down_sync(0xffffffffu, acc, o);
        if (lane == 0) d_phiw[tap] = (1.0f + 2.0f*acc) / 16000.0f;
    } else {
        if (q < 128) { float s, c; sincospif(-(float)q/64.0f, &s, &c); d_rtA[q] = make_float2(c, s); }
        else if (q < 253) { int t = q-128; float s, c; sincospif(-(float)t/8000.0f, &s, &c); d_rtB[t] = make_float2(c, s); }
    }
}

// ---------------- small DFTs ----------------
template<int SIGN>
__device__ __forceinline__ void dft4(float2&z0,float2&z1,float2&z2,float2&z3){
    float2 t0=cadd(z0,z2), t1=csub(z0,z2), t2=cadd(z1,z3), t3=csub(z1,z3);
    const float s = (float)SIGN;
    z0 = cadd(t0,t2);
    z2 = csub(t0,t2);
    z1 = make_float2(t1.x - s*t3.y, t1.y + s*t3.x);
    z3 = make_float2(t1.x + s*t3.y, t1.y - s*t3.x);
}

template<int SIGN>
__device__ __forceinline__ void dft5(float2&z0,float2&z1,float2&z2,float2&z3,float2&z4){
    const float K1 =  0.309016994374947424f;
    const float K2 = -0.809016994374947424f;
    const float S1 =  0.951056516295153572f;
    const float S2 =  0.587785252292473129f;
    float2 t1=cadd(z1,z4), t2=cadd(z2,z3), t3=csub(z1,z4), t4=csub(z2,z3);
    float2 a = z0;
    float2 sum = cadd(a, cadd(t1,t2));
    float2 r1 = make_float2(a.x + K1*t1.x + K2*t2.x, a.y + K1*t1.y + K2*t2.y);
    float2 r2 = make_float2(a.x + K2*t1.x + K1*t2.x, a.y + K2*t1.y + K1*t2.y);
    float2 q1 = make_float2(S1*t3.x + S2*t4.x, S1*t3.y + S2*t4.y);
    float2 q2 = make_float2(S2*t3.x - S1*t4.x, S2*t3.y - S1*t4.y);
    const float s = (float)SIGN;
    z0 = sum;
    z1 = make_float2(r1.x - s*q1.y, r1.y + s*q1.x);
    z4 = make_float2(r1.x + s*q1.y, r1.y - s*q1.x);
    z2 = make_float2(r2.x - s*q2.y, r2.y + s*q2.x);
    z3 = make_float2(r2.x + s*q2.y, r2.y - s*q2.x);
}

__device__ __forceinline__ float2 twb(int x, const float2* rtA, const float2* rtB){
    int a = x / 125;
    return cmul(rtA[a], rtB[x - a*125]);
}
__device__ __forceinline__ float2 twg(int x){
    int a = x / 125;
    return cmul(d_rtA[a], d_rtB[x - a*125]);
}

// ================= forward phase A: pure-register radix-16, global->global =================
__global__ void k_fwdA(const float* __restrict__ x){
    const float2 c16_1 = make_float2(0.92387953251128674f, -0.38268343236508977f);
    const float2 c16_2 = make_float2(0.70710678118654752f, -0.70710678118654752f);
    const float2 c16_3 = make_float2(0.38268343236508977f, -0.92387953251128674f);
    int b = blockIdx.y;
    int p = blockIdx.x*512 + threadIdx.x;
    if (p >= 1000) return;
    const float* xb = x + b*TN;
    float2 z[16];
    #pragma unroll
    for (int j=0;j<4;j++)
        #pragma unroll
        for (int i=0;i<4;i++)
            z[4*j+i] = make_float2(xb[p + 1000*j + 4000*i], 0.f);
    float2 a = twg(p);
    float2 bw = twg(4*p);
    #pragma unroll
    for (int j=0;j<4;j++) dft4<-1>(z[4*j+0], z[4*j+1], z[4*j+2], z[4*j+3]);
    #pragma unroll
    for (int j=0;j<4;j++){
        float2 t = (j==0)? a : (j==1? cmul(a,c16_1) : (j==2? cmul(a,c16_2) : cmul(a,c16_3)));
        float2 t2 = cmul(t,t);
        z[4*j+1]=cmul(z[4*j+1],t); z[4*j+2]=cmul(z[4*j+2],t2); z[4*j+3]=cmul(z[4*j+3],cmul(t2,t));
    }
    #pragma unroll
    for (int s1=0;s1<4;s1++) dft4<-1>(z[s1], z[4+s1], z[8+s1], z[12+s1]);
    float2 b2 = cmul(bw,bw), b3 = cmul(b2,bw);
    #pragma unroll
    for (int s1=0;s1<4;s1++){ z[4+s1]=cmul(z[4+s1],bw); z[8+s1]=cmul(z[8+s1],b2); z[12+s1]=cmul(z[12+s1],b3); }
    float2* Xo = d_Xm + b*TN;
    #pragma unroll
    for (int s1=0;s1<4;s1++)
        #pragma unroll
        for (int s2=0;s2<4;s2++)
            Xo[s1*4000 + s2*1000 + p] = z[4*s2+s1];
}

// forward radix-10 stage, generalized (cnt=400, 512 thr), block-local
template<int M, int CC>
__device__ void stage10fg(float2* buf, const float2* rtA, const float2* rtB){
    const float c1x=0.809016994374947424f, c1y=0.587785252292473129f;
    const float c2x=0.309016994374947424f, c2y=0.951056516295153572f;
    const float2 w10_1 = make_float2( c1x, -c1y);
    const float2 w10_2 = make_float2( c2x, -c2y);
    const float2 w10_3 = make_float2(-c2x, -c2y);
    const float2 w10_4 = make_float2(-c1x, -c1y);
    for (int idx = threadIdx.x; idx < 400; idx += 512) {
        int blk = idx / M;
        int p   = idx - blk*M;
        int o   = blk*(10*M) + p;
        float2 z[10];
        #pragma unroll
        for (int i=0;i<10;i++) z[i] = buf[o + M*i];
        float2 v = twb(CC*p, rtA, rtB);
        float2 b  = cmul(v,v);
        float2 b2 = cmul(b,b);
        float2 b3 = cmul(b2,b);
        float2 b4 = cmul(b2,b2);
        float2 m1 = cmul(w10_1, v);
        float2 m2 = cmul(w10_2, v);
        float2 m3 = cmul(w10_3, v);
        float2 m4 = cmul(w10_4, v);
        float2 e0=cadd(z[0],z[5]), e1=cadd(z[1],z[6]), e2=cadd(z[2],z[7]), e3=cadd(z[3],z[8]), e4=cadd(z[4],z[9]);
        float2 q0=cmul(csub(z[0],z[5]), v ), q1=cmul(csub(z[1],z[6]), m1),
               q2=cmul(csub(z[2],z[7]), m2), q3=cmul(csub(z[3],z[8]), m3),
               q4=cmul(csub(z[4],z[9]), m4);
        dft5<-1>(e0,e1,e2,e3,e4);
        dft5<-1>(q0,q1,q2,q3,q4);
        z[0]=e0;          z[1]=q0;
        z[2]=cmul(e1,b);  z[3]=cmul(q1,b);
        z[4]=cmul(e2,b2); z[5]=cmul(q2,b2);
        z[6]=cmul(e3,b3); z[7]=cmul(q3,b3);
        z[8]=cmul(e4,b4); z[9]=cmul(q4,b4);
        #pragma unroll
        for (int i=0;i<10;i++) buf[o + M*i] = z[i];
    }
    __syncthreads();
}

// ================= forward phase B: 4 independent 1000-pt blocks per CTA =================
__global__ __launch_bounds__(512) void k_fwdB(){
    extern __shared__ __align__(16) unsigned char sm[];
    float2* buf = (float2*)sm;                       // 4000 complex
    __shared__ float2 rtA[128]; __shared__ float2 rtB[125];
    for (int i = threadIdx.x; i < 128; i += 512) rtA[i] = d_rtA[i];
    for (int i = threadIdx.x; i < 125; i += 512) rtB[i] = d_rtB[i];
    int b = blockIdx.y;
    int base = blockIdx.x * 4000;
    const float4* src = (const float4*)(d_Xm + b*TN + base);
    float4* bd = (float4*)buf;
    for (int i = threadIdx.x; i < 2000; i += 512) bd[i] = src[i];
    __syncthreads();
    stage10fg<100,16>(buf, rtA, rtB);
    stage10fg<10,160>(buf, rtA, rtB);
    const float c1x=0.809016994374947424f, c1y=0.587785252292473129f;
    const float c2x=0.309016994374947424f, c2y=0.951056516295153572f;
    const float2 w1 = make_float2( c1x, -c1y);
    const float2 w2 = make_float2( c2x, -c2y);
    const float2 w3 = make_float2(-c2x, -c2y);
    const float2 w4 = make_float2(-c1x, -c1y);
    float2* Xo = d_X + b*TN + base;
    for (int blk = threadIdx.x; blk < 400; blk += 512) {
        int o = 10*blk;
        float2 z[10];
        #pragma unroll
        for (int i=0;i<10;i++) z[i] = buf[o+i];
        float2 e0=cadd(z[0],z[5]), e1=cadd(z[1],z[6]), e2=cadd(z[2],z[7]), e3=cadd(z[3],z[8]), e4=cadd(z[4],z[9]);
        float2 q0=csub(z[0],z[5]),           q1=cmul(csub(z[1],z[6]), w1),
               q2=cmul(csub(z[2],z[7]), w2), q3=cmul(csub(z[3],z[8]), w3),
               q4=cmul(csub(z[4],z[9]), w4);
        dft5<-1>(e0,e1,e2,e3,e4);
        dft5<-1>(q0,q1,q2,q3,q4);
        float4* X4 = (float4*)(Xo + o);
        X4[0] = make_float4(e0.x,e0.y,q0.x,q0.y);
        X4[1] = make_float4(e1.x,e1.y,q1.x,q1.y);
        X4[2] = make_float4(e2.x,e2.y,q2.x,q2.y);
        X4[3] = make_float4(e3.x,e3.y,q3.x,q3.y);
        X4[4] = make_float4(e4.x,e4.y,q4.x,q4.y);
    }
}

// ================= S0: parallel warp-per-output smoothing from global x =================
// grid (8, NB): CTA g handles outputs m0 in [g*32, min(g*32+32, NOUT))
__global__ __launch_bounds__(256) void k_s0(const float* __restrict__ x){
    __shared__ float sphi[NTAPS];
    int g = blockIdx.x, b = blockIdx.y;
    for (int i = threadIdx.x; i < NTAPS; i += 256) sphi[i] = d_phiw[i];
    __syncthreads();
    int w = threadIdx.x >> 5, l = threadIdx.x & 31;
    const float* xb = x + b*TN;
    for (int m0 = g*32 + w; m0 < NOUT && m0 < g*32 + 32; m0 += 8) {
        int tau = 64*m0;
        float acc = 0.f;
        #pragma unroll
        for (int it = 0; it < 9; ++it) {
            int tl = l + 32*it;
            if (tl <= 256) {
                int i = tl - 128;
                int id = tau - i;
                if (id >= TN) id -= TN;
                if (id < 0)   id += TN;
                acc += sphi[tl] * xb[id];
            }
        }
        #pragma unroll
        for (int o = 16; o; o >>= 1) acc += __shfl_down_sync(0xffffffffu, acc, o);
        if (l == 0) d_S1[(b*NCH)*NOUT + m0] = acc;
    }
}

// ================= inverse pieces (generalized over sub-unit tid/THRL) =================

template<int THRL>
__device__ void s10_load_g(int t, float2* buf, const float2* __restrict__ Xb,
                           const int* __restrict__ idx, const float* __restrict__ wt, int cnt10){
    const float c1x=0.809016994374947424f, c1y=0.587785252292473129f;
    const float c2x=0.309016994374947424f, c2y=0.951056516295153572f;
    const float2 w1 = make_float2( c1x,  c1y);
    const float2 w2 = make_float2( c2x,  c2y);
    const float2 w3 = make_float2(-c2x,  c2y);
    const float2 w4 = make_float2(-c1x,  c1y);
    for (int blk = t; blk < cnt10; blk += THRL) {
        int o = 10*blk;
        float2 z[10];
        #pragma unroll
        for (int i=0;i<10;i++){
            float2 v = Xb[idx[o+i]];
            float  w = wt[o+i];
            z[i] = make_float2(v.x*w, v.y*w);
        }
        float2 E0=z[0], E1=z[2], E2=z[4], E3=z[6], E4=z[8];
        float2 O0=z[1], O1=z[3], O2=z[5], O3=z[7], O4=z[9];
        dft5<1>(E0,E1,E2,E3,E4);
        dft5<1>(O0,O1,O2,O3,O4);
        O1=cmul(O1,w1); O2=cmul(O2,w2); O3=cmul(O3,w3); O4=cmul(O4,w4);
        buf[o  ]=cadd(E0,O0); buf[o+5]=csub(E0,O0);
        buf[o+1]=cadd(E1,O1); buf[o+6]=csub(E1,O1);
        buf[o+2]=cadd(E2,O2); buf[o+7]=csub(E2,O2);
        buf[o+3]=cadd(E3,O3); buf[o+8]=csub(E3,O3);
        buf[o+4]=cadd(E4,O4); buf[o+9]=csub(E4,O4);
    }
    __syncthreads();
}

__device__ void s10_load_dual(float2* buf, const float2* __restrict__ Xb,
                              const int2* __restrict__ sidx, const float4* __restrict__ swt){
    const float c1x=0.809016994374947424f, c1y=0.587785252292473129f;
    const float c2x=0.309016994374947424f, c2y=0.951056516295153572f;
    const float2 w1 = make_float2( c1x,  c1y);
    const float2 w2 = make_float2( c2x,  c2y);
    const float2 w3 = make_float2(-c2x,  c2y);
    const float2 w4 = make_float2(-c1x,  c1y);
    for (int blk = threadIdx.x; blk < 400; blk += 512) {
        int o = 10*blk;
        float2 z[10];
        #pragma unroll
        for (int i=0;i<10;i++){
            int2   ii = sidx[o+i];
            float4 ww = swt[o+i];
            float2 v1 = Xb[ii.x];
            float2 v2 = Xb[ii.y];
            z[i] = cadd(cmul(v1, make_float2(ww.x, ww.y)), cmul(v2, make_float2(ww.z, ww.w)));
        }
        float2 E0=z[0], E1=z[2], E2=z[4], E3=z[6], E4=z[8];
        float2 O0=z[1], O1=z[3], O2=z[5], O3=z[7], O4=z[9];
        dft5<1>(E0,E1,E2,E3,E4);
        dft5<1>(O0,O1,O2,O3,O4);
        O1=cmul(O1,w1); O2=cmul(O2,w2); O3=cmul(O3,w3); O4=cmul(O4,w4);
        buf[o  ]=cadd(E0,O0); buf[o+5]=csub(E0,O0);
        buf[o+1]=cadd(E1,O1); buf[o+6]=csub(E1,O1);
        buf[o+2]=cadd(E2,O2); buf[o+7]=csub(E2,O2);
        buf[o+3]=cadd(E3,O3); buf[o+8]=csub(E3,O3);
        buf[o+4]=cadd(E4,O4); buf[o+9]=csub(E4,O4);
    }
    __syncthreads();
}

template<int M, int CC, int THRL, bool ABS>
__device__ void s10i_g(int t, float2* buf, float* U, int cnt, const float2* rtA, const float2* rtB){
    const float c1x=0.809016994374947424f, c1y=0.587785252292473129f;
    const float c2x=0.309016994374947424f, c2y=0.951056516295153572f;
    const float2 w10_1 = make_float2( c1x,  c1y);
    const float2 w10_2 = make_float2( c2x,  c2y);
    const float2 w10_3 = make_float2(-c2x,  c2y);
    const float2 w10_4 = make_float2(-c1x,  c1y);
    for (int idx = t; idx < cnt; idx += THRL) {
        int blk = idx / M;
        int p   = idx - blk*M;
        int o   = blk*(10*M) + p;
        float2 z[10];
        #pragma unroll
        for (int i=0;i<10;i++) z[i] = buf[o + M*i];
        float2 v = twb(CC*p, rtA, rtB);
        v.y = -v.y;
        float2 b  = cmul(v,v);
        float2 b2 = cmul(b,b);
        float2 b3 = cmul(b2,b);
        float2 b4 = cmul(b2,b2);
        float2 m1 = cmul(w10_1, v);
        float2 m2 = cmul(w10_2, v);
        float2 m3 = cmul(w10_3, v);
        float2 m4 = cmul(w10_4, v);
        float2 E0=z[0], E1=cmul(z[2],b), E2=cmul(z[4],b2), E3=cmul(z[6],b3), E4=cmul(z[8],b4);
        float2 O0=z[1], O1=cmul(z[3],b), O2=cmul(z[5],b2), O3=cmul(z[7],b3), O4=cmul(z[9],b4);
        dft5<1>(E0,E1,E2,E3,E4);
        dft5<1>(O0,O1,O2,O3,O4);
        O0=cmul(O0,v ); O1=cmul(O1,m1); O2=cmul(O2,m2); O3=cmul(O3,m3); O4=cmul(O4,m4);
        float2 y[10];
        y[0]=cadd(E0,O0); y[5]=csub(E0,O0);
        y[1]=cadd(E1,O1); y[6]=csub(E1,O1);
        y[2]=cadd(E2,O2); y[7]=csub(E2,O2);
        y[3]=cadd(E3,O3); y[8]=csub(E3,O3);
        y[4]=cadd(E4,O4); y[9]=csub(E4,O4);
        if (ABS) {
            #pragma unroll
            for (int i=0;i<10;i++) U[o + M*i] = sqrtf(y[i].x*y[i].x + y[i].y*y[i].y);
        } else {
            #pragma unroll
            for (int i=0;i<10;i++) buf[o + M*i] = y[i];
        }
    }
    __syncthreads();
}

template<int THRL, bool ABS>
__device__ void s4i_g(int t, float2* buf, float* U, int cnt, const float2* rtA, const float2* rtB){
    for (int idx = t; idx < cnt; idx += THRL) {
        int blk = idx / 1000;
        int p   = idx - blk*1000;
        int o   = blk*4000 + p;
        float2 z0=buf[o], z1=buf[o+1000], z2=buf[o+2000], z3=buf[o+3000];
        float2 w1 = twb(4*p, rtA, rtB); w1.y = -w1.y;
        float2 w2 = cmul(w1,w1), w3 = cmul(w2,w1);
        z1=cmul(z1,w1); z2=cmul(z2,w2); z3=cmul(z3,w3);
        dft4<1>(z0,z1,z2,z3);
        if (ABS) {
            U[o]      = sqrtf(z0.x*z0.x + z0.y*z0.y);
            U[o+1000] = sqrtf(z1.x*z1.x + z1.y*z1.y);
            U[o+2000] = sqrtf(z2.x*z2.x + z2.y*z2.y);
            U[o+3000] = sqrtf(z3.x*z3.x + z3.y*z3.y);
        } else {
            buf[o]=z0; buf[o+1000]=z1; buf[o+2000]=z2; buf[o+3000]=z3;
        }
    }
    __syncthreads();
}

template<int THRL, int M2, int DD>
__device__ void s2i_abs_g(int t, float2* buf, float* U, const float2* rtA, const float2* rtB){
    for (int p = t; p < M2; p += THRL) {
        float2 a = buf[p];
        float2 w = twb(DD*p, rtA, rtB); w.y = -w.y;
        float2 bb = cmul(buf[p+M2], w);
        float2 y0 = cadd(a,bb), y1 = csub(a,bb);
        U[p]    = sqrtf(y0.x*y0.x + y0.y*y0.y);
        U[p+M2] = sqrtf(y1.x*y1.x + y1.y*y1.y);
    }
    __syncthreads();
}

template<int THRL>
__device__ void init_tables(float2* rtA, float2* rtB, float* sphi){
    for (int i = threadIdx.x; i < 128; i += THRL) rtA[i] = d_rtA[i];
    for (int i = threadIdx.x; i < 125; i += THRL) rtB[i] = d_rtB[i];
    for (int i = threadIdx.x; i < NTAPS; i += THRL) sphi[i] = d_phiw[i];
}

template<int NJ, int DEC, int THRL>
__device__ void smooth_dec_g(int t, const float* __restrict__ S, const float* __restrict__ sphi, float* dst){
    const int T = 128 / DEC;
    const int ITER = (2*T + 1 + 31) / 32;
    int w = t >> 5, l = t & 31;
    for (int m0 = w; m0 < NOUT; m0 += THRL/32) {
        int tau = (64/DEC) * m0;
        float acc = 0.f;
        #pragma unroll
        for (int it = 0; it < ITER; ++it) {
            int tl = l + 32*it;
            if (tl <= 2*T) {
                int i = tl - T;
                int id = tau - i;
                if (id >= NJ) id -= NJ;
                if (id < 0)   id += NJ;
                acc += sphi[DEC*i + 128] * S[id];
            }
        }
        #pragma unroll
        for (int o = 16; o; o >>= 1) acc += __shfl_down_sync(0xffffffffu, acc, o);
        if (l == 0) dst[m0] = acc * (float)DEC;
    }
}

template<int PI>
__device__ void smooth_split(const float* __restrict__ S, const float* __restrict__ sphi, float* dst){
    int w = threadIdx.x >> 5, l = threadIdx.x & 31;
    for (int m0 = w; m0 < NOUT; m0 += 16) {
        int tau = 16*m0 - PI;
        float acc = 0.f;
        #pragma unroll
        for (int it = 0; it < 3; ++it) {
            int t = l + 32*it;
            if (t <= 64 - PI) {
                int i = t - 32;
                int id = tau - i;
                if (id >= 4000) id -= 4000;
                if (id < 0)     id += 4000;
                acc += sphi[4*i + 2*PI + 128] * S[id];
            }
        }
        #pragma unroll
        for (int o = 16; o; o >>= 1) acc += __shfl_down_sync(0xffffffffu, acc, o);
        if (l == 0) dst[m0] = 2.0f * acc;
    }
}

// ---------------- unified band kernel: 23 CTAs per batch ----------------
__global__ __launch_bounds__(512, 3) void k_band_all(){
    extern __shared__ __align__(16) unsigned char sm[];
    __shared__ float2 rtA[128]; __shared__ float2 rtB[125]; __shared__ float sphi[NTAPS];
    int u = blockIdx.x, b = blockIdx.y;
    int tid = threadIdx.x;
    init_tables<512>(rtA, rtB, sphi);
    __syncthreads();
    const float2* Xb = d_X + b*TN;
    if (u < 6) {
        float2* buf = (float2*)sm;
        float*  U   = (float*)(sm + 4000*sizeof(float2));
        int j = u >> 1, pi = u & 1;
        s10_load_dual(buf, Xb, d_sidx + u*4000, d_swt + u*4000);
        s10i_g<10,160,512,false>(tid, buf, U, 400, rtA, rtB);
        s10i_g<100,16,512,false>(tid, buf, U, 400, rtA, rtB);
        s4i_g<512,true>(tid, buf, U, 1000, rtA, rtB);
        if (pi == 0) smooth_split<0>(U, sphi, &d_S1[(b*NCH + 1 + j)*NOUT]);
        else         smooth_split<1>(U, sphi, &d_S1p[(b*3 + j)*NOUT]);
    } else if (u < 13) {
        float2* buf = (float2*)sm;
        float*  U   = (float*)(sm + 4000*sizeof(float2));
        int jc = u - 6;
        s10_load_g<512>(tid, buf, Xb, d_idx + jc*4000, d_wt + jc*4000, 400);
        s10i_g<10,160,512,false>(tid, buf, U, 400, rtA, rtB);
        s10i_g<100,16,512,false>(tid, buf, U, 400, rtA, rtB);
        s4i_g<512,true>(tid, buf, U, 1000, rtA, rtB);
        smooth_dec_g<4000,4,512>(tid, U, sphi, &d_S1[(b*NCH + 1 + 3 + jc)*NOUT]);
    } else if (u < 19) {
        int sub = tid >> 8, t = tid & 255;
        int jc = (u - 13)*2 + sub; if (jc > 10) jc = 10;
        float2* buf = (float2*)(sm + sub*24000);
        float*  U   = (float*)(sm + sub*24000 + 2000*sizeof(float2));
        s10_load_g<256>(t, buf, Xb, d_idx + 28000 + jc*2000, d_wt + 28000 + jc*2000, 200);
        s10i_g<10,160,256,false>(t, buf, U, 200, rtA, rtB);
        s10i_g<100,16,256,false>(t, buf, U, 200, rtA, rtB);
        s2i_abs_g<256,1000,8>(t, buf, U, rtA, rtB);
        smooth_dec_g<2000,8,256>(t, U, sphi, &d_S1[(b*NCH + 1 + 10 + jc)*NOUT]);
    } else {
        int sub = tid >> 7, t = tid & 127;
        int jc = (u - 19)*4 + sub; if (jc > 14) jc = 14;
        float2* buf = (float2*)(sm + sub*12000);
        float*  U   = (float*)(sm + sub*12000 + 1000*sizeof(float2));
        s10_load_g<128>(t, buf, Xb, d_idx + 50000 + jc*1000, d_wt + 50000 + jc*1000, 100);
        s10i_g<10,160,128,false>(t, buf, U, 100, rtA, rtB);
        s10i_g<100,16,128,true>(t, buf, U, 100, rtA, rtB);
        smooth_dec_g<1000,16,128>(t, U, sphi, &d_S1[(b*NCH + 1 + 21 + jc)*NOUT]);
    }
}

// ---------------- kernel 3: channel-group means (+ parity-1 partials for j=0..2) ----------------
__global__ void k_reduce(float* __restrict__ out){
    int i = blockIdx.x * blockDim.x + threadIdx.x;
    if (i >= NB*3*NOUT) return;
    int m0 = i % NOUT;
    int g  = (i / NOUT) % 3;
    int b  = i / (3*NOUT);
    int c0 = (g==0) ? 0 : (g==1 ? 12 : 24);
    int nc = (g==2) ? 13 : 12;
    float acc = 0.f;
    for (int c = 0; c < nc; ++c) acc += d_S1[(b*NCH + c0 + c)*NOUT + m0];
    if (g == 0) {
        for (int j = 0; j < 3; ++j) acc += d_S1p[(b*3 + j)*NOUT + m0];
    }
    out[i] = acc / (float)nc;
}

// ---------------- launch ----------------
extern "C" void kernel_launch(void* const* d_in, const int* in_sizes, int n_in,
                              void* d_out, int out_size) {
    (void)in_sizes; (void)n_in; (void)out_size;
    const float* x = (const float*)d_in[0];
    float* out = (float*)d_out;
    const int smBand = 48000;
    const int smFB   = 32000;
    cudaFuncSetAttribute(k_band_all, cudaFuncAttributeMaxDynamicSharedMemorySize, smBand);
    cudaFuncSetAttribute(k_fwdB,     cudaFuncAttributeMaxDynamicSharedMemorySize, smFB);
    prep_all2<<<dim3(33, NF + 8), 256>>>();
    k_fwdA<<<dim3(2, NB), 512>>>(x);
    k_fwdB<<<dim3(4, NB), 512, smFB>>>();
    k_s0<<<dim3(8, NB), 256>>>(x);
    k_band_all<<<dim3(23, NB), 512, smBand>>>();
    k_reduce<<<(NB*3*NOUT + 511)/512, 512>>>(out);
}

// round 15
// speedup vs baseline: 2.2101x; 1.0091x over previous
#include <cuda_runtime.h>
#include <math.h>

#define TN 16000
#define NF 36
#define NB 64
#define NOUT 250
#define NTAPS 257
#define KPHI 569
#define NCH 37
#define TBL 65000

// ---------------- static device scratch ----------------
__device__ float2 d_X[NB * TN];        // scrambled forward FFT of x
__device__ int    d_idx[TBL];          // per-channel gather index (classes C/D/E)
__device__ float  d_wt[TBL];           // per-channel psi weight (incl 1/16000)
__device__ int2   d_sidx[6*4000];      // split units (j=0..2 x parity): two gather indices
__device__ float4 d_swt[6*4000];       // split units: two complex weights
__device__ float  d_phiw[NTAPS];       // time-domain lowpass taps phi(d), d=-128..128
__device__ float2 d_rtA[128];          // W_16000^{-125 i}
__device__ float2 d_rtB[125];          // W_16000^{-i}
__device__ float  d_S1[NB * NCH * NOUT];
__device__ float  d_S1p[NB * 3 * NOUT];  // parity-1 partial sums for j=0..2

// ---------------- complex helpers ----------------
__device__ __forceinline__ float2 cmul(float2 a, float2 b) {
    return make_float2(a.x*b.x - a.y*b.y, a.x*b.y + a.y*b.x);
}
__device__ __forceinline__ float2 cadd(float2 a, float2 b){ return make_float2(a.x+b.x, a.y+b.y); }
__device__ __forceinline__ float2 csub(float2 a, float2 b){ return make_float2(a.x-b.x, a.y-b.y); }

__device__ __forceinline__ int scrampos(int k){
    int e2 = k/1600, r = k - 1600*e2;
    int d2 = r/160;  r -= 160*d2;
    int c2 = r/16;   r -= 16*c2;
    int b2 = r/4,    a2 = r - 4*b2;
    return 4000*a2 + 1000*b2 + 100*c2 + 10*d2 + e2;
}
__device__ __forceinline__ float psiwt(int k, float xi, float sg){
    float f = (k < 8000) ? (float)k/16000.0f : (float)(k - 16000)/16000.0f;
    float u = (f - xi) / sg;
    return (u*u < 50.0f) ? __expf(-0.5f*u*u)/16000.0f : 0.0f;
}

// ---------------- ONE prep kernel ----------------
__global__ void prep_all2() {
    int row = blockIdx.y;
    int q = blockIdx.x * blockDim.x + threadIdx.x;
    const float rr  = exp2f(1.0f/6.0f);
    const float fac = (rr - 1.0f) / (rr + 1.0f);
    if (row < NF) {
        int j = row;
        if (j < 3) return;
        int cls, NJ, off;
        if      (j < 10){ cls=2; NJ=4000; off = (j-3)*4000; }
        else if (j < 21){ cls=3; NJ=2000; off = 28000 + (j-10)*2000; }
        else            { cls=4; NJ=1000; off = 50000 + (j-21)*1000; }
        if (q >= NJ) return;
        int kq;
        if      (cls == 2) { int b=q/1000, c=(q/100)%10, d=(q/10)%10, e=q%10; kq = b + 4*c + 40*d + 400*e; }
        else if (cls == 3) { int a=q/1000, c=(q/100)%10, d=(q/10)%10, e=q%10; kq = a + 2*c + 20*d + 200*e; }
        else               { int c=q/100, d=(q/10)%10, e=q%10; kq = c + 10*d + 100*e; }
        float xi = 0.35f * exp2f(-(float)j/6.0f);
        int k_lo = (int)(xi * 16000.0f) - NJ/2;
        if (k_lo < 0) k_lo = 0;
        int k = k_lo + kq;
        d_idx[off+q] = scrampos(k);
        d_wt[off+q]  = psiwt(k, xi, xi*fac);
    } else if (row < NF + 6) {
        int u = row - NF;
        int j = u >> 1, pi = u & 1;
        if (q >= 4000) return;
        int b=q/1000, c=(q/100)%10, d=(q/10)%10, e=q%10;
        int kq = b + 4*c + 40*d + 400*e;
        float xi = 0.35f * exp2f(-(float)j/6.0f);
        int k_lo = (int)(xi * 16000.0f) - 4000;
        if (k_lo < 0) k_lo = 0;
        int k1 = k_lo + kq, k2 = k_lo + kq + 4000;
        float sg = xi*fac;
        float p1 = psiwt(k1, xi, sg);
        float p2 = psiwt(k2, xi, sg);
        float2 ph = make_float2(1.f, 0.f);
        if (pi) { float s, cx; sincospif((float)kq/4000.0f, &s, &cx); ph = make_float2(cx, s); }
        float sgn = pi ? -1.f : 1.f;
        d_sidx[u*4000+q] = make_int2(scrampos(k1), scrampos(k2));
        d_swt[u*4000+q]  = make_float4(p1*ph.x, p1*ph.y, sgn*p2*ph.x, sgn*p2*ph.y);
    } else if (row == NF + 6) {
        int tap  = blockIdx.x*8 + (threadIdx.x >> 5);
        int lane = threadIdx.x & 31;
        if (tap >= NTAPS) return;
        int d = tap - 128;
        const float sp = 0.35f / 64.0f;
        float acc = 0.f;
        for (int k = 1 + lane; k <= KPHI; k += 32) {
            float f = (float)k / 16000.0f;
            float g = __expf(-f*f / (2.0f*sp*sp));
            acc += g * cospif(2.0f * (float)(k*d) / 16000.0f);
        }
        for (int o = 16; o; o >>= 1) acc += __shfl_down_sync(0xffffffffu, acc, o);
        if (lane == 0) d_phiw[tap] = (1.0f + 2.0f*acc) / 16000.0f;
    } else {
        if (q < 128) { float s, c; sincospif(-(float)q/64.0f, &s, &c); d_rtA[q] = make_float2(c, s); }
        else if (q < 253) { int t = q-128; float s, c; sincospif(-(float)t/8000.0f, &s, &c); d_rtB[t] = make_float2(c, s); }
    }
}

// ---------------- small DFTs ----------------
template<int SIGN>
__device__ __forceinline__ void dft4(float2&z0,float2&z1,float2&z2,float2&z3){
    float2 t0=cadd(z0,z2), t1=csub(z0,z2), t2=cadd(z1,z3), t3=csub(z1,z3);
    const float s = (float)SIGN;
    z0 = cadd(t0,t2);
    z2 = csub(t0,t2);
    z1 = make_float2(t1.x - s*t3.y, t1.y + s*t3.x);
    z3 = make_float2(t1.x + s*t3.y, t1.y - s*t3.x);
}

template<int SIGN>
__device__ __forceinline__ void dft5(float2&z0,float2&z1,float2&z2,float2&z3,float2&z4){
    const float K1 =  0.309016994374947424f;
    const float K2 = -0.809016994374947424f;
    const float S1 =  0.951056516295153572f;
    const float S2 =  0.587785252292473129f;
    float2 t1=cadd(z1,z4), t2=cadd(z2,z3), t3=csub(z1,z4), t4=csub(z2,z3);
    float2 a = z0;
    float2 sum = cadd(a, cadd(t1,t2));
    float2 r1 = make_float2(a.x + K1*t1.x + K2*t2.x, a.y + K1*t1.y + K2*t2.y);
    float2 r2 = make_float2(a.x + K2*t1.x + K1*t2.x, a.y + K2*t1.y + K1*t2.y);
    float2 q1 = make_float2(S1*t3.x + S2*t4.x, S1*t3.y + S2*t4.y);
    float2 q2 = make_float2(S2*t3.x - S1*t4.x, S2*t3.y - S1*t4.y);
    const float s = (float)SIGN;
    z0 = sum;
    z1 = make_float2(r1.x - s*q1.y, r1.y + s*q1.x);
    z4 = make_float2(r1.x + s*q1.y, r1.y - s*q1.x);
    z2 = make_float2(r2.x - s*q2.y, r2.y + s*q2.x);
    z3 = make_float2(r2.x + s*q2.y, r2.y - s*q2.x);
}

__device__ __forceinline__ float2 twb(int x, const float2* rtA, const float2* rtB){
    int a = x / 125;
    return cmul(rtA[a], rtB[x - a*125]);
}

// forward radix-10 stage, block-local (cnt=400, 512 thr)
template<int M, int CC>
__device__ void stage10fg(float2* buf, const float2* rtA, const float2* rtB){
    const float c1x=0.809016994374947424f, c1y=0.587785252292473129f;
    const float c2x=0.309016994374947424f, c2y=0.951056516295153572f;
    const float2 w10_1 = make_float2( c1x, -c1y);
    const float2 w10_2 = make_float2( c2x, -c2y);
    const float2 w10_3 = make_float2(-c2x, -c2y);
    const float2 w10_4 = make_float2(-c1x, -c1y);
    for (int idx = threadIdx.x; idx < 400; idx += 512) {
        int blk = idx / M;
        int p   = idx - blk*M;
        int o   = blk*(10*M) + p;
        float2 z[10];
        #pragma unroll
        for (int i=0;i<10;i++) z[i] = buf[o + M*i];
        float2 v = twb(CC*p, rtA, rtB);
        float2 b  = cmul(v,v);
        float2 b2 = cmul(b,b);
        float2 b3 = cmul(b2,b);
        float2 b4 = cmul(b2,b2);
        float2 m1 = cmul(w10_1, v);
        float2 m2 = cmul(w10_2, v);
        float2 m3 = cmul(w10_3, v);
        float2 m4 = cmul(w10_4, v);
        float2 e0=cadd(z[0],z[5]), e1=cadd(z[1],z[6]), e2=cadd(z[2],z[7]), e3=cadd(z[3],z[8]), e4=cadd(z[4],z[9]);
        float2 q0=cmul(csub(z[0],z[5]), v ), q1=cmul(csub(z[1],z[6]), m1),
               q2=cmul(csub(z[2],z[7]), m2), q3=cmul(csub(z[3],z[8]), m3),
               q4=cmul(csub(z[4],z[9]), m4);
        dft5<-1>(e0,e1,e2,e3,e4);
        dft5<-1>(q0,q1,q2,q3,q4);
        z[0]=e0;          z[1]=q0;
        z[2]=cmul(e1,b);  z[3]=cmul(q1,b);
        z[4]=cmul(e2,b2); z[5]=cmul(q2,b2);
        z[6]=cmul(e3,b3); z[7]=cmul(q3,b3);
        z[8]=cmul(e4,b4); z[9]=cmul(q4,b4);
        #pragma unroll
        for (int i=0;i<10;i++) buf[o + M*i] = z[i];
    }
    __syncthreads();
}

// ================= merged forward: radix-4 component from global + local [4,10,10,10] =================
// grid (4, NB): CTA (s,b) computes sub-block s (k mod 4 == s), 4000 points, writes d_X[b*TN + 4000s ..)
__global__ __launch_bounds__(512) void k_fwd2(const float* __restrict__ x){
    extern __shared__ __align__(16) unsigned char sm[];
    float2* buf = (float2*)sm;                       // 4000 complex
    __shared__ float2 rtA[128]; __shared__ float2 rtB[125];
    for (int i = threadIdx.x; i < 128; i += 512) rtA[i] = d_rtA[i];
    for (int i = threadIdx.x; i < 125; i += 512) rtB[i] = d_rtB[i];
    int s = blockIdx.x, b = blockIdx.y;
    const float* xb = x + b*TN;
    __syncthreads();
    // level-1 radix-4 component s (x real), twiddle W^{-s p}
    for (int p = threadIdx.x; p < 4000; p += 512) {
        float x0=xb[p], x1=xb[p+4000], x2=xb[p+8000], x3=xb[p+12000];
        float2 comp;
        if      (s==0) comp = make_float2(x0+x1+x2+x3, 0.f);
        else if (s==1) comp = make_float2(x0-x2, -(x1-x3));
        else if (s==2) comp = make_float2(x0-x1+x2-x3, 0.f);
        else           comp = make_float2(x0-x2,  (x1-x3));
        if (s) comp = cmul(comp, twb(s*p, rtA, rtB));
        buf[p] = comp;
    }
    __syncthreads();
    // level-2 radix-4, M=1000, twiddle W_16000^{-4 p s2}
    for (int p = threadIdx.x; p < 1000; p += 512) {
        float2 z0=buf[p], z1=buf[p+1000], z2=buf[p+2000], z3=buf[p+3000];
        dft4<-1>(z0,z1,z2,z3);
        float2 w1 = twb(4*p, rtA, rtB);
        float2 w2 = cmul(w1,w1), w3 = cmul(w2,w1);
        z1=cmul(z1,w1); z2=cmul(z2,w2); z3=cmul(z3,w3);
        buf[p]=z0; buf[p+1000]=z1; buf[p+2000]=z2; buf[p+3000]=z3;
    }
    __syncthreads();
    stage10fg<100,16>(buf, rtA, rtB);
    stage10fg<10,160>(buf, rtA, rtB);
    // final radix-10 M=1, no twiddle, store natural
    const float c1x=0.809016994374947424f, c1y=0.587785252292473129f;
    const float c2x=0.309016994374947424f, c2y=0.951056516295153572f;
    const float2 w1 = make_float2( c1x, -c1y);
    const float2 w2 = make_float2( c2x, -c2y);
    const float2 w3 = make_float2(-c2x, -c2y);
    const float2 w4 = make_float2(-c1x, -c1y);
    float2* Xo = d_X + b*TN + s*4000;
    for (int blk = threadIdx.x; blk < 400; blk += 512) {
        int o = 10*blk;
        float2 z[10];
        #pragma unroll
        for (int i=0;i<10;i++) z[i] = buf[o+i];
        float2 e0=cadd(z[0],z[5]), e1=cadd(z[1],z[6]), e2=cadd(z[2],z[7]), e3=cadd(z[3],z[8]), e4=cadd(z[4],z[9]);
        float2 q0=csub(z[0],z[5]),           q1=cmul(csub(z[1],z[6]), w1),
               q2=cmul(csub(z[2],z[7]), w2), q3=cmul(csub(z[3],z[8]), w3),
               q4=cmul(csub(z[4],z[9]), w4);
        dft5<-1>(e0,e1,e2,e3,e4);
        dft5<-1>(q0,q1,q2,q3,q4);
        float4* X4 = (float4*)(Xo + o);
        X4[0] = make_float4(e0.x,e0.y,q0.x,q0.y);
        X4[1] = make_float4(e1.x,e1.y,q1.x,q1.y);
        X4[2] = make_float4(e2.x,e2.y,q2.x,q2.y);
        X4[3] = make_float4(e3.x,e3.y,q3.x,q3.y);
        X4[4] = make_float4(e4.x,e4.y,q4.x,q4.y);
    }
}

// ================= S0: smem-windowed warp-per-output smoothing =================
// grid (8, NB): CTA g covers outputs [32g, 32g+32); window = 2241 samples, no inner modulo
__global__ __launch_bounds__(256) void k_s0(const float* __restrict__ x){
    __shared__ float sphi[NTAPS];
    __shared__ float sx[2304];
    int g = blockIdx.x, b = blockIdx.y;
    const float* xb = x + b*TN;
    int base = 64*32*g - 128;
    for (int i = threadIdx.x; i < NTAPS; i += 256) sphi[i] = d_phiw[i];
    for (int t = threadIdx.x; t < 2304; t += 256) {
        int id = base + t;
        if (id < 0)   id += TN;
        if (id >= TN) id -= TN;
        sx[t] = xb[id];
    }
    __syncthreads();
    int w = threadIdx.x >> 5, l = threadIdx.x & 31;
    for (int m0 = g*32 + w; m0 < NOUT && m0 < g*32 + 32; m0 += 8) {
        int offb = 64*(m0 - g*32) + 256;
        float acc = 0.f;
        #pragma unroll
        for (int it = 0; it < 9; ++it) {
            int tl = l + 32*it;
            if (tl <= 256) acc += sphi[tl] * sx[offb - tl];
        }
        #pragma unroll
        for (int o = 16; o; o >>= 1) acc += __shfl_down_sync(0xffffffffu, acc, o);
        if (l == 0) d_S1[(b*NCH)*NOUT + m0] = acc;
    }
}

// ================= inverse pieces (generalized over sub-unit tid/THRL) =================

template<int THRL>
__device__ void s10_load_g(int t, float2* buf, const float2* __restrict__ Xb,
                           const int* __restrict__ idx, const float* __restrict__ wt, int cnt10){
    const float c1x=0.809016994374947424f, c1y=0.587785252292473129f;
    const float c2x=0.309016994374947424f, c2y=0.951056516295153572f;
    const float2 w1 = make_float2( c1x,  c1y);
    const float2 w2 = make_float2( c2x,  c2y);
    const float2 w3 = make_float2(-c2x,  c2y);
    const float2 w4 = make_float2(-c1x,  c1y);
    for (int blk = t; blk < cnt10; blk += THRL) {
        int o = 10*blk;
        float2 z[10];
        #pragma unroll
        for (int i=0;i<10;i++){
            float2 v = Xb[idx[o+i]];
            float  w = wt[o+i];
            z[i] = make_float2(v.x*w, v.y*w);
        }
        float2 E0=z[0], E1=z[2], E2=z[4], E3=z[6], E4=z[8];
        float2 O0=z[1], O1=z[3], O2=z[5], O3=z[7], O4=z[9];
        dft5<1>(E0,E1,E2,E3,E4);
        dft5<1>(O0,O1,O2,O3,O4);
        O1=cmul(O1,w1); O2=cmul(O2,w2); O3=cmul(O3,w3); O4=cmul(O4,w4);
        buf[o  ]=cadd(E0,O0); buf[o+5]=csub(E0,O0);
        buf[o+1]=cadd(E1,O1); buf[o+6]=csub(E1,O1);
        buf[o+2]=cadd(E2,O2); buf[o+7]=csub(E2,O2);
        buf[o+3]=cadd(E3,O3); buf[o+8]=csub(E3,O3);
        buf[o+4]=cadd(E4,O4); buf[o+9]=csub(E4,O4);
    }
    __syncthreads();
}

__device__ void s10_load_dual(float2* buf, const float2* __restrict__ Xb,
                              const int2* __restrict__ sidx, const float4* __restrict__ swt){
    const float c1x=0.809016994374947424f, c1y=0.587785252292473129f;
    const float c2x=0.309016994374947424f, c2y=0.951056516295153572f;
    const float2 w1 = make_float2( c1x,  c1y);
    const float2 w2 = make_float2( c2x,  c2y);
    const float2 w3 = make_float2(-c2x,  c2y);
    const float2 w4 = make_float2(-c1x,  c1y);
    for (int blk = threadIdx.x; blk < 400; blk += 512) {
        int o = 10*blk;
        float2 z[10];
        #pragma unroll
        for (int i=0;i<10;i++){
            int2   ii = sidx[o+i];
            float4 ww = swt[o+i];
            float2 v1 = Xb[ii.x];
            float2 v2 = Xb[ii.y];
            z[i] = cadd(cmul(v1, make_float2(ww.x, ww.y)), cmul(v2, make_float2(ww.z, ww.w)));
        }
        float2 E0=z[0], E1=z[2], E2=z[4], E3=z[6], E4=z[8];
        float2 O0=z[1], O1=z[3], O2=z[5], O3=z[7], O4=z[9];
        dft5<1>(E0,E1,E2,E3,E4);
        dft5<1>(O0,O1,O2,O3,O4);
        O1=cmul(O1,w1); O2=cmul(O2,w2); O3=cmul(O3,w3); O4=cmul(O4,w4);
        buf[o  ]=cadd(E0,O0); buf[o+5]=csub(E0,O0);
        buf[o+1]=cadd(E1,O1); buf[o+6]=csub(E1,O1);
        buf[o+2]=cadd(E2,O2); buf[o+7]=csub(E2,O2);
        buf[o+3]=cadd(E3,O3); buf[o+8]=csub(E3,O3);
        buf[o+4]=cadd(E4,O4); buf[o+9]=csub(E4,O4);
    }
    __syncthreads();
}

template<int M, int CC, int THRL, bool ABS>
__device__ void s10i_g(int t, float2* buf, float* U, int cnt, const float2* rtA, const float2* rtB){
    const float c1x=0.809016994374947424f, c1y=0.587785252292473129f;
    const float c2x=0.309016994374947424f, c2y=0.951056516295153572f;
    const float2 w10_1 = make_float2( c1x,  c1y);
    const float2 w10_2 = make_float2( c2x,  c2y);
    const float2 w10_3 = make_float2(-c2x,  c2y);
    const float2 w10_4 = make_float2(-c1x,  c1y);
    for (int idx = t; idx < cnt; idx += THRL) {
        int blk = idx / M;
        int p   = idx - blk*M;
        int o   = blk*(10*M) + p;
        float2 z[10];
        #pragma unroll
        for (int i=0;i<10;i++) z[i] = buf[o + M*i];
        float2 v = twb(CC*p, rtA, rtB);
        v.y = -v.y;
        float2 b  = cmul(v,v);
        float2 b2 = cmul(b,b);
        float2 b3 = cmul(b2,b);
        float2 b4 = cmul(b2,b2);
        float2 m1 = cmul(w10_1, v);
        float2 m2 = cmul(w10_2, v);
        float2 m3 = cmul(w10_3, v);
        float2 m4 = cmul(w10_4, v);
        float2 E0=z[0], E1=cmul(z[2],b), E2=cmul(z[4],b2), E3=cmul(z[6],b3), E4=cmul(z[8],b4);
        float2 O0=z[1], O1=cmul(z[3],b), O2=cmul(z[5],b2), O3=cmul(z[7],b3), O4=cmul(z[9],b4);
        dft5<1>(E0,E1,E2,E3,E4);
        dft5<1>(O0,O1,O2,O3,O4);
        O0=cmul(O0,v ); O1=cmul(O1,m1); O2=cmul(O2,m2); O3=cmul(O3,m3); O4=cmul(O4,m4);
        float2 y[10];
        y[0]=cadd(E0,O0); y[5]=csub(E0,O0);
        y[1]=cadd(E1,O1); y[6]=csub(E1,O1);
        y[2]=cadd(E2,O2); y[7]=csub(E2,O2);
        y[3]=cadd(E3,O3); y[8]=csub(E3,O3);
        y[4]=cadd(E4,O4); y[9]=csub(E4,O4);
        if (ABS) {
            #pragma unroll
            for (int i=0;i<10;i++) U[o + M*i] = sqrtf(y[i].x*y[i].x + y[i].y*y[i].y);
        } else {
            #pragma unroll
            for (int i=0;i<10;i++) buf[o + M*i] = y[i];
        }
    }
    __syncthreads();
}

template<int THRL, bool ABS>
__device__ void s4i_g(int t, float2* buf, float* U, int cnt, const float2* rtA, const float2* rtB){
    for (int idx = t; idx < cnt; idx += THRL) {
        int blk = idx / 1000;
        int p   = idx - blk*1000;
        int o   = blk*4000 + p;
        float2 z0=buf[o], z1=buf[o+1000], z2=buf[o+2000], z3=buf[o+3000];
        float2 w1 = twb(4*p, rtA, rtB); w1.y = -w1.y;
        float2 w2 = cmul(w1,w1), w3 = cmul(w2,w1);
        z1=cmul(z1,w1); z2=cmul(z2,w2); z3=cmul(z3,w3);
        dft4<1>(z0,z1,z2,z3);
        if (ABS) {
            U[o]      = sqrtf(z0.x*z0.x + z0.y*z0.y);
            U[o+1000] = sqrtf(z1.x*z1.x + z1.y*z1.y);
            U[o+2000] = sqrtf(z2.x*z2.x + z2.y*z2.y);
            U[o+3000] = sqrtf(z3.x*z3.x + z3.y*z3.y);
        } else {
            buf[o]=z0; buf[o+1000]=z1; buf[o+2000]=z2; buf[o+3000]=z3;
        }
    }
    __syncthreads();
}

template<int THRL, int M2, int DD>
__device__ void s2i_abs_g(int t, float2* buf, float* U, const float2* rtA, const float2* rtB){
    for (int p = t; p < M2; p += THRL) {
        float2 a = buf[p];
        float2 w = twb(DD*p, rtA, rtB); w.y = -w.y;
        float2 bb = cmul(buf[p+M2], w);
        float2 y0 = cadd(a,bb), y1 = csub(a,bb);
        U[p]    = sqrtf(y0.x*y0.x + y0.y*y0.y);
        U[p+M2] = sqrtf(y1.x*y1.x + y1.y*y1.y);
    }
    __syncthreads();
}

template<int THRL>
__device__ void init_tables(float2* rtA, float2* rtB, float* sphi){
    for (int i = threadIdx.x; i < 128; i += THRL) rtA[i] = d_rtA[i];
    for (int i = threadIdx.x; i < 125; i += THRL) rtB[i] = d_rtB[i];
    for (int i = threadIdx.x; i < NTAPS; i += THRL) sphi[i] = d_phiw[i];
}

template<int NJ, int DEC, int THRL>
__device__ void smooth_dec_g(int t, const float* __restrict__ S, const float* __restrict__ sphi, float* dst){
    const int T = 128 / DEC;
    const int ITER = (2*T + 1 + 31) / 32;
    int w = t >> 5, l = t & 31;
    for (int m0 = w; m0 < NOUT; m0 += THRL/32) {
        int tau = (64/DEC) * m0;
        float acc = 0.f;
        #pragma unroll
        for (int it = 0; it < ITER; ++it) {
            int tl = l + 32*it;
            if (tl <= 2*T) {
                int i = tl - T;
                int id = tau - i;
                if (id >= NJ) id -= NJ;
                if (id < 0)   id += NJ;
                acc += sphi[DEC*i + 128] * S[id];
            }
        }
        #pragma unroll
        for (int o = 16; o; o >>= 1) acc += __shfl_down_sync(0xffffffffu, acc, o);
        if (l == 0) dst[m0] = acc * (float)DEC;
    }
}

template<int PI>
__device__ void smooth_split(const float* __restrict__ S, const float* __restrict__ sphi, float* dst){
    int w = threadIdx.x >> 5, l = threadIdx.x & 31;
    for (int m0 = w; m0 < NOUT; m0 += 16) {
        int tau = 16*m0 - PI;
        float acc = 0.f;
        #pragma unroll
        for (int it = 0; it < 3; ++it) {
            int t = l + 32*it;
            if (t <= 64 - PI) {
                int i = t - 32;
                int id = tau - i;
                if (id >= 4000) id -= 4000;
                if (id < 0)     id += 4000;
                acc += sphi[4*i + 2*PI + 128] * S[id];
            }
        }
        #pragma unroll
        for (int o = 16; o; o >>= 1) acc += __shfl_down_sync(0xffffffffu, acc, o);
        if (l == 0) dst[m0] = 2.0f * acc;
    }
}

// ---------------- unified band kernel: 23 CTAs per batch ----------------
__global__ __launch_bounds__(512, 3) void k_band_all(){
    extern __shared__ __align__(16) unsigned char sm[];
    __shared__ float2 rtA[128]; __shared__ float2 rtB[125]; __shared__ float sphi[NTAPS];
    int u = blockIdx.x, b = blockIdx.y;
    int tid = threadIdx.x;
    init_tables<512>(rtA, rtB, sphi);
    __syncthreads();
    const float2* Xb = d_X + b*TN;
    if (u < 6) {
        float2* buf = (float2*)sm;
        float*  U   = (float*)(sm + 4000*sizeof(float2));
        int j = u >> 1, pi = u & 1;
        s10_load_dual(buf, Xb, d_sidx + u*4000, d_swt + u*4000);
        s10i_g<10,160,512,false>(tid, buf, U, 400, rtA, rtB);
        s10i_g<100,16,512,false>(tid, buf, U, 400, rtA, rtB);
        s4i_g<512,true>(tid, buf, U, 1000, rtA, rtB);
        if (pi == 0) smooth_split<0>(U, sphi, &d_S1[(b*NCH + 1 + j)*NOUT]);
        else         smooth_split<1>(U, sphi, &d_S1p[(b*3 + j)*NOUT]);
    } else if (u < 13) {
        float2* buf = (float2*)sm;
        float*  U   = (float*)(sm + 4000*sizeof(float2));
        int jc = u - 6;
        s10_load_g<512>(tid, buf, Xb, d_idx + jc*4000, d_wt + jc*4000, 400);
        s10i_g<10,160,512,false>(tid, buf, U, 400, rtA, rtB);
        s10i_g<100,16,512,false>(tid, buf, U, 400, rtA, rtB);
        s4i_g<512,true>(tid, buf, U, 1000, rtA, rtB);
        smooth_dec_g<4000,4,512>(tid, U, sphi, &d_S1[(b*NCH + 1 + 3 + jc)*NOUT]);
    } else if (u < 19) {
        int sub = tid >> 8, t = tid & 255;
        int jc = (u - 13)*2 + sub; if (jc > 10) jc = 10;
        float2* buf = (float2*)(sm + sub*24000);
        float*  U   = (float*)(sm + sub*24000 + 2000*sizeof(float2));
        s10_load_g<256>(t, buf, Xb, d_idx + 28000 + jc*2000, d_wt + 28000 + jc*2000, 200);
        s10i_g<10,160,256,false>(t, buf, U, 200, rtA, rtB);
        s10i_g<100,16,256,false>(t, buf, U, 200, rtA, rtB);
        s2i_abs_g<256,1000,8>(t, buf, U, rtA, rtB);
        smooth_dec_g<2000,8,256>(t, U, sphi, &d_S1[(b*NCH + 1 + 10 + jc)*NOUT]);
    } else {
        int sub = tid >> 7, t = tid & 127;
        int jc = (u - 19)*4 + sub; if (jc > 14) jc = 14;
        float2* buf = (float2*)(sm + sub*12000);
        float*  U   = (float*)(sm + sub*12000 + 1000*sizeof(float2));
        s10_load_g<128>(t, buf, Xb, d_idx + 50000 + jc*1000, d_wt + 50000 + jc*1000, 100);
        s10i_g<10,160,128,false>(t, buf, U, 100, rtA, rtB);
        s10i_g<100,16,128,true>(t, buf, U, 100, rtA, rtB);
        smooth_dec_g<1000,16,128>(t, U, sphi, &d_S1[(b*NCH + 1 + 21 + jc)*NOUT]);
    }
}

// ---------------- kernel 3: channel-group means (+ parity-1 partials for j=0..2) ----------------
__global__ void k_reduce(float* __restrict__ out){
    int i = blockIdx.x * blockDim.x + threadIdx.x;
    if (i >= NB*3*NOUT) return;
    int m0 = i % NOUT;
    int g  = (i / NOUT) % 3;
    int b  = i / (3*NOUT);
    int c0 = (g==0) ? 0 : (g==1 ? 12 : 24);
    int nc = (g==2) ? 13 : 12;
    float acc = 0.f;
    for (int c = 0; c < nc; ++c) acc += d_S1[(b*NCH + c0 + c)*NOUT + m0];
    if (g == 0) {
        for (int j = 0; j < 3; ++j) acc += d_S1p[(b*3 + j)*NOUT + m0];
    }
    out[i] = acc / (float)nc;
}

// ---------------- launch ----------------
extern "C" void kernel_launch(void* const* d_in, const int* in_sizes, int n_in,
                              void* d_out, int out_size) {
    (void)in_sizes; (void)n_in; (void)out_size;
    const float* x = (const float*)d_in[0];
    float* out = (float*)d_out;
    const int smBand = 48000;
    const int smFW   = 32000;
    cudaFuncSetAttribute(k_band_all, cudaFuncAttributeMaxDynamicSharedMemorySize, smBand);
    cudaFuncSetAttribute(k_fwd2,     cudaFuncAttributeMaxDynamicSharedMemorySize, smFW);
    prep_all2<<<dim3(33, NF + 8), 256>>>();
    k_fwd2<<<dim3(4, NB), 512, smFW>>>(x);
    k_s0<<<dim3(8, NB), 256>>>(x);
    k_band_all<<<dim3(23, NB), 512, smBand>>>();
    k_reduce<<<(NB*3*NOUT + 511)/512, 512>>>(out);
}